// round 10
// baseline (speedup 1.0000x reference)
#include <cuda_runtime.h>
#include <math.h>

#define HH 128
#define WW 160
#define CC 32
#define DD 32
#define BB 2
#define VV 5
#define HWSZ (HH*WW)       // 20480
#define NPIX (BB*HWSZ)     // 40960
#define NDEP (BB*DD*HWSZ)  // 1310720

// out layout (flattened tuple in reference-return order):
#define OFF_DEPTH 0
#define OFF_CONF  40960
#define OFF_PROB  81920
#define OFF_COST  1392640
#define OFF_VW    2703360

__device__ float g_rot[4][BB][9];
__device__ float g_trans[4][BB][3];
// piecewise-affine MLP table: g_abf[i*16 + j] = alpha_j, [i*16+8+j] = beta_j
__device__ float g_thr[16];
__device__ float g_abf[17*16];
__device__ float g_w2s[8];
__device__ float g_B2s;
__device__ float g_sim[BB*DD*HWSZ];
__device__ unsigned g_dminu = 0xFFFFFFFFu;  // ordered-encoded min (idempotent across replays)
__device__ unsigned g_dmaxu = 0u;
__device__ int g_fast;
__device__ int g_jlo[4][BB];
__device__ int g_ktap[4][BB];

__device__ __forceinline__ unsigned ord_enc(float x) {
    unsigned u = __float_as_uint(x);
    return (u & 0x80000000u) ? ~u : (u | 0x80000000u);
}
__device__ __forceinline__ float ord_dec(unsigned u) {
    u = (u & 0x80000000u) ? (u & 0x7FFFFFFFu) : ~u;
    return __uint_as_float(u);
}

// ---------------------------------------------------------------------------
// k1: fused prep (block 128) + depth minmax (blocks 0..127).
// ---------------------------------------------------------------------------
__global__ void __launch_bounds__(256) prep_minmax(const float* __restrict__ depthv,
    const float* __restrict__ pm,
    const float* __restrict__ w0, const float* __restrict__ g0,
    const float* __restrict__ b0, const float* __restrict__ m0, const float* __restrict__ v0,
    const float* __restrict__ w1, const float* __restrict__ g1,
    const float* __restrict__ b1, const float* __restrict__ m1, const float* __restrict__ v1,
    const float* __restrict__ w2, const float* __restrict__ b2)
{
    if (blockIdx.x < 128) {
        __shared__ unsigned smin[256], smax[256];
        unsigned mn = 0xFFFFFFFFu, mx = 0u;
        for (int i = blockIdx.x*256 + threadIdx.x; i < NDEP; i += 128*256) {
            unsigned e = ord_enc(depthv[i]);
            mn = min(mn, e); mx = max(mx, e);
        }
        smin[threadIdx.x] = mn; smax[threadIdx.x] = mx;
        __syncthreads();
        for (int s = 128; s > 0; s >>= 1) {
            if (threadIdx.x < s) {
                smin[threadIdx.x] = min(smin[threadIdx.x], smin[threadIdx.x+s]);
                smax[threadIdx.x] = max(smax[threadIdx.x], smax[threadIdx.x+s]);
            }
            __syncthreads();
        }
        if (threadIdx.x == 0) {
            atomicMin(&g_dminu, smin[0]);
            atomicMax(&g_dmaxu, smax[0]);
        }
        return;
    }

    int t = threadIdx.x;
    if (t < 8) {
        int b = t >> 2;
        int v = (t & 3) + 1;
        double Ar[9], tr[3], As[9], ts[3];
        for (int which = 0; which < 2; ++which) {
            int view = which ? v : 0;
            const float* E = pm + ((b*VV + view)*2 + 0)*16;
            const float* K = pm + ((b*VV + view)*2 + 1)*16;
            double* A = which ? As : Ar;
            double* tv = which ? ts : tr;
            for (int r = 0; r < 3; ++r) {
                for (int c = 0; c < 3; ++c) {
                    double s = 0.0;
                    for (int k = 0; k < 3; ++k) s += (double)K[r*4+k]*(double)E[k*4+c];
                    A[r*3+c] = s;
                }
                double s = 0.0;
                for (int k = 0; k < 3; ++k) s += (double)K[r*4+k]*(double)E[k*4+3];
                tv[r] = s;
            }
        }
        double c00 = Ar[4]*Ar[8]-Ar[5]*Ar[7];
        double c01 = Ar[5]*Ar[6]-Ar[3]*Ar[8];
        double c02 = Ar[3]*Ar[7]-Ar[4]*Ar[6];
        double det = Ar[0]*c00 + Ar[1]*c01 + Ar[2]*c02;
        double id  = 1.0/det;
        double Ai[9];
        Ai[0] = c00*id;
        Ai[1] = (Ar[2]*Ar[7]-Ar[1]*Ar[8])*id;
        Ai[2] = (Ar[1]*Ar[5]-Ar[2]*Ar[4])*id;
        Ai[3] = c01*id;
        Ai[4] = (Ar[0]*Ar[8]-Ar[2]*Ar[6])*id;
        Ai[5] = (Ar[2]*Ar[3]-Ar[0]*Ar[5])*id;
        Ai[6] = c02*id;
        Ai[7] = (Ar[1]*Ar[6]-Ar[0]*Ar[7])*id;
        Ai[8] = (Ar[0]*Ar[4]-Ar[1]*Ar[3])*id;
        double rot[9];
        for (int r = 0; r < 3; ++r)
            for (int c = 0; c < 3; ++c) {
                double s = 0.0;
                for (int k = 0; k < 3; ++k) s += As[r*3+k]*Ai[k*3+c];
                rot[r*3+c] = s;
                g_rot[v-1][b][r*3+c] = (float)s;
            }
        for (int r = 0; r < 3; ++r) {
            double s = ts[r];
            for (int k = 0; k < 3; ++k) s -= rot[r*3+k]*tr[k];
            g_trans[v-1][b][r] = (float)s;
        }
    } else if (t >= 16 && t < 16 + 17*8) {
        // one thread per (interval i, hidden unit j): exact piecewise-affine MLP
        int i = (t - 16) >> 3;
        int j = (t - 16) & 7;
        double a[16], c[16];
        for (int o = 0; o < 16; ++o) {
            double ai = (double)g0[o] / sqrt((double)v0[o] + 1e-5);
            a[o] = (double)w0[o] * ai;
            c[o] = (double)b0[o] - (double)m0[o] * ai;
        }
        double thr[16];
        for (int o = 0; o < 16; ++o) {
            if (a[o] != 0.0) thr[o] = -c[o] / a[o];
            else             thr[o] = (c[o] > 0.0) ? -1e30 : 1e30;
        }
        for (int ii = 1; ii < 16; ++ii) {
            double key = thr[ii]; int jj = ii - 1;
            while (jj >= 0 && thr[jj] > key) { thr[jj+1] = thr[jj]; --jj; }
            thr[jj+1] = key;
        }
        if (i == 0 && j < 8) {
            if (j == 0) {
                for (int k = 0; k < 16; ++k) g_thr[k] = (float)thr[k];
                g_B2s = b2[0];
            }
            g_w2s[j] = w2[j];
        }
        double aij = (double)g1[j] / sqrt((double)v1[j] + 1e-5);
        double c1j = (double)b1[j] - (double)m1[j] * aij;
        double lo = (i == 0)  ? thr[0]  - 1.0 : thr[i-1];
        double hi = (i == 16) ? thr[15] + 1.0 : thr[i];
        double rep = 0.5*(lo + hi);
        double aj = 0.0, bj = c1j;
        for (int o = 0; o < 16; ++o) {
            if (a[o]*rep + c[o] > 0.0) {
                double w1f = (double)w1[j*16 + o] * aij;
                aj += w1f*a[o]; bj += w1f*c[o];
            }
        }
        g_abf[i*16 + j]     = (float)aj;
        g_abf[i*16 + 8 + j] = (float)bj;
    }
}

// ---------------------------------------------------------------------------
// k2: decide fast path (pure horizontal shift) + per-(v,b) shift windows
// ---------------------------------------------------------------------------
__global__ void flags_kernel()
{
    if (threadIdx.x != 0 || blockIdx.x != 0) return;
    float dmin = ord_dec(g_dminu), dmax = ord_dec(g_dmaxu);
    int fast = (dmin > 1e-3f) ? 1 : 0;
    for (int v = 0; v < 4 && fast; ++v)
        for (int b = 0; b < BB && fast; ++b) {
            const float* R = g_rot[v][b];
            const float* T = g_trans[v][b];
            float dev = 0.f;
            for (int i = 0; i < 9; ++i) {
                float ident = (i == 0 || i == 4 || i == 8) ? 1.f : 0.f;
                dev = fmaxf(dev, fabsf(R[i] - ident));
            }
            if (dev > 1e-5f || fabsf(T[1]) > 1e-3f || fabsf(T[2]) > 1e-3f) { fast = 0; break; }
            double tx = (double)T[0];
            double d0 = tx / (double)dmax, d1 = tx / (double)dmin;
            double dlo = fmin(d0, d1), dhi = fmax(d0, d1);
            int jl = (int)floor(dlo) - 1;
            int jh = (int)floor(dhi) + 1;
            int kt = jh - jl + 1;
            if (kt > 16) { fast = 0; break; }
            g_jlo[v][b]  = jl;
            g_ktap[v][b] = kt;
        }
    g_fast = fast;
}

// ---------------------------------------------------------------------------
// templated Q accumulation: Q(p,k) = sum_c ref_c(p) * src_c(p+k)
// NT = threads per block (Qs stride).
// ---------------------------------------------------------------------------
template<int KT, int NT>
__device__ __forceinline__ void qaccum(const float* __restrict__ refb,
                                       const float* __restrict__ srcb,
                                       int hw, int base, int klo, int khi,
                                       float* __restrict__ Qs, int tid)
{
    float Qr[KT];
    #pragma unroll
    for (int k = 0; k < KT; ++k) Qr[k] = 0.f;
    #pragma unroll 4
    for (int c = 0; c < CC; ++c) {
        float rc = __ldg(refb + (size_t)c*HWSZ + hw);
        const float* sc = srcb + (size_t)c*HWSZ + base;
        #pragma unroll
        for (int k = 0; k < KT; ++k) {
            float sv = (k >= klo && k <= khi) ? __ldg(sc + k) : 0.f;
            Qr[k] = fmaf(rc, sv, Qr[k]);
        }
    }
    #pragma unroll
    for (int k = 0; k < KT; ++k) Qs[k*NT + tid] = Qr[k];
}

// ---------------------------------------------------------------------------
// k3 (fast path): fully fused sim: view-sequential Q-factorized similarity +
// piecewise MLP + max->sigmoid vw + weighted accumulation -> g_sim directly.
// No per-view volume scratch, no combine pass.
// ---------------------------------------------------------------------------
__global__ void __launch_bounds__(64) simfuse_kernel(const float* __restrict__ feat,
                                                     const float* __restrict__ depthv,
                                                     float* __restrict__ out)
{
    if (!g_fast) return;
    __shared__ float  Qs[16*64];
    __shared__ float  ssim[DD*64];
    __shared__ float  s_thr[16];
    __shared__ float4 s_ab[17*4];
    __shared__ float  s_w2[8];
    __shared__ float  s_B2;
    if (threadIdx.x < 16) s_thr[threadIdx.x] = g_thr[threadIdx.x];
    if (threadIdx.x < 8)  s_w2[threadIdx.x] = g_w2s[threadIdx.x];
    if (threadIdx.x == 8) s_B2 = g_B2s;
    for (int i = threadIdx.x; i < 68; i += 64) s_ab[i] = ((const float4*)g_abf)[i];
    __syncthreads();

    int tid = threadIdx.x;
    int g  = blockIdx.x * 64 + tid;      // NPIX = 640*64 exactly
    int b  = g / HWSZ;
    int hw = g - b*HWSZ;
    int w  = hw % WW;

    const float* refb   = feat + (size_t)(b*CC)*HWSZ;
    const float* depcol = depthv + (size_t)(b*DD)*HWSZ + hw;

    float acc[DD];
    #pragma unroll
    for (int d = 0; d < DD; ++d) acc[d] = 0.f;
    float wsum = 1e-5f;

    for (int vi = 0; vi < 4; ++vi) {
        int jlo  = g_jlo[vi][b];
        int ktap = g_ktap[vi][b];
        float tx = g_trans[vi][b][0];
        const float* srcb = feat + (size_t)(((vi+1)*BB + b)*CC)*HWSZ;

        int klo = -(w + jlo);
        int khi = (WW-1) - (w + jlo);
        int base = hw + jlo;

        // each thread only touches its own Qs column -> no sync needed
        if (ktap <= 8)       qaccum<8,64>(refb, srcb, hw, base, klo, khi, Qs, tid);
        else if (ktap <= 12) qaccum<12,64>(refb, srcb, hw, base, klo, khi, Qs, tid);
        else                 qaccum<16,64>(refb, srcb, hw, base, klo, khi, Qs, tid);

        float vmaxo = -1e30f;
        int jcap = ktap - 2;

        for (int d = 0; d < DD; ++d) {
            float dep = __ldg(depcol + (size_t)d*HWSZ);
            float delta = __fdividef(tx, dep);
            float jf = floorf(delta);
            float fx = delta - jf;
            int jj = (int)jf - jlo;
            jj = min(max(jj, 0), jcap);
            float q0 = Qs[jj*64 + tid];
            float q1 = Qs[(jj+1)*64 + tid];
            float sim = fmaf(fx, q1 - q0, q0) * (1.f/32.f);
            ssim[d*64 + tid] = sim;

            int idx = 0;
            #pragma unroll
            for (int k = 0; k < 16; ++k) idx += (sim > s_thr[k]) ? 1 : 0;
            const float4* tab = s_ab + idx*4;
            float4 A0 = tab[0], A1 = tab[1], B0 = tab[2], B1 = tab[3];
            float o2 = s_B2;
            o2 = fmaf(s_w2[0], fmaxf(fmaf(A0.x, sim, B0.x), 0.f), o2);
            o2 = fmaf(s_w2[1], fmaxf(fmaf(A0.y, sim, B0.y), 0.f), o2);
            o2 = fmaf(s_w2[2], fmaxf(fmaf(A0.z, sim, B0.z), 0.f), o2);
            o2 = fmaf(s_w2[3], fmaxf(fmaf(A0.w, sim, B0.w), 0.f), o2);
            o2 = fmaf(s_w2[4], fmaxf(fmaf(A1.x, sim, B1.x), 0.f), o2);
            o2 = fmaf(s_w2[5], fmaxf(fmaf(A1.y, sim, B1.y), 0.f), o2);
            o2 = fmaf(s_w2[6], fmaxf(fmaf(A1.z, sim, B1.z), 0.f), o2);
            o2 = fmaf(s_w2[7], fmaxf(fmaf(A1.w, sim, B1.w), 0.f), o2);
            vmaxo = fmaxf(vmaxo, o2);
        }

        float vw = 1.f / (1.f + __expf(-vmaxo));
        out[OFF_VW + (b*4 + vi)*HWSZ + hw] = vw;
        wsum += vw;
        #pragma unroll
        for (int d = 0; d < DD; ++d)
            acc[d] = fmaf(ssim[d*64 + tid], vw, acc[d]);
    }

    float invw = 1.f / wsum;
    float* so = g_sim + (size_t)(b*DD)*HWSZ + hw;
    #pragma unroll
    for (int d = 0; d < DD; ++d) so[(size_t)d*HWSZ] = acc[d] * invw;
}

// ---------------------------------------------------------------------------
// k4 (general fallback): full bilinear gather path, 4 pixels per thread so
// the fast-path early exit costs only 80 blocks. Early-exits on fast path.
// ---------------------------------------------------------------------------
__global__ void __launch_bounds__(128) simgen_kernel(const float* __restrict__ feat,
                                                     const float* __restrict__ depthv,
                                                     float* __restrict__ out)
{
    if (g_fast) return;
    __shared__ float  s_thr[16];
    __shared__ float4 s_ab[17*4];
    __shared__ float  s_w2[8];
    __shared__ float  s_B2;
    __shared__ float  ssim[DD*128];
    if (threadIdx.x < 16) s_thr[threadIdx.x] = g_thr[threadIdx.x];
    if (threadIdx.x < 68) s_ab[threadIdx.x] = ((const float4*)g_abf)[threadIdx.x];
    if (threadIdx.x < 8)  s_w2[threadIdx.x] = g_w2s[threadIdx.x];
    if (threadIdx.x == 8) s_B2 = g_B2s;
    __syncthreads();

    for (int pp = 0; pp < 4; ++pp) {
        int g  = pp*10240 + blockIdx.x * 128 + threadIdx.x;
        int b  = g / HWSZ;
        int hw = g - b*HWSZ;
        int h  = hw / WW, w = hw - h*WW;
        float xf = (float)w, yf = (float)h;

        const float* ref = feat + (size_t)(b*CC)*HWSZ + hw;
        float refv[CC];
        #pragma unroll
        for (int c = 0; c < CC; ++c) refv[c] = __ldg(ref + (size_t)c*HWSZ);

        float acc[DD];
        #pragma unroll
        for (int d = 0; d < DD; ++d) acc[d] = 0.f;
        float wsum = 1e-5f;
        const float* depcol = depthv + (size_t)(b*DD)*HWSZ + hw;

        for (int v = 1; v < VV; ++v) {
            const float* R = g_rot[v-1][b];
            const float* T = g_trans[v-1][b];
            float rx = R[0]*xf + R[1]*yf + R[2];
            float ry = R[3]*xf + R[4]*yf + R[5];
            float rz = R[6]*xf + R[7]*yf + R[8];
            float tx = T[0], ty = T[1], tz = T[2];
            const float* src = feat + (size_t)((v*BB + b)*CC)*HWSZ;
            float vmaxo = -1e30f;

            for (int d = 0; d < DD; ++d) {
                float dep = __ldg(depcol + (size_t)d*HWSZ);
                float px = fmaf(rx, dep, tx);
                float py = fmaf(ry, dep, ty);
                float pz = fmaf(rz, dep, tz);
                float iz = 1.0f / pz;
                float xs = px * iz, ys = py * iz;
                float x0f = floorf(xs), y0f = floorf(ys);
                float wx = xs - x0f, wy = ys - y0f;
                int ix = (int)x0f, iy = (int)y0f;
                float w00 = (1.f-wx)*(1.f-wy), w01 = wx*(1.f-wy);
                float w10 = (1.f-wx)*wy,       w11 = wx*wy;
                bool vx0 = (ix   >= 0) && (ix   < WW);
                bool vx1 = (ix+1 >= 0) && (ix+1 < WW);
                bool vy0 = (iy   >= 0) && (iy   < HH);
                bool vy1 = (iy+1 >= 0) && (iy+1 < HH);
                if (!(vx0 && vy0)) w00 = 0.f;
                if (!(vx1 && vy0)) w01 = 0.f;
                if (!(vx0 && vy1)) w10 = 0.f;
                if (!(vx1 && vy1)) w11 = 0.f;
                int x0c = min(max(ix,   0), WW-1), x1c = min(max(ix+1, 0), WW-1);
                int y0c = min(max(iy,   0), HH-1), y1c = min(max(iy+1, 0), HH-1);
                int o00 = y0c*WW + x0c, o01 = y0c*WW + x1c;
                int o10 = y1c*WW + x0c, o11 = y1c*WW + x1c;

                float s = 0.f;
                #pragma unroll
                for (int c = 0; c < CC; ++c) {
                    const float* p = src + (size_t)c*HWSZ;
                    float tap = fmaf(w00, __ldg(p+o00),
                                fmaf(w01, __ldg(p+o01),
                                fmaf(w10, __ldg(p+o10), w11 * __ldg(p+o11))));
                    s = fmaf(tap, refv[c], s);
                }
                float sim = s * (1.f/32.f);
                ssim[d*128 + threadIdx.x] = sim;

                int idx = 0;
                #pragma unroll
                for (int k = 0; k < 16; ++k) idx += (sim > s_thr[k]) ? 1 : 0;
                const float4* tab = s_ab + idx*4;
                float4 A0 = tab[0], A1 = tab[1], B0 = tab[2], B1 = tab[3];
                float o2 = s_B2;
                o2 = fmaf(s_w2[0], fmaxf(fmaf(A0.x, sim, B0.x), 0.f), o2);
                o2 = fmaf(s_w2[1], fmaxf(fmaf(A0.y, sim, B0.y), 0.f), o2);
                o2 = fmaf(s_w2[2], fmaxf(fmaf(A0.z, sim, B0.z), 0.f), o2);
                o2 = fmaf(s_w2[3], fmaxf(fmaf(A0.w, sim, B0.w), 0.f), o2);
                o2 = fmaf(s_w2[4], fmaxf(fmaf(A1.x, sim, B1.x), 0.f), o2);
                o2 = fmaf(s_w2[5], fmaxf(fmaf(A1.y, sim, B1.y), 0.f), o2);
                o2 = fmaf(s_w2[6], fmaxf(fmaf(A1.z, sim, B1.z), 0.f), o2);
                o2 = fmaf(s_w2[7], fmaxf(fmaf(A1.w, sim, B1.w), 0.f), o2);
                vmaxo = fmaxf(vmaxo, o2);
            }

            float vmax = 1.f / (1.f + __expf(-vmaxo));
            out[OFF_VW + (b*4 + (v-1))*HWSZ + hw] = vmax;
            wsum += vmax;
            #pragma unroll
            for (int d = 0; d < DD; ++d)
                acc[d] = fmaf(ssim[d*128 + threadIdx.x], vmax, acc[d]);
        }

        float invw = 1.f / wsum;
        float* so = g_sim + (size_t)(b*DD)*HWSZ + hw;
        #pragma unroll
        for (int d = 0; d < DD; ++d) so[(size_t)d*HWSZ] = acc[d] * invw;
    }
}

// ---------------------------------------------------------------------------
// k5: 3x3x3 conv + softmax + argmax, D split across 8 threads per pixel.
// Correlation orientation: cost[d] += rw[kd]*sim[d+kd-1]  =>  kd = dd - d + 1.
// ---------------------------------------------------------------------------
__global__ void __launch_bounds__(256) post_kernel(const float* __restrict__ depthv,
                                                   const float* __restrict__ regw,
                                                   const float* __restrict__ regb,
                                                   float* __restrict__ out)
{
    __shared__ float rw[27];
    __shared__ float rb;
    __shared__ float red[8][33];
    __shared__ int   redi[8][33];
    int tx = threadIdx.x;   // pixel lane 0..31
    int ty = threadIdx.y;   // d-group 0..7
    int lin = ty*32 + tx;
    if (lin < 27) rw[lin] = regw[lin];
    if (lin == 27) rb = regb[0];
    __syncthreads();

    int g  = blockIdx.x * 32 + tx;
    int b  = g / HWSZ;
    int hw = g - b*HWSZ;
    int h  = hw / WW, w = hw - h*WW;
    int dbase = ty * 4;
    const float* simb = g_sim + (size_t)(b*DD)*HWSZ;

    float cost[4] = {rb, rb, rb, rb};

    #pragma unroll
    for (int o = 0; o < 6; ++o) {
        int dd = dbase - 1 + o;
        if (dd < 0 || dd >= DD) continue;
        float s[9];
        #pragma unroll
        for (int kh = 0; kh < 3; ++kh)
            #pragma unroll
            for (int kw = 0; kw < 3; ++kw) {
                int h2 = h + kh - 1, w2 = w + kw - 1;
                s[kh*3+kw] = (h2 >= 0 && h2 < HH && w2 >= 0 && w2 < WW)
                             ? __ldg(simb + (size_t)dd*HWSZ + h2*WW + w2) : 0.f;
            }
        #pragma unroll
        for (int q = 0; q < 4; ++q) {
            int kd = dd - (dbase + q) + 1;   // correlation: dd = d + kd - 1
            if (kd >= 0 && kd <= 2) {
                float p = 0.f;
                #pragma unroll
                for (int i = 0; i < 9; ++i) p = fmaf(rw[kd*9+i], s[i], p);
                cost[q] += p;
            }
        }
    }

    float lm = fmaxf(fmaxf(cost[0], cost[1]), fmaxf(cost[2], cost[3]));
    red[ty][tx] = lm;
    __syncthreads();
    float m;
    {
        float t0 = fmaxf(red[0][tx], red[1][tx]);
        float t1 = fmaxf(red[2][tx], red[3][tx]);
        float t2 = fmaxf(red[4][tx], red[5][tx]);
        float t3 = fmaxf(red[6][tx], red[7][tx]);
        m = fmaxf(fmaxf(t0, t1), fmaxf(t2, t3));
    }
    __syncthreads();

    float e[4];
    float ls = 0.f;
    #pragma unroll
    for (int q = 0; q < 4; ++q) { e[q] = __expf(cost[q] - m); ls += e[q]; }
    red[ty][tx] = ls;
    __syncthreads();
    float sum = red[0][tx] + red[1][tx] + red[2][tx] + red[3][tx]
              + red[4][tx] + red[5][tx] + red[6][tx] + red[7][tx];
    float isum = 1.f / sum;
    __syncthreads();

    int li = 0; float lb = cost[0];
    #pragma unroll
    for (int q = 1; q < 4; ++q) if (cost[q] > lb) { lb = cost[q]; li = q; }
    red[ty][tx]  = lb;
    redi[ty][tx] = dbase + li;
    __syncthreads();

    if (ty == 0) {
        float best = red[0][tx]; int bi = redi[0][tx];
        #pragma unroll
        for (int yy = 1; yy < 8; ++yy)
            if (red[yy][tx] > best) { best = red[yy][tx]; bi = redi[yy][tx]; }
        out[OFF_DEPTH + g] = __ldg(depthv + (size_t)(b*DD + bi)*HWSZ + hw);
        out[OFF_CONF  + g] = isum;
    }

    #pragma unroll
    for (int q = 0; q < 4; ++q) {
        int d = dbase + q;
        out[OFF_PROB + (size_t)(b*DD + d)*HWSZ + hw] = e[q] * isum;
        out[OFF_COST + (size_t)(b*DD + d)*HWSZ + hw] = cost[q];
    }
}

extern "C" void kernel_launch(void* const* d_in, const int* in_sizes, int n_in,
                              void* d_out, int out_size)
{
    const float* feat   = (const float*)d_in[0];
    const float* pm     = (const float*)d_in[1];
    const float* depthv = (const float*)d_in[2];
    int base = (n_in >= 18) ? 4 : 3;
    const float* w0 = (const float*)d_in[base + 0];
    const float* g0 = (const float*)d_in[base + 1];
    const float* b0 = (const float*)d_in[base + 2];
    const float* m0 = (const float*)d_in[base + 3];
    const float* v0 = (const float*)d_in[base + 4];
    const float* w1 = (const float*)d_in[base + 5];
    const float* g1 = (const float*)d_in[base + 6];
    const float* b1 = (const float*)d_in[base + 7];
    const float* m1 = (const float*)d_in[base + 8];
    const float* v1 = (const float*)d_in[base + 9];
    const float* w2 = (const float*)d_in[base + 10];
    const float* b2 = (const float*)d_in[base + 11];
    const float* regw = (const float*)d_in[base + 12];
    const float* regb = (const float*)d_in[base + 13];
    float* out = (float*)d_out;

    prep_minmax<<<129, 256>>>(depthv, pm, w0, g0, b0, m0, v0,
                              w1, g1, b1, m1, v1, w2, b2);
    flags_kernel<<<1, 1>>>();
    simfuse_kernel<<<NPIX/64, 64>>>(feat, depthv, out);
    simgen_kernel<<<80, 128>>>(feat, depthv, out);
    post_kernel<<<NPIX/32, dim3(32, 8)>>>(depthv, regw, regb, out);
}

// round 11
// speedup vs baseline: 1.0977x; 1.0977x over previous
#include <cuda_runtime.h>
#include <math.h>

#define HH 128
#define WW 160
#define CC 32
#define DD 32
#define BB 2
#define VV 5
#define HWSZ (HH*WW)       // 20480
#define NPIX (BB*HWSZ)     // 40960
#define NDEP (BB*DD*HWSZ)  // 1310720
#define SEG 144            // staged segment length: 128 + 16

// out layout (flattened tuple in reference-return order):
#define OFF_DEPTH 0
#define OFF_CONF  40960
#define OFF_PROB  81920
#define OFF_COST  1392640
#define OFF_VW    2703360

__device__ float g_rot[4][BB][9];
__device__ float g_trans[4][BB][3];
// piecewise-affine MLP table: g_abf[i*16 + j] = alpha_j, [i*16+8+j] = beta_j
__device__ float g_thr[16];
__device__ float g_abf[17*16];
__device__ float g_w2s[8];
__device__ float g_B2s;
__device__ float g_sim[BB*DD*HWSZ];
__device__ float g_simv[4*BB*DD*HWSZ];   // per-view sim volumes (fast path)
__device__ unsigned g_dminu = 0xFFFFFFFFu;  // ordered-encoded min (idempotent across replays)
__device__ unsigned g_dmaxu = 0u;
__device__ int g_fast;
__device__ int g_jlo[4][BB];
__device__ int g_ktap[4][BB];

__device__ __forceinline__ unsigned ord_enc(float x) {
    unsigned u = __float_as_uint(x);
    return (u & 0x80000000u) ? ~u : (u | 0x80000000u);
}
__device__ __forceinline__ float ord_dec(unsigned u) {
    u = (u & 0x80000000u) ? (u & 0x7FFFFFFFu) : ~u;
    return __uint_as_float(u);
}

// ---------------------------------------------------------------------------
// k1: fused prep (block 128) + depth minmax (blocks 0..127).
// ---------------------------------------------------------------------------
__global__ void __launch_bounds__(256) prep_minmax(const float* __restrict__ depthv,
    const float* __restrict__ pm,
    const float* __restrict__ w0, const float* __restrict__ g0,
    const float* __restrict__ b0, const float* __restrict__ m0, const float* __restrict__ v0,
    const float* __restrict__ w1, const float* __restrict__ g1,
    const float* __restrict__ b1, const float* __restrict__ m1, const float* __restrict__ v1,
    const float* __restrict__ w2, const float* __restrict__ b2)
{
    if (blockIdx.x < 128) {
        __shared__ unsigned smin[256], smax[256];
        unsigned mn = 0xFFFFFFFFu, mx = 0u;
        for (int i = blockIdx.x*256 + threadIdx.x; i < NDEP; i += 128*256) {
            unsigned e = ord_enc(depthv[i]);
            mn = min(mn, e); mx = max(mx, e);
        }
        smin[threadIdx.x] = mn; smax[threadIdx.x] = mx;
        __syncthreads();
        for (int s = 128; s > 0; s >>= 1) {
            if (threadIdx.x < s) {
                smin[threadIdx.x] = min(smin[threadIdx.x], smin[threadIdx.x+s]);
                smax[threadIdx.x] = max(smax[threadIdx.x], smax[threadIdx.x+s]);
            }
            __syncthreads();
        }
        if (threadIdx.x == 0) {
            atomicMin(&g_dminu, smin[0]);
            atomicMax(&g_dmaxu, smax[0]);
        }
        return;
    }

    int t = threadIdx.x;
    if (t < 8) {
        int b = t >> 2;
        int v = (t & 3) + 1;
        double Ar[9], tr[3], As[9], ts[3];
        for (int which = 0; which < 2; ++which) {
            int view = which ? v : 0;
            const float* E = pm + ((b*VV + view)*2 + 0)*16;
            const float* K = pm + ((b*VV + view)*2 + 1)*16;
            double* A = which ? As : Ar;
            double* tv = which ? ts : tr;
            for (int r = 0; r < 3; ++r) {
                for (int c = 0; c < 3; ++c) {
                    double s = 0.0;
                    for (int k = 0; k < 3; ++k) s += (double)K[r*4+k]*(double)E[k*4+c];
                    A[r*3+c] = s;
                }
                double s = 0.0;
                for (int k = 0; k < 3; ++k) s += (double)K[r*4+k]*(double)E[k*4+3];
                tv[r] = s;
            }
        }
        double c00 = Ar[4]*Ar[8]-Ar[5]*Ar[7];
        double c01 = Ar[5]*Ar[6]-Ar[3]*Ar[8];
        double c02 = Ar[3]*Ar[7]-Ar[4]*Ar[6];
        double det = Ar[0]*c00 + Ar[1]*c01 + Ar[2]*c02;
        double id  = 1.0/det;
        double Ai[9];
        Ai[0] = c00*id;
        Ai[1] = (Ar[2]*Ar[7]-Ar[1]*Ar[8])*id;
        Ai[2] = (Ar[1]*Ar[5]-Ar[2]*Ar[4])*id;
        Ai[3] = c01*id;
        Ai[4] = (Ar[0]*Ar[8]-Ar[2]*Ar[6])*id;
        Ai[5] = (Ar[2]*Ar[3]-Ar[0]*Ar[5])*id;
        Ai[6] = c02*id;
        Ai[7] = (Ar[1]*Ar[6]-Ar[0]*Ar[7])*id;
        Ai[8] = (Ar[0]*Ar[4]-Ar[1]*Ar[3])*id;
        double rot[9];
        for (int r = 0; r < 3; ++r)
            for (int c = 0; c < 3; ++c) {
                double s = 0.0;
                for (int k = 0; k < 3; ++k) s += As[r*3+k]*Ai[k*3+c];
                rot[r*3+c] = s;
                g_rot[v-1][b][r*3+c] = (float)s;
            }
        for (int r = 0; r < 3; ++r) {
            double s = ts[r];
            for (int k = 0; k < 3; ++k) s -= rot[r*3+k]*tr[k];
            g_trans[v-1][b][r] = (float)s;
        }
    } else if (t >= 16 && t < 16 + 17*8) {
        // one thread per (interval i, hidden unit j): exact piecewise-affine MLP
        int i = (t - 16) >> 3;
        int j = (t - 16) & 7;
        double a[16], c[16];
        for (int o = 0; o < 16; ++o) {
            double ai = (double)g0[o] / sqrt((double)v0[o] + 1e-5);
            a[o] = (double)w0[o] * ai;
            c[o] = (double)b0[o] - (double)m0[o] * ai;
        }
        double thr[16];
        for (int o = 0; o < 16; ++o) {
            if (a[o] != 0.0) thr[o] = -c[o] / a[o];
            else             thr[o] = (c[o] > 0.0) ? -1e30 : 1e30;
        }
        for (int ii = 1; ii < 16; ++ii) {
            double key = thr[ii]; int jj = ii - 1;
            while (jj >= 0 && thr[jj] > key) { thr[jj+1] = thr[jj]; --jj; }
            thr[jj+1] = key;
        }
        if (i == 0 && j < 8) {
            if (j == 0) {
                for (int k = 0; k < 16; ++k) g_thr[k] = (float)thr[k];
                g_B2s = b2[0];
            }
            g_w2s[j] = w2[j];
        }
        double aij = (double)g1[j] / sqrt((double)v1[j] + 1e-5);
        double c1j = (double)b1[j] - (double)m1[j] * aij;
        double lo = (i == 0)  ? thr[0]  - 1.0 : thr[i-1];
        double hi = (i == 16) ? thr[15] + 1.0 : thr[i];
        double rep = 0.5*(lo + hi);
        double aj = 0.0, bj = c1j;
        for (int o = 0; o < 16; ++o) {
            if (a[o]*rep + c[o] > 0.0) {
                double w1f = (double)w1[j*16 + o] * aij;
                aj += w1f*a[o]; bj += w1f*c[o];
            }
        }
        g_abf[i*16 + j]     = (float)aj;
        g_abf[i*16 + 8 + j] = (float)bj;
    }
}

// ---------------------------------------------------------------------------
// k2: decide fast path (pure horizontal shift) + per-(v,b) shift windows
// ---------------------------------------------------------------------------
__global__ void flags_kernel()
{
    if (threadIdx.x != 0 || blockIdx.x != 0) return;
    float dmin = ord_dec(g_dminu), dmax = ord_dec(g_dmaxu);
    int fast = (dmin > 1e-3f) ? 1 : 0;
    for (int v = 0; v < 4 && fast; ++v)
        for (int b = 0; b < BB && fast; ++b) {
            const float* R = g_rot[v][b];
            const float* T = g_trans[v][b];
            float dev = 0.f;
            for (int i = 0; i < 9; ++i) {
                float ident = (i == 0 || i == 4 || i == 8) ? 1.f : 0.f;
                dev = fmaxf(dev, fabsf(R[i] - ident));
            }
            if (dev > 1e-5f || fabsf(T[1]) > 1e-3f || fabsf(T[2]) > 1e-3f) { fast = 0; break; }
            double tx = (double)T[0];
            double d0 = tx / (double)dmax, d1 = tx / (double)dmin;
            double dlo = fmin(d0, d1), dhi = fmax(d0, d1);
            int jl = (int)floor(dlo) - 1;
            int jh = (int)floor(dhi) + 1;
            int kt = jh - jl + 1;
            if (kt > 16) { fast = 0; break; }
            g_jlo[v][b]  = jl;
            g_ktap[v][b] = kt;
        }
    g_fast = fast;
}

// ---------------------------------------------------------------------------
// templated Q accumulation from a staged shared segment.
// sh layout: sh[c*SEG + i] = src[c*HWSZ + clamp(blockhw + jlo + i)]
// Thread tid's tap k value sits at sh[c*SEG + tid + k]. Pure LDS+FMA inner
// loop; the (c-independent) window mask is applied once per k at the end.
// ---------------------------------------------------------------------------
template<int KT>
__device__ __forceinline__ void qaccum_sh(const float* __restrict__ refb,
                                          const float* __restrict__ sh,
                                          int hw, int klo, int khi,
                                          float* __restrict__ Qs, int tid)
{
    float Qr[KT];
    #pragma unroll
    for (int k = 0; k < KT; ++k) Qr[k] = 0.f;
    #pragma unroll 4
    for (int c = 0; c < CC; ++c) {
        float rc = __ldg(refb + (size_t)c*HWSZ + hw);
        const float* sc = sh + c*SEG + tid;
        #pragma unroll
        for (int k = 0; k < KT; ++k)
            Qr[k] = fmaf(rc, sc[k], Qr[k]);
    }
    #pragma unroll
    for (int k = 0; k < KT; ++k)
        Qs[k*128 + tid] = (k >= klo && k <= khi) ? Qr[k] : 0.f;
}

// ---------------------------------------------------------------------------
// k3 (fast path): shift-factorized similarity with block-staged source rows.
// Block = (128 pixels, 1 view).
// ---------------------------------------------------------------------------
__global__ void __launch_bounds__(128) simfast_kernel(const float* __restrict__ feat,
                                                      const float* __restrict__ depthv,
                                                      float* __restrict__ out)
{
    if (!g_fast) return;
    __shared__ float  sh[CC*SEG];      // 18 KB staged source segment
    __shared__ float  Qs[16*128];      // 8 KB
    __shared__ float  s_thr[16];
    __shared__ float4 s_ab[17*4];
    __shared__ float  s_w2[8];
    __shared__ float  s_B2;
    if (threadIdx.x < 16) s_thr[threadIdx.x] = g_thr[threadIdx.x];
    if (threadIdx.x < 68) s_ab[threadIdx.x] = ((const float4*)g_abf)[threadIdx.x];
    if (threadIdx.x < 8)  s_w2[threadIdx.x] = g_w2s[threadIdx.x];
    if (threadIdx.x == 8) s_B2 = g_B2s;

    int tid = threadIdx.x;
    int g  = blockIdx.x * 128 + tid;
    int vi = blockIdx.y;
    int b  = g / HWSZ;
    int hw = g - b*HWSZ;
    int w  = hw % WW;
    int hwblock = (blockIdx.x * 128) % HWSZ;   // same b for whole block

    int jlo  = g_jlo[vi][b];
    int ktap = g_ktap[vi][b];
    float tx = g_trans[vi][b][0];

    const float* refb = feat + (size_t)(b*CC)*HWSZ;
    const float* srcb = feat + (size_t)(((vi+1)*BB + b)*CC)*HWSZ;

    // cooperative stage: 32 channels x SEG floats, coalesced, clamped
    {
        int segbase = hwblock + jlo;
        for (int idx = tid; idx < CC*SEG; idx += 128) {
            int c = idx / SEG;
            int i = idx - c*SEG;
            int p = min(max(segbase + i, 0), HWSZ-1);
            sh[idx] = __ldg(srcb + (size_t)c*HWSZ + p);
        }
    }
    __syncthreads();

    // valid k window for this pixel: 0 <= w + jlo + k <= WW-1
    int klo = -(w + jlo);
    int khi = (WW-1) - (w + jlo);

    if (ktap <= 8)       qaccum_sh<8>(refb, sh, hw, klo, khi, Qs, tid);
    else if (ktap <= 12) qaccum_sh<12>(refb, sh, hw, klo, khi, Qs, tid);
    else                 qaccum_sh<16>(refb, sh, hw, klo, khi, Qs, tid);

    const float* depcol = depthv + (size_t)(b*DD)*HWSZ + hw;
    float* svout = g_simv + ((size_t)(vi*BB + b)*DD)*HWSZ + hw;
    float vmaxo = -1e30f;
    int jcap = ktap - 2;

    for (int d = 0; d < DD; ++d) {
        float dep = __ldg(depcol + (size_t)d*HWSZ);
        float delta = __fdividef(tx, dep);
        float jf = floorf(delta);
        float fx = delta - jf;
        int jj = (int)jf - jlo;
        jj = min(max(jj, 0), jcap);
        float q0 = Qs[jj*128 + tid];
        float q1 = Qs[(jj+1)*128 + tid];
        float sim = fmaf(fx, q1 - q0, q0) * (1.f/32.f);
        svout[(size_t)d*HWSZ] = sim;

        int idx = 0;
        #pragma unroll
        for (int k = 0; k < 16; ++k) idx += (sim > s_thr[k]) ? 1 : 0;
        const float4* tab = s_ab + idx*4;
        float4 A0 = tab[0], A1 = tab[1], B0 = tab[2], B1 = tab[3];
        float o2 = s_B2;
        o2 = fmaf(s_w2[0], fmaxf(fmaf(A0.x, sim, B0.x), 0.f), o2);
        o2 = fmaf(s_w2[1], fmaxf(fmaf(A0.y, sim, B0.y), 0.f), o2);
        o2 = fmaf(s_w2[2], fmaxf(fmaf(A0.z, sim, B0.z), 0.f), o2);
        o2 = fmaf(s_w2[3], fmaxf(fmaf(A0.w, sim, B0.w), 0.f), o2);
        o2 = fmaf(s_w2[4], fmaxf(fmaf(A1.x, sim, B1.x), 0.f), o2);
        o2 = fmaf(s_w2[5], fmaxf(fmaf(A1.y, sim, B1.y), 0.f), o2);
        o2 = fmaf(s_w2[6], fmaxf(fmaf(A1.z, sim, B1.z), 0.f), o2);
        o2 = fmaf(s_w2[7], fmaxf(fmaf(A1.w, sim, B1.w), 0.f), o2);
        vmaxo = fmaxf(vmaxo, o2);
    }

    out[OFF_VW + (b*4 + vi)*HWSZ + hw] = 1.f / (1.f + __expf(-vmaxo));
}

// ---------------------------------------------------------------------------
// k4 (general fallback): full bilinear gather path, 4 pixels per thread so
// the fast-path early exit costs only 80 blocks. Early-exits on fast path.
// ---------------------------------------------------------------------------
__global__ void __launch_bounds__(128) simgen_kernel(const float* __restrict__ feat,
                                                     const float* __restrict__ depthv,
                                                     float* __restrict__ out)
{
    if (g_fast) return;
    __shared__ float  s_thr[16];
    __shared__ float4 s_ab[17*4];
    __shared__ float  s_w2[8];
    __shared__ float  s_B2;
    __shared__ float  ssim[DD*128];
    if (threadIdx.x < 16) s_thr[threadIdx.x] = g_thr[threadIdx.x];
    if (threadIdx.x < 68) s_ab[threadIdx.x] = ((const float4*)g_abf)[threadIdx.x];
    if (threadIdx.x < 8)  s_w2[threadIdx.x] = g_w2s[threadIdx.x];
    if (threadIdx.x == 8) s_B2 = g_B2s;
    __syncthreads();

    for (int pp = 0; pp < 4; ++pp) {
        int g  = pp*10240 + blockIdx.x * 128 + threadIdx.x;
        int b  = g / HWSZ;
        int hw = g - b*HWSZ;
        int h  = hw / WW, w = hw - h*WW;
        float xf = (float)w, yf = (float)h;

        const float* ref = feat + (size_t)(b*CC)*HWSZ + hw;
        float refv[CC];
        #pragma unroll
        for (int c = 0; c < CC; ++c) refv[c] = __ldg(ref + (size_t)c*HWSZ);

        float acc[DD];
        #pragma unroll
        for (int d = 0; d < DD; ++d) acc[d] = 0.f;
        float wsum = 1e-5f;
        const float* depcol = depthv + (size_t)(b*DD)*HWSZ + hw;

        for (int v = 1; v < VV; ++v) {
            const float* R = g_rot[v-1][b];
            const float* T = g_trans[v-1][b];
            float rx = R[0]*xf + R[1]*yf + R[2];
            float ry = R[3]*xf + R[4]*yf + R[5];
            float rz = R[6]*xf + R[7]*yf + R[8];
            float tx = T[0], ty = T[1], tz = T[2];
            const float* src = feat + (size_t)((v*BB + b)*CC)*HWSZ;
            float vmaxo = -1e30f;

            for (int d = 0; d < DD; ++d) {
                float dep = __ldg(depcol + (size_t)d*HWSZ);
                float px = fmaf(rx, dep, tx);
                float py = fmaf(ry, dep, ty);
                float pz = fmaf(rz, dep, tz);
                float iz = 1.0f / pz;
                float xs = px * iz, ys = py * iz;
                float x0f = floorf(xs), y0f = floorf(ys);
                float wx = xs - x0f, wy = ys - y0f;
                int ix = (int)x0f, iy = (int)y0f;
                float w00 = (1.f-wx)*(1.f-wy), w01 = wx*(1.f-wy);
                float w10 = (1.f-wx)*wy,       w11 = wx*wy;
                bool vx0 = (ix   >= 0) && (ix   < WW);
                bool vx1 = (ix+1 >= 0) && (ix+1 < WW);
                bool vy0 = (iy   >= 0) && (iy   < HH);
                bool vy1 = (iy+1 >= 0) && (iy+1 < HH);
                if (!(vx0 && vy0)) w00 = 0.f;
                if (!(vx1 && vy0)) w01 = 0.f;
                if (!(vx0 && vy1)) w10 = 0.f;
                if (!(vx1 && vy1)) w11 = 0.f;
                int x0c = min(max(ix,   0), WW-1), x1c = min(max(ix+1, 0), WW-1);
                int y0c = min(max(iy,   0), HH-1), y1c = min(max(iy+1, 0), HH-1);
                int o00 = y0c*WW + x0c, o01 = y0c*WW + x1c;
                int o10 = y1c*WW + x0c, o11 = y1c*WW + x1c;

                float s = 0.f;
                #pragma unroll
                for (int c = 0; c < CC; ++c) {
                    const float* p = src + (size_t)c*HWSZ;
                    float tap = fmaf(w00, __ldg(p+o00),
                                fmaf(w01, __ldg(p+o01),
                                fmaf(w10, __ldg(p+o10), w11 * __ldg(p+o11))));
                    s = fmaf(tap, refv[c], s);
                }
                float sim = s * (1.f/32.f);
                ssim[d*128 + threadIdx.x] = sim;

                int idx = 0;
                #pragma unroll
                for (int k = 0; k < 16; ++k) idx += (sim > s_thr[k]) ? 1 : 0;
                const float4* tab = s_ab + idx*4;
                float4 A0 = tab[0], A1 = tab[1], B0 = tab[2], B1 = tab[3];
                float o2 = s_B2;
                o2 = fmaf(s_w2[0], fmaxf(fmaf(A0.x, sim, B0.x), 0.f), o2);
                o2 = fmaf(s_w2[1], fmaxf(fmaf(A0.y, sim, B0.y), 0.f), o2);
                o2 = fmaf(s_w2[2], fmaxf(fmaf(A0.z, sim, B0.z), 0.f), o2);
                o2 = fmaf(s_w2[3], fmaxf(fmaf(A0.w, sim, B0.w), 0.f), o2);
                o2 = fmaf(s_w2[4], fmaxf(fmaf(A1.x, sim, B1.x), 0.f), o2);
                o2 = fmaf(s_w2[5], fmaxf(fmaf(A1.y, sim, B1.y), 0.f), o2);
                o2 = fmaf(s_w2[6], fmaxf(fmaf(A1.z, sim, B1.z), 0.f), o2);
                o2 = fmaf(s_w2[7], fmaxf(fmaf(A1.w, sim, B1.w), 0.f), o2);
                vmaxo = fmaxf(vmaxo, o2);
            }

            float vmax = 1.f / (1.f + __expf(-vmaxo));
            out[OFF_VW + (b*4 + (v-1))*HWSZ + hw] = vmax;
            wsum += vmax;
            #pragma unroll
            for (int d = 0; d < DD; ++d)
                acc[d] = fmaf(ssim[d*128 + threadIdx.x], vmax, acc[d]);
        }

        float invw = 1.f / wsum;
        float* so = g_sim + (size_t)(b*DD)*HWSZ + hw;
        #pragma unroll
        for (int d = 0; d < DD; ++d) so[(size_t)d*HWSZ] = acc[d] * invw;
    }
}

// ---------------------------------------------------------------------------
// k5 (fast path only): combine views, float4 over pixels.
// ---------------------------------------------------------------------------
__global__ void __launch_bounds__(128) combine_kernel(float* __restrict__ out)
{
    if (!g_fast) return;
    int t  = blockIdx.x * 128 + threadIdx.x;
    int g4 = t * 4;
    int b  = g4 / HWSZ;
    int hw = g4 - b*HWSZ;

    float4 vw0 = *(const float4*)(out + OFF_VW + (size_t)(b*4 + 0)*HWSZ + hw);
    float4 vw1 = *(const float4*)(out + OFF_VW + (size_t)(b*4 + 1)*HWSZ + hw);
    float4 vw2 = *(const float4*)(out + OFF_VW + (size_t)(b*4 + 2)*HWSZ + hw);
    float4 vw3 = *(const float4*)(out + OFF_VW + (size_t)(b*4 + 3)*HWSZ + hw);
    float4 inv;
    inv.x = 1.f / (1e-5f + vw0.x + vw1.x + vw2.x + vw3.x);
    inv.y = 1.f / (1e-5f + vw0.y + vw1.y + vw2.y + vw3.y);
    inv.z = 1.f / (1e-5f + vw0.z + vw1.z + vw2.z + vw3.z);
    inv.w = 1.f / (1e-5f + vw0.w + vw1.w + vw2.w + vw3.w);

    const float* s0 = g_simv + ((size_t)(0*BB + b)*DD)*HWSZ + hw;
    const float* s1 = g_simv + ((size_t)(1*BB + b)*DD)*HWSZ + hw;
    const float* s2 = g_simv + ((size_t)(2*BB + b)*DD)*HWSZ + hw;
    const float* s3 = g_simv + ((size_t)(3*BB + b)*DD)*HWSZ + hw;
    float* so = g_sim + (size_t)(b*DD)*HWSZ + hw;

    #pragma unroll 4
    for (int d = 0; d < DD; ++d) {
        float4 a = *(const float4*)(s0 + (size_t)d*HWSZ);
        float4 bq= *(const float4*)(s1 + (size_t)d*HWSZ);
        float4 c = *(const float4*)(s2 + (size_t)d*HWSZ);
        float4 e = *(const float4*)(s3 + (size_t)d*HWSZ);
        float4 r;
        r.x = (a.x*vw0.x + bq.x*vw1.x + c.x*vw2.x + e.x*vw3.x) * inv.x;
        r.y = (a.y*vw0.y + bq.y*vw1.y + c.y*vw2.y + e.y*vw3.y) * inv.y;
        r.z = (a.z*vw0.z + bq.z*vw1.z + c.z*vw2.z + e.z*vw3.z) * inv.z;
        r.w = (a.w*vw0.w + bq.w*vw1.w + c.w*vw2.w + e.w*vw3.w) * inv.w;
        *(float4*)(so + (size_t)d*HWSZ) = r;
    }
}

// ---------------------------------------------------------------------------
// k6: 3x3x3 conv + softmax + argmax, D split across 8 threads per pixel.
// Correlation orientation: cost[d] += rw[kd]*sim[d+kd-1]  =>  kd = dd - d + 1.
// ---------------------------------------------------------------------------
__global__ void __launch_bounds__(256) post_kernel(const float* __restrict__ depthv,
                                                   const float* __restrict__ regw,
                                                   const float* __restrict__ regb,
                                                   float* __restrict__ out)
{
    __shared__ float rw[27];
    __shared__ float rb;
    __shared__ float red[8][33];
    __shared__ int   redi[8][33];
    int tx = threadIdx.x;   // pixel lane 0..31
    int ty = threadIdx.y;   // d-group 0..7
    int lin = ty*32 + tx;
    if (lin < 27) rw[lin] = regw[lin];
    if (lin == 27) rb = regb[0];
    __syncthreads();

    int g  = blockIdx.x * 32 + tx;
    int b  = g / HWSZ;
    int hw = g - b*HWSZ;
    int h  = hw / WW, w = hw - h*WW;
    int dbase = ty * 4;
    const float* simb = g_sim + (size_t)(b*DD)*HWSZ;

    float cost[4] = {rb, rb, rb, rb};

    #pragma unroll
    for (int o = 0; o < 6; ++o) {
        int dd = dbase - 1 + o;
        if (dd < 0 || dd >= DD) continue;
        float s[9];
        #pragma unroll
        for (int kh = 0; kh < 3; ++kh)
            #pragma unroll
            for (int kw = 0; kw < 3; ++kw) {
                int h2 = h + kh - 1, w2 = w + kw - 1;
                s[kh*3+kw] = (h2 >= 0 && h2 < HH && w2 >= 0 && w2 < WW)
                             ? __ldg(simb + (size_t)dd*HWSZ + h2*WW + w2) : 0.f;
            }
        #pragma unroll
        for (int q = 0; q < 4; ++q) {
            int kd = dd - (dbase + q) + 1;   // correlation: dd = d + kd - 1
            if (kd >= 0 && kd <= 2) {
                float p = 0.f;
                #pragma unroll
                for (int i = 0; i < 9; ++i) p = fmaf(rw[kd*9+i], s[i], p);
                cost[q] += p;
            }
        }
    }

    float lm = fmaxf(fmaxf(cost[0], cost[1]), fmaxf(cost[2], cost[3]));
    red[ty][tx] = lm;
    __syncthreads();
    float m;
    {
        float t0 = fmaxf(red[0][tx], red[1][tx]);
        float t1 = fmaxf(red[2][tx], red[3][tx]);
        float t2 = fmaxf(red[4][tx], red[5][tx]);
        float t3 = fmaxf(red[6][tx], red[7][tx]);
        m = fmaxf(fmaxf(t0, t1), fmaxf(t2, t3));
    }
    __syncthreads();

    float e[4];
    float ls = 0.f;
    #pragma unroll
    for (int q = 0; q < 4; ++q) { e[q] = __expf(cost[q] - m); ls += e[q]; }
    red[ty][tx] = ls;
    __syncthreads();
    float sum = red[0][tx] + red[1][tx] + red[2][tx] + red[3][tx]
              + red[4][tx] + red[5][tx] + red[6][tx] + red[7][tx];
    float isum = 1.f / sum;
    __syncthreads();

    int li = 0; float lb = cost[0];
    #pragma unroll
    for (int q = 1; q < 4; ++q) if (cost[q] > lb) { lb = cost[q]; li = q; }
    red[ty][tx]  = lb;
    redi[ty][tx] = dbase + li;
    __syncthreads();

    if (ty == 0) {
        float best = red[0][tx]; int bi = redi[0][tx];
        #pragma unroll
        for (int yy = 1; yy < 8; ++yy)
            if (red[yy][tx] > best) { best = red[yy][tx]; bi = redi[yy][tx]; }
        out[OFF_DEPTH + g] = __ldg(depthv + (size_t)(b*DD + bi)*HWSZ + hw);
        out[OFF_CONF  + g] = isum;
    }

    #pragma unroll
    for (int q = 0; q < 4; ++q) {
        int d = dbase + q;
        out[OFF_PROB + (size_t)(b*DD + d)*HWSZ + hw] = e[q] * isum;
        out[OFF_COST + (size_t)(b*DD + d)*HWSZ + hw] = cost[q];
    }
}

extern "C" void kernel_launch(void* const* d_in, const int* in_sizes, int n_in,
                              void* d_out, int out_size)
{
    const float* feat   = (const float*)d_in[0];
    const float* pm     = (const float*)d_in[1];
    const float* depthv = (const float*)d_in[2];
    int base = (n_in >= 18) ? 4 : 3;
    const float* w0 = (const float*)d_in[base + 0];
    const float* g0 = (const float*)d_in[base + 1];
    const float* b0 = (const float*)d_in[base + 2];
    const float* m0 = (const float*)d_in[base + 3];
    const float* v0 = (const float*)d_in[base + 4];
    const float* w1 = (const float*)d_in[base + 5];
    const float* g1 = (const float*)d_in[base + 6];
    const float* b1 = (const float*)d_in[base + 7];
    const float* m1 = (const float*)d_in[base + 8];
    const float* v1 = (const float*)d_in[base + 9];
    const float* w2 = (const float*)d_in[base + 10];
    const float* b2 = (const float*)d_in[base + 11];
    const float* regw = (const float*)d_in[base + 12];
    const float* regb = (const float*)d_in[base + 13];
    float* out = (float*)d_out;

    prep_minmax<<<129, 256>>>(depthv, pm, w0, g0, b0, m0, v0,
                              w1, g1, b1, m1, v1, w2, b2);
    flags_kernel<<<1, 1>>>();
    simfast_kernel<<<dim3(NPIX/128, 4), 128>>>(feat, depthv, out);
    simgen_kernel<<<80, 128>>>(feat, depthv, out);
    combine_kernel<<<NPIX/4/128, 128>>>(out);
    post_kernel<<<NPIX/32, dim3(32, 8)>>>(depthv, regw, regb, out);
}

// round 12
// speedup vs baseline: 1.1919x; 1.0858x over previous
#include <cuda_runtime.h>
#include <math.h>

#define HH 128
#define WW 160
#define CC 32
#define DD 32
#define BB 2
#define VV 5
#define HWSZ (HH*WW)       // 20480
#define NPIX (BB*HWSZ)     // 40960
#define NDEP (BB*DD*HWSZ)  // 1310720

// out layout (flattened tuple in reference-return order):
#define OFF_DEPTH 0
#define OFF_CONF  40960
#define OFF_PROB  81920
#define OFF_COST  1392640
#define OFF_VW    2703360

__device__ float g_rot[4][BB][9];
__device__ float g_trans[4][BB][3];
// piecewise-affine MLP table: g_abf[i*16 + j] = alpha_j, [i*16+8+j] = beta_j
__device__ float g_thr[16];
__device__ float g_abf[17*16];
__device__ float g_w2s[8];
__device__ float g_B2s;
__device__ float g_sim[BB*DD*HWSZ];
__device__ float g_simv[4*BB*DD*HWSZ];   // per-view sim volumes (fast path)
__device__ unsigned g_dminu = 0xFFFFFFFFu;  // ordered-encoded min (idempotent across replays)
__device__ unsigned g_dmaxu = 0u;
__device__ int g_uni = 1;                // depth spatially uniform? (idempotent: only cleared)
__device__ int g_fast;
__device__ int g_jlo[4][BB];
__device__ int g_ktap[4][BB];
__device__ int   g_dj[4][BB][DD];        // per-(v,b,d) tap index (uniform-depth path)
__device__ float g_df[4][BB][DD];        // per-(v,b,d) lerp fraction

__device__ __forceinline__ unsigned ord_enc(float x) {
    unsigned u = __float_as_uint(x);
    return (u & 0x80000000u) ? ~u : (u | 0x80000000u);
}
__device__ __forceinline__ float ord_dec(unsigned u) {
    u = (u & 0x80000000u) ? (u & 0x7FFFFFFFu) : ~u;
    return __uint_as_float(u);
}

// folded pixelwise MLP via exact piecewise-affine table
__device__ __forceinline__ float mlp_o2(float sim,
    const float* __restrict__ s_thr, const float4* __restrict__ s_ab,
    const float* __restrict__ s_w2, float s_B2)
{
    int idx = 0;
    #pragma unroll
    for (int k = 0; k < 16; ++k) idx += (sim > s_thr[k]) ? 1 : 0;
    const float4* tab = s_ab + idx*4;
    float4 A0 = tab[0], A1 = tab[1], B0 = tab[2], B1 = tab[3];
    float o2 = s_B2;
    o2 = fmaf(s_w2[0], fmaxf(fmaf(A0.x, sim, B0.x), 0.f), o2);
    o2 = fmaf(s_w2[1], fmaxf(fmaf(A0.y, sim, B0.y), 0.f), o2);
    o2 = fmaf(s_w2[2], fmaxf(fmaf(A0.z, sim, B0.z), 0.f), o2);
    o2 = fmaf(s_w2[3], fmaxf(fmaf(A0.w, sim, B0.w), 0.f), o2);
    o2 = fmaf(s_w2[4], fmaxf(fmaf(A1.x, sim, B1.x), 0.f), o2);
    o2 = fmaf(s_w2[5], fmaxf(fmaf(A1.y, sim, B1.y), 0.f), o2);
    o2 = fmaf(s_w2[6], fmaxf(fmaf(A1.z, sim, B1.z), 0.f), o2);
    o2 = fmaf(s_w2[7], fmaxf(fmaf(A1.w, sim, B1.w), 0.f), o2);
    return o2;
}

// ---------------------------------------------------------------------------
// k1: fused prep (block 128) + depth minmax & uniformity (blocks 0..127).
// ---------------------------------------------------------------------------
__global__ void __launch_bounds__(256) prep_minmax(const float* __restrict__ depthv,
    const float* __restrict__ pm,
    const float* __restrict__ w0, const float* __restrict__ g0,
    const float* __restrict__ b0, const float* __restrict__ m0, const float* __restrict__ v0,
    const float* __restrict__ w1, const float* __restrict__ g1,
    const float* __restrict__ b1, const float* __restrict__ m1, const float* __restrict__ v1,
    const float* __restrict__ w2, const float* __restrict__ b2)
{
    if (blockIdx.x < 128) {
        __shared__ unsigned smin[256], smax[256];
        unsigned mn = 0xFFFFFFFFu, mx = 0u;
        int mism = 0;
        for (int i = blockIdx.x*256 + threadIdx.x; i < NDEP; i += 128*256) {
            float dv = depthv[i];
            unsigned e = ord_enc(dv);
            mn = min(mn, e); mx = max(mx, e);
            // uniformity: compare bitwise against the (b,d)-slice head
            int head = (i / HWSZ) * HWSZ;
            if (__float_as_uint(dv) != __float_as_uint(__ldg(depthv + head))) mism = 1;
        }
        smin[threadIdx.x] = mn; smax[threadIdx.x] = mx;
        __syncthreads();
        for (int s = 128; s > 0; s >>= 1) {
            if (threadIdx.x < s) {
                smin[threadIdx.x] = min(smin[threadIdx.x], smin[threadIdx.x+s]);
                smax[threadIdx.x] = max(smax[threadIdx.x], smax[threadIdx.x+s]);
            }
            __syncthreads();
        }
        if (threadIdx.x == 0) {
            atomicMin(&g_dminu, smin[0]);
            atomicMax(&g_dmaxu, smax[0]);
        }
        if (mism) g_uni = 0;   // only ever cleared -> idempotent across replays
        return;
    }

    int t = threadIdx.x;
    if (t < 8) {
        int b = t >> 2;
        int v = (t & 3) + 1;
        double Ar[9], tr[3], As[9], ts[3];
        for (int which = 0; which < 2; ++which) {
            int view = which ? v : 0;
            const float* E = pm + ((b*VV + view)*2 + 0)*16;
            const float* K = pm + ((b*VV + view)*2 + 1)*16;
            double* A = which ? As : Ar;
            double* tv = which ? ts : tr;
            for (int r = 0; r < 3; ++r) {
                for (int c = 0; c < 3; ++c) {
                    double s = 0.0;
                    for (int k = 0; k < 3; ++k) s += (double)K[r*4+k]*(double)E[k*4+c];
                    A[r*3+c] = s;
                }
                double s = 0.0;
                for (int k = 0; k < 3; ++k) s += (double)K[r*4+k]*(double)E[k*4+3];
                tv[r] = s;
            }
        }
        double c00 = Ar[4]*Ar[8]-Ar[5]*Ar[7];
        double c01 = Ar[5]*Ar[6]-Ar[3]*Ar[8];
        double c02 = Ar[3]*Ar[7]-Ar[4]*Ar[6];
        double det = Ar[0]*c00 + Ar[1]*c01 + Ar[2]*c02;
        double id  = 1.0/det;
        double Ai[9];
        Ai[0] = c00*id;
        Ai[1] = (Ar[2]*Ar[7]-Ar[1]*Ar[8])*id;
        Ai[2] = (Ar[1]*Ar[5]-Ar[2]*Ar[4])*id;
        Ai[3] = c01*id;
        Ai[4] = (Ar[0]*Ar[8]-Ar[2]*Ar[6])*id;
        Ai[5] = (Ar[2]*Ar[3]-Ar[0]*Ar[5])*id;
        Ai[6] = c02*id;
        Ai[7] = (Ar[1]*Ar[6]-Ar[0]*Ar[7])*id;
        Ai[8] = (Ar[0]*Ar[4]-Ar[1]*Ar[3])*id;
        double rot[9];
        for (int r = 0; r < 3; ++r)
            for (int c = 0; c < 3; ++c) {
                double s = 0.0;
                for (int k = 0; k < 3; ++k) s += As[r*3+k]*Ai[k*3+c];
                rot[r*3+c] = s;
                g_rot[v-1][b][r*3+c] = (float)s;
            }
        for (int r = 0; r < 3; ++r) {
            double s = ts[r];
            for (int k = 0; k < 3; ++k) s -= rot[r*3+k]*tr[k];
            g_trans[v-1][b][r] = (float)s;
        }
    } else if (t >= 16 && t < 16 + 17*8) {
        // one thread per (interval i, hidden unit j): exact piecewise-affine MLP
        int i = (t - 16) >> 3;
        int j = (t - 16) & 7;
        double a[16], c[16];
        for (int o = 0; o < 16; ++o) {
            double ai = (double)g0[o] / sqrt((double)v0[o] + 1e-5);
            a[o] = (double)w0[o] * ai;
            c[o] = (double)b0[o] - (double)m0[o] * ai;
        }
        double thr[16];
        for (int o = 0; o < 16; ++o) {
            if (a[o] != 0.0) thr[o] = -c[o] / a[o];
            else             thr[o] = (c[o] > 0.0) ? -1e30 : 1e30;
        }
        for (int ii = 1; ii < 16; ++ii) {
            double key = thr[ii]; int jj = ii - 1;
            while (jj >= 0 && thr[jj] > key) { thr[jj+1] = thr[jj]; --jj; }
            thr[jj+1] = key;
        }
        if (i == 0 && j < 8) {
            if (j == 0) {
                for (int k = 0; k < 16; ++k) g_thr[k] = (float)thr[k];
                g_B2s = b2[0];
            }
            g_w2s[j] = w2[j];
        }
        double aij = (double)g1[j] / sqrt((double)v1[j] + 1e-5);
        double c1j = (double)b1[j] - (double)m1[j] * aij;
        double lo = (i == 0)  ? thr[0]  - 1.0 : thr[i-1];
        double hi = (i == 16) ? thr[15] + 1.0 : thr[i];
        double rep = 0.5*(lo + hi);
        double aj = 0.0, bj = c1j;
        for (int o = 0; o < 16; ++o) {
            if (a[o]*rep + c[o] > 0.0) {
                double w1f = (double)w1[j*16 + o] * aij;
                aj += w1f*a[o]; bj += w1f*c[o];
            }
        }
        g_abf[i*16 + j]     = (float)aj;
        g_abf[i*16 + 8 + j] = (float)bj;
    }
}

// ---------------------------------------------------------------------------
// k2: decide fast path + shift windows; if depth uniform, precompute per-
// (v,b,d) tap index and lerp fraction with the SAME float ops as the per-
// pixel path (bit-identical results).
// ---------------------------------------------------------------------------
__global__ void __launch_bounds__(256) flags_kernel(const float* __restrict__ depthv)
{
    __shared__ int s_fast;
    if (threadIdx.x == 0) {
        float dmin = ord_dec(g_dminu), dmax = ord_dec(g_dmaxu);
        int fast = (dmin > 1e-3f) ? 1 : 0;
        for (int v = 0; v < 4 && fast; ++v)
            for (int b = 0; b < BB && fast; ++b) {
                const float* R = g_rot[v][b];
                const float* T = g_trans[v][b];
                float dev = 0.f;
                for (int i = 0; i < 9; ++i) {
                    float ident = (i == 0 || i == 4 || i == 8) ? 1.f : 0.f;
                    dev = fmaxf(dev, fabsf(R[i] - ident));
                }
                if (dev > 1e-5f || fabsf(T[1]) > 1e-3f || fabsf(T[2]) > 1e-3f) { fast = 0; break; }
                double tx = (double)T[0];
                double d0 = tx / (double)dmax, d1 = tx / (double)dmin;
                double dlo = fmin(d0, d1), dhi = fmax(d0, d1);
                int jl = (int)floor(dlo) - 1;
                int jh = (int)floor(dhi) + 1;
                int kt = jh - jl + 1;
                if (kt > 16) { fast = 0; break; }
                g_jlo[v][b]  = jl;
                g_ktap[v][b] = kt;
            }
        g_fast = fast;
        s_fast = fast;
    }
    __syncthreads();
    if (s_fast && g_uni) {
        int t = threadIdx.x;          // 256 = 4*2*32 exactly
        int v = t >> 6;
        int b = (t >> 5) & 1;
        int d = t & 31;
        float dep = __ldg(depthv + (size_t)(b*DD + d)*HWSZ);   // slice head
        float tx  = g_trans[v][b][0];
        float delta = __fdividef(tx, dep);
        float jf = floorf(delta);
        float fx = delta - jf;
        int jj = (int)jf - g_jlo[v][b];
        jj = min(max(jj, 0), g_ktap[v][b] - 2);
        g_dj[v][b][d] = jj;
        g_df[v][b][d] = fx;
    }
}

// ---------------------------------------------------------------------------
// templated Q accumulation: Q(p,k) = sum_c ref_c(p) * src_c(p+k)
// ---------------------------------------------------------------------------
template<int KT>
__device__ __forceinline__ void qaccum(const float* __restrict__ refb,
                                       const float* __restrict__ srcb,
                                       int hw, int base, int klo, int khi,
                                       float* __restrict__ Qs, int tid)
{
    float Qr[KT];
    #pragma unroll
    for (int k = 0; k < KT; ++k) Qr[k] = 0.f;
    #pragma unroll 4
    for (int c = 0; c < CC; ++c) {
        float rc = __ldg(refb + (size_t)c*HWSZ + hw);
        const float* sc = srcb + (size_t)c*HWSZ + base;
        #pragma unroll
        for (int k = 0; k < KT; ++k) {
            float sv = (k >= klo && k <= khi) ? __ldg(sc + k) : 0.f;
            Qr[k] = fmaf(rc, sv, Qr[k]);
        }
    }
    #pragma unroll
    for (int k = 0; k < KT; ++k) Qs[k*128 + tid] = Qr[k];
}

// ---------------------------------------------------------------------------
// k3 (fast path): shift-factorized similarity + piecewise MLP + max -> vw.
// Uniform-depth mode replaces the per-pixel depth load/div/floor with a
// shared 32-entry (jj, fx) table.
// ---------------------------------------------------------------------------
__global__ void __launch_bounds__(128) simfast_kernel(const float* __restrict__ feat,
                                                      const float* __restrict__ depthv,
                                                      float* __restrict__ out)
{
    if (!g_fast) return;
    __shared__ float  Qs[16*128];
    __shared__ float  s_thr[16];
    __shared__ float4 s_ab[17*4];
    __shared__ float  s_w2[8];
    __shared__ float  s_B2;
    __shared__ int    s_dj[DD];
    __shared__ float  s_df[DD];

    int tid = threadIdx.x;
    int g  = blockIdx.x * 128 + tid;
    int vi = blockIdx.y;
    int b  = g / HWSZ;            // same for whole block (HWSZ % 128 == 0)
    int hw = g - b*HWSZ;
    int w  = hw % WW;
    int uni = g_uni;

    if (tid < 16) s_thr[tid] = g_thr[tid];
    if (tid < 68) s_ab[tid] = ((const float4*)g_abf)[tid];
    if (tid < 8)  s_w2[tid] = g_w2s[tid];
    if (tid == 8) s_B2 = g_B2s;
    if (uni && tid < DD) { s_dj[tid] = g_dj[vi][b][tid]; s_df[tid] = g_df[vi][b][tid]; }
    __syncthreads();

    int jlo  = g_jlo[vi][b];
    int ktap = g_ktap[vi][b];
    float tx = g_trans[vi][b][0];

    const float* refb = feat + (size_t)(b*CC)*HWSZ;
    const float* srcb = feat + (size_t)(((vi+1)*BB + b)*CC)*HWSZ;

    int klo = -(w + jlo);
    int khi = (WW-1) - (w + jlo);
    int base = hw + jlo;

    if (ktap <= 8)       qaccum<8>(refb, srcb, hw, base, klo, khi, Qs, tid);
    else if (ktap <= 12) qaccum<12>(refb, srcb, hw, base, klo, khi, Qs, tid);
    else                 qaccum<16>(refb, srcb, hw, base, klo, khi, Qs, tid);

    float* svout = g_simv + ((size_t)(vi*BB + b)*DD)*HWSZ + hw;
    float vmaxo = -1e30f;

    if (uni) {
        #pragma unroll 8
        for (int d = 0; d < DD; ++d) {
            int jj = s_dj[d];
            float fx = s_df[d];
            float q0 = Qs[jj*128 + tid];
            float q1 = Qs[(jj+1)*128 + tid];
            float sim = fmaf(fx, q1 - q0, q0) * (1.f/32.f);
            svout[(size_t)d*HWSZ] = sim;
            vmaxo = fmaxf(vmaxo, mlp_o2(sim, s_thr, (const float4*)s_ab, s_w2, s_B2));
        }
    } else {
        const float* depcol = depthv + (size_t)(b*DD)*HWSZ + hw;
        int jcap = ktap - 2;
        for (int d = 0; d < DD; ++d) {
            float dep = __ldg(depcol + (size_t)d*HWSZ);
            float delta = __fdividef(tx, dep);
            float jf = floorf(delta);
            float fx = delta - jf;
            int jj = (int)jf - jlo;
            jj = min(max(jj, 0), jcap);
            float q0 = Qs[jj*128 + tid];
            float q1 = Qs[(jj+1)*128 + tid];
            float sim = fmaf(fx, q1 - q0, q0) * (1.f/32.f);
            svout[(size_t)d*HWSZ] = sim;
            vmaxo = fmaxf(vmaxo, mlp_o2(sim, s_thr, (const float4*)s_ab, s_w2, s_B2));
        }
    }

    out[OFF_VW + (b*4 + vi)*HWSZ + hw] = 1.f / (1.f + __expf(-vmaxo));
}

// ---------------------------------------------------------------------------
// k4 (general fallback): full bilinear gather path, 4 pixels per thread.
// Early-exits on fast path.
// ---------------------------------------------------------------------------
__global__ void __launch_bounds__(128) simgen_kernel(const float* __restrict__ feat,
                                                     const float* __restrict__ depthv,
                                                     float* __restrict__ out)
{
    if (g_fast) return;
    __shared__ float  s_thr[16];
    __shared__ float4 s_ab[17*4];
    __shared__ float  s_w2[8];
    __shared__ float  s_B2;
    __shared__ float  ssim[DD*128];
    if (threadIdx.x < 16) s_thr[threadIdx.x] = g_thr[threadIdx.x];
    if (threadIdx.x < 68) s_ab[threadIdx.x] = ((const float4*)g_abf)[threadIdx.x];
    if (threadIdx.x < 8)  s_w2[threadIdx.x] = g_w2s[threadIdx.x];
    if (threadIdx.x == 8) s_B2 = g_B2s;
    __syncthreads();

    for (int pp = 0; pp < 4; ++pp) {
        int g  = pp*10240 + blockIdx.x * 128 + threadIdx.x;
        int b  = g / HWSZ;
        int hw = g - b*HWSZ;
        int h  = hw / WW, w = hw - h*WW;
        float xf = (float)w, yf = (float)h;

        const float* ref = feat + (size_t)(b*CC)*HWSZ + hw;
        float refv[CC];
        #pragma unroll
        for (int c = 0; c < CC; ++c) refv[c] = __ldg(ref + (size_t)c*HWSZ);

        float acc[DD];
        #pragma unroll
        for (int d = 0; d < DD; ++d) acc[d] = 0.f;
        float wsum = 1e-5f;
        const float* depcol = depthv + (size_t)(b*DD)*HWSZ + hw;

        for (int v = 1; v < VV; ++v) {
            const float* R = g_rot[v-1][b];
            const float* T = g_trans[v-1][b];
            float rx = R[0]*xf + R[1]*yf + R[2];
            float ry = R[3]*xf + R[4]*yf + R[5];
            float rz = R[6]*xf + R[7]*yf + R[8];
            float tx = T[0], ty = T[1], tz = T[2];
            const float* src = feat + (size_t)((v*BB + b)*CC)*HWSZ;
            float vmaxo = -1e30f;

            for (int d = 0; d < DD; ++d) {
                float dep = __ldg(depcol + (size_t)d*HWSZ);
                float px = fmaf(rx, dep, tx);
                float py = fmaf(ry, dep, ty);
                float pz = fmaf(rz, dep, tz);
                float iz = 1.0f / pz;
                float xs = px * iz, ys = py * iz;
                float x0f = floorf(xs), y0f = floorf(ys);
                float wx = xs - x0f, wy = ys - y0f;
                int ix = (int)x0f, iy = (int)y0f;
                float w00 = (1.f-wx)*(1.f-wy), w01 = wx*(1.f-wy);
                float w10 = (1.f-wx)*wy,       w11 = wx*wy;
                bool vx0 = (ix   >= 0) && (ix   < WW);
                bool vx1 = (ix+1 >= 0) && (ix+1 < WW);
                bool vy0 = (iy   >= 0) && (iy   < HH);
                bool vy1 = (iy+1 >= 0) && (iy+1 < HH);
                if (!(vx0 && vy0)) w00 = 0.f;
                if (!(vx1 && vy0)) w01 = 0.f;
                if (!(vx0 && vy1)) w10 = 0.f;
                if (!(vx1 && vy1)) w11 = 0.f;
                int x0c = min(max(ix,   0), WW-1), x1c = min(max(ix+1, 0), WW-1);
                int y0c = min(max(iy,   0), HH-1), y1c = min(max(iy+1, 0), HH-1);
                int o00 = y0c*WW + x0c, o01 = y0c*WW + x1c;
                int o10 = y1c*WW + x0c, o11 = y1c*WW + x1c;

                float s = 0.f;
                #pragma unroll
                for (int c = 0; c < CC; ++c) {
                    const float* p = src + (size_t)c*HWSZ;
                    float tap = fmaf(w00, __ldg(p+o00),
                                fmaf(w01, __ldg(p+o01),
                                fmaf(w10, __ldg(p+o10), w11 * __ldg(p+o11))));
                    s = fmaf(tap, refv[c], s);
                }
                float sim = s * (1.f/32.f);
                ssim[d*128 + threadIdx.x] = sim;
                vmaxo = fmaxf(vmaxo, mlp_o2(sim, s_thr, (const float4*)s_ab, s_w2, s_B2));
            }

            float vmax = 1.f / (1.f + __expf(-vmaxo));
            out[OFF_VW + (b*4 + (v-1))*HWSZ + hw] = vmax;
            wsum += vmax;
            #pragma unroll
            for (int d = 0; d < DD; ++d)
                acc[d] = fmaf(ssim[d*128 + threadIdx.x], vmax, acc[d]);
        }

        float invw = 1.f / wsum;
        float* so = g_sim + (size_t)(b*DD)*HWSZ + hw;
        #pragma unroll
        for (int d = 0; d < DD; ++d) so[(size_t)d*HWSZ] = acc[d] * invw;
    }
}

// ---------------------------------------------------------------------------
// k5 (fast path only): combine views, float4 over pixels.
// ---------------------------------------------------------------------------
__global__ void __launch_bounds__(128) combine_kernel(float* __restrict__ out)
{
    if (!g_fast) return;
    int t  = blockIdx.x * 128 + threadIdx.x;
    int g4 = t * 4;
    int b  = g4 / HWSZ;
    int hw = g4 - b*HWSZ;

    float4 vw0 = *(const float4*)(out + OFF_VW + (size_t)(b*4 + 0)*HWSZ + hw);
    float4 vw1 = *(const float4*)(out + OFF_VW + (size_t)(b*4 + 1)*HWSZ + hw);
    float4 vw2 = *(const float4*)(out + OFF_VW + (size_t)(b*4 + 2)*HWSZ + hw);
    float4 vw3 = *(const float4*)(out + OFF_VW + (size_t)(b*4 + 3)*HWSZ + hw);
    float4 inv;
    inv.x = 1.f / (1e-5f + vw0.x + vw1.x + vw2.x + vw3.x);
    inv.y = 1.f / (1e-5f + vw0.y + vw1.y + vw2.y + vw3.y);
    inv.z = 1.f / (1e-5f + vw0.z + vw1.z + vw2.z + vw3.z);
    inv.w = 1.f / (1e-5f + vw0.w + vw1.w + vw2.w + vw3.w);

    const float* s0 = g_simv + ((size_t)(0*BB + b)*DD)*HWSZ + hw;
    const float* s1 = g_simv + ((size_t)(1*BB + b)*DD)*HWSZ + hw;
    const float* s2 = g_simv + ((size_t)(2*BB + b)*DD)*HWSZ + hw;
    const float* s3 = g_simv + ((size_t)(3*BB + b)*DD)*HWSZ + hw;
    float* so = g_sim + (size_t)(b*DD)*HWSZ + hw;

    #pragma unroll 4
    for (int d = 0; d < DD; ++d) {
        float4 a = *(const float4*)(s0 + (size_t)d*HWSZ);
        float4 bq= *(const float4*)(s1 + (size_t)d*HWSZ);
        float4 c = *(const float4*)(s2 + (size_t)d*HWSZ);
        float4 e = *(const float4*)(s3 + (size_t)d*HWSZ);
        float4 r;
        r.x = (a.x*vw0.x + bq.x*vw1.x + c.x*vw2.x + e.x*vw3.x) * inv.x;
        r.y = (a.y*vw0.y + bq.y*vw1.y + c.y*vw2.y + e.y*vw3.y) * inv.y;
        r.z = (a.z*vw0.z + bq.z*vw1.z + c.z*vw2.z + e.z*vw3.z) * inv.z;
        r.w = (a.w*vw0.w + bq.w*vw1.w + c.w*vw2.w + e.w*vw3.w) * inv.w;
        *(float4*)(so + (size_t)d*HWSZ) = r;
    }
}

// ---------------------------------------------------------------------------
// k6: 3x3x3 conv + softmax + argmax, D split across 8 threads per pixel.
// Correlation orientation: cost[d] += rw[kd]*sim[d+kd-1]  =>  kd = dd - d + 1.
// ---------------------------------------------------------------------------
__global__ void __launch_bounds__(256) post_kernel(const float* __restrict__ depthv,
                                                   const float* __restrict__ regw,
                                                   const float* __restrict__ regb,
                                                   float* __restrict__ out)
{
    __shared__ float rw[27];
    __shared__ float rb;
    __shared__ float red[8][33];
    __shared__ int   redi[8][33];
    int tx = threadIdx.x;   // pixel lane 0..31
    int ty = threadIdx.y;   // d-group 0..7
    int lin = ty*32 + tx;
    if (lin < 27) rw[lin] = regw[lin];
    if (lin == 27) rb = regb[0];
    __syncthreads();

    int g  = blockIdx.x * 32 + tx;
    int b  = g / HWSZ;
    int hw = g - b*HWSZ;
    int h  = hw / WW, w = hw - h*WW;
    int dbase = ty * 4;
    const float* simb = g_sim + (size_t)(b*DD)*HWSZ;

    float cost[4] = {rb, rb, rb, rb};

    #pragma unroll
    for (int o = 0; o < 6; ++o) {
        int dd = dbase - 1 + o;
        if (dd < 0 || dd >= DD) continue;
        float s[9];
        #pragma unroll
        for (int kh = 0; kh < 3; ++kh)
            #pragma unroll
            for (int kw = 0; kw < 3; ++kw) {
                int h2 = h + kh - 1, w2 = w + kw - 1;
                s[kh*3+kw] = (h2 >= 0 && h2 < HH && w2 >= 0 && w2 < WW)
                             ? __ldg(simb + (size_t)dd*HWSZ + h2*WW + w2) : 0.f;
            }
        #pragma unroll
        for (int q = 0; q < 4; ++q) {
            int kd = dd - (dbase + q) + 1;   // correlation: dd = d + kd - 1
            if (kd >= 0 && kd <= 2) {
                float p = 0.f;
                #pragma unroll
                for (int i = 0; i < 9; ++i) p = fmaf(rw[kd*9+i], s[i], p);
                cost[q] += p;
            }
        }
    }

    float lm = fmaxf(fmaxf(cost[0], cost[1]), fmaxf(cost[2], cost[3]));
    red[ty][tx] = lm;
    __syncthreads();
    float m;
    {
        float t0 = fmaxf(red[0][tx], red[1][tx]);
        float t1 = fmaxf(red[2][tx], red[3][tx]);
        float t2 = fmaxf(red[4][tx], red[5][tx]);
        float t3 = fmaxf(red[6][tx], red[7][tx]);
        m = fmaxf(fmaxf(t0, t1), fmaxf(t2, t3));
    }
    __syncthreads();

    float e[4];
    float ls = 0.f;
    #pragma unroll
    for (int q = 0; q < 4; ++q) { e[q] = __expf(cost[q] - m); ls += e[q]; }
    red[ty][tx] = ls;
    __syncthreads();
    float sum = red[0][tx] + red[1][tx] + red[2][tx] + red[3][tx]
              + red[4][tx] + red[5][tx] + red[6][tx] + red[7][tx];
    float isum = 1.f / sum;
    __syncthreads();

    int li = 0; float lb = cost[0];
    #pragma unroll
    for (int q = 1; q < 4; ++q) if (cost[q] > lb) { lb = cost[q]; li = q; }
    red[ty][tx]  = lb;
    redi[ty][tx] = dbase + li;
    __syncthreads();

    if (ty == 0) {
        float best = red[0][tx]; int bi = redi[0][tx];
        #pragma unroll
        for (int yy = 1; yy < 8; ++yy)
            if (red[yy][tx] > best) { best = red[yy][tx]; bi = redi[yy][tx]; }
        out[OFF_DEPTH + g] = __ldg(depthv + (size_t)(b*DD + bi)*HWSZ + hw);
        out[OFF_CONF  + g] = isum;
    }

    #pragma unroll
    for (int q = 0; q < 4; ++q) {
        int d = dbase + q;
        out[OFF_PROB + (size_t)(b*DD + d)*HWSZ + hw] = e[q] * isum;
        out[OFF_COST + (size_t)(b*DD + d)*HWSZ + hw] = cost[q];
    }
}

extern "C" void kernel_launch(void* const* d_in, const int* in_sizes, int n_in,
                              void* d_out, int out_size)
{
    const float* feat   = (const float*)d_in[0];
    const float* pm     = (const float*)d_in[1];
    const float* depthv = (const float*)d_in[2];
    int base = (n_in >= 18) ? 4 : 3;
    const float* w0 = (const float*)d_in[base + 0];
    const float* g0 = (const float*)d_in[base + 1];
    const float* b0 = (const float*)d_in[base + 2];
    const float* m0 = (const float*)d_in[base + 3];
    const float* v0 = (const float*)d_in[base + 4];
    const float* w1 = (const float*)d_in[base + 5];
    const float* g1 = (const float*)d_in[base + 6];
    const float* b1 = (const float*)d_in[base + 7];
    const float* m1 = (const float*)d_in[base + 8];
    const float* v1 = (const float*)d_in[base + 9];
    const float* w2 = (const float*)d_in[base + 10];
    const float* b2 = (const float*)d_in[base + 11];
    const float* regw = (const float*)d_in[base + 12];
    const float* regb = (const float*)d_in[base + 13];
    float* out = (float*)d_out;

    prep_minmax<<<129, 256>>>(depthv, pm, w0, g0, b0, m0, v0,
                              w1, g1, b1, m1, v1, w2, b2);
    flags_kernel<<<1, 256>>>(depthv);
    simfast_kernel<<<dim3(NPIX/128, 4), 128>>>(feat, depthv, out);
    simgen_kernel<<<80, 128>>>(feat, depthv, out);
    combine_kernel<<<NPIX/4/128, 128>>>(out);
    post_kernel<<<NPIX/32, dim3(32, 8)>>>(depthv, regw, regb, out);
}

// round 13
// speedup vs baseline: 1.2809x; 1.0747x over previous
#include <cuda_runtime.h>
#include <math.h>

#define HH 128
#define WW 160
#define CC 32
#define DD 32
#define BB 2
#define VV 5
#define HWSZ (HH*WW)       // 20480
#define NPIX (BB*HWSZ)     // 40960
#define NDEP (BB*DD*HWSZ)  // 1310720

// out layout (flattened tuple in reference-return order):
#define OFF_DEPTH 0
#define OFF_CONF  40960
#define OFF_PROB  81920
#define OFF_COST  1392640
#define OFF_VW    2703360

__device__ float g_rot[4][BB][9];
__device__ float g_trans[4][BB][3];
// piecewise-affine MLP table: g_abf[i*16 + j] = alpha_j, [i*16+8+j] = beta_j
__device__ float g_thr[16];
__device__ float g_abf[17*16];
__device__ float g_w2s[8];
__device__ float g_B2s;
__device__ float g_sim[BB*DD*HWSZ];
__device__ float g_simv[4*BB*DD*HWSZ];   // per-view sim volumes (fast path)
__device__ unsigned g_dminu = 0xFFFFFFFFu;  // ordered-encoded min (idempotent across replays)
__device__ unsigned g_dmaxu = 0u;
__device__ int g_uni = 1;                // depth spatially uniform? (only ever cleared)
__device__ int g_cnt = 0;                // intra-grid barrier counter (reset each replay)
__device__ int g_fast;
__device__ int g_jlo[4][BB];
__device__ int g_ktap[4][BB];
__device__ int   g_dj[4][BB][DD];        // per-(v,b,d) tap index (uniform-depth path)
__device__ float g_df[4][BB][DD];        // per-(v,b,d) lerp fraction

__device__ __forceinline__ unsigned ord_enc(float x) {
    unsigned u = __float_as_uint(x);
    return (u & 0x80000000u) ? ~u : (u | 0x80000000u);
}
__device__ __forceinline__ float ord_dec(unsigned u) {
    u = (u & 0x80000000u) ? (u & 0x7FFFFFFFu) : ~u;
    return __uint_as_float(u);
}

// folded pixelwise MLP via exact piecewise-affine table
__device__ __forceinline__ float mlp_o2(float sim,
    const float* __restrict__ s_thr, const float4* __restrict__ s_ab,
    const float* __restrict__ s_w2, float s_B2)
{
    int idx = 0;
    #pragma unroll
    for (int k = 0; k < 16; ++k) idx += (sim > s_thr[k]) ? 1 : 0;
    const float4* tab = s_ab + idx*4;
    float4 A0 = tab[0], A1 = tab[1], B0 = tab[2], B1 = tab[3];
    float o2 = s_B2;
    o2 = fmaf(s_w2[0], fmaxf(fmaf(A0.x, sim, B0.x), 0.f), o2);
    o2 = fmaf(s_w2[1], fmaxf(fmaf(A0.y, sim, B0.y), 0.f), o2);
    o2 = fmaf(s_w2[2], fmaxf(fmaf(A0.z, sim, B0.z), 0.f), o2);
    o2 = fmaf(s_w2[3], fmaxf(fmaf(A0.w, sim, B0.w), 0.f), o2);
    o2 = fmaf(s_w2[4], fmaxf(fmaf(A1.x, sim, B1.x), 0.f), o2);
    o2 = fmaf(s_w2[5], fmaxf(fmaf(A1.y, sim, B1.y), 0.f), o2);
    o2 = fmaf(s_w2[6], fmaxf(fmaf(A1.z, sim, B1.z), 0.f), o2);
    o2 = fmaf(s_w2[7], fmaxf(fmaf(A1.w, sim, B1.w), 0.f), o2);
    return o2;
}

// ---------------------------------------------------------------------------
// k1: prep + minmax + flags, one launch.
// Blocks 0..127: depth minmax & uniformity, then signal the counter.
// Block 128: matrices + MLP compile, spin on the counter (all 129 blocks are
// co-resident: 129 < 148 SMs -> deadlock-free), then the flags decision and
// the uniform-depth (jj, fx) tables.
// ---------------------------------------------------------------------------
__global__ void __launch_bounds__(256) prep_kernel(const float* __restrict__ depthv,
    const float* __restrict__ pm,
    const float* __restrict__ w0, const float* __restrict__ g0,
    const float* __restrict__ b0, const float* __restrict__ m0, const float* __restrict__ v0,
    const float* __restrict__ w1, const float* __restrict__ g1,
    const float* __restrict__ b1, const float* __restrict__ m1, const float* __restrict__ v1,
    const float* __restrict__ w2, const float* __restrict__ b2)
{
    if (blockIdx.x < 128) {
        __shared__ unsigned smin[256], smax[256];
        __shared__ int smism;
        if (threadIdx.x == 0) smism = 0;
        __syncthreads();
        unsigned mn = 0xFFFFFFFFu, mx = 0u;
        int mism = 0;
        for (int i = blockIdx.x*256 + threadIdx.x; i < NDEP; i += 128*256) {
            float dv = depthv[i];
            unsigned e = ord_enc(dv);
            mn = min(mn, e); mx = max(mx, e);
            int head = (i / HWSZ) * HWSZ;
            if (__float_as_uint(dv) != __float_as_uint(__ldg(depthv + head))) mism = 1;
        }
        smin[threadIdx.x] = mn; smax[threadIdx.x] = mx;
        if (mism) smism = 1;
        __syncthreads();
        for (int s = 128; s > 0; s >>= 1) {
            if (threadIdx.x < s) {
                smin[threadIdx.x] = min(smin[threadIdx.x], smin[threadIdx.x+s]);
                smax[threadIdx.x] = max(smax[threadIdx.x], smax[threadIdx.x+s]);
            }
            __syncthreads();
        }
        if (threadIdx.x == 0) {
            atomicMin(&g_dminu, smin[0]);
            atomicMax(&g_dmaxu, smax[0]);
            if (smism) g_uni = 0;         // only cleared -> idempotent
            __threadfence();
            atomicAdd(&g_cnt, 1);
        }
        return;
    }

    // ---- block 128 ----
    int t = threadIdx.x;
    if (t < 8) {
        int b = t >> 2;
        int v = (t & 3) + 1;
        double Ar[9], tr[3], As[9], ts[3];
        for (int which = 0; which < 2; ++which) {
            int view = which ? v : 0;
            const float* E = pm + ((b*VV + view)*2 + 0)*16;
            const float* K = pm + ((b*VV + view)*2 + 1)*16;
            double* A = which ? As : Ar;
            double* tv = which ? ts : tr;
            for (int r = 0; r < 3; ++r) {
                for (int c = 0; c < 3; ++c) {
                    double s = 0.0;
                    for (int k = 0; k < 3; ++k) s += (double)K[r*4+k]*(double)E[k*4+c];
                    A[r*3+c] = s;
                }
                double s = 0.0;
                for (int k = 0; k < 3; ++k) s += (double)K[r*4+k]*(double)E[k*4+3];
                tv[r] = s;
            }
        }
        double c00 = Ar[4]*Ar[8]-Ar[5]*Ar[7];
        double c01 = Ar[5]*Ar[6]-Ar[3]*Ar[8];
        double c02 = Ar[3]*Ar[7]-Ar[4]*Ar[6];
        double det = Ar[0]*c00 + Ar[1]*c01 + Ar[2]*c02;
        double id  = 1.0/det;
        double Ai[9];
        Ai[0] = c00*id;
        Ai[1] = (Ar[2]*Ar[7]-Ar[1]*Ar[8])*id;
        Ai[2] = (Ar[1]*Ar[5]-Ar[2]*Ar[4])*id;
        Ai[3] = c01*id;
        Ai[4] = (Ar[0]*Ar[8]-Ar[2]*Ar[6])*id;
        Ai[5] = (Ar[2]*Ar[3]-Ar[0]*Ar[5])*id;
        Ai[6] = c02*id;
        Ai[7] = (Ar[1]*Ar[6]-Ar[0]*Ar[7])*id;
        Ai[8] = (Ar[0]*Ar[4]-Ar[1]*Ar[3])*id;
        double rot[9];
        for (int r = 0; r < 3; ++r)
            for (int c = 0; c < 3; ++c) {
                double s = 0.0;
                for (int k = 0; k < 3; ++k) s += As[r*3+k]*Ai[k*3+c];
                rot[r*3+c] = s;
                g_rot[v-1][b][r*3+c] = (float)s;
            }
        for (int r = 0; r < 3; ++r) {
            double s = ts[r];
            for (int k = 0; k < 3; ++k) s -= rot[r*3+k]*tr[k];
            g_trans[v-1][b][r] = (float)s;
        }
    } else if (t >= 16 && t < 16 + 17*8) {
        // one thread per (interval i, hidden unit j): exact piecewise-affine MLP
        int i = (t - 16) >> 3;
        int j = (t - 16) & 7;
        double a[16], c[16];
        for (int o = 0; o < 16; ++o) {
            double ai = (double)g0[o] / sqrt((double)v0[o] + 1e-5);
            a[o] = (double)w0[o] * ai;
            c[o] = (double)b0[o] - (double)m0[o] * ai;
        }
        double thr[16];
        for (int o = 0; o < 16; ++o) {
            if (a[o] != 0.0) thr[o] = -c[o] / a[o];
            else             thr[o] = (c[o] > 0.0) ? -1e30 : 1e30;
        }
        for (int ii = 1; ii < 16; ++ii) {
            double key = thr[ii]; int jj = ii - 1;
            while (jj >= 0 && thr[jj] > key) { thr[jj+1] = thr[jj]; --jj; }
            thr[jj+1] = key;
        }
        if (i == 0 && j < 8) {
            if (j == 0) {
                for (int k = 0; k < 16; ++k) g_thr[k] = (float)thr[k];
                g_B2s = b2[0];
            }
            g_w2s[j] = w2[j];
        }
        double aij = (double)g1[j] / sqrt((double)v1[j] + 1e-5);
        double c1j = (double)b1[j] - (double)m1[j] * aij;
        double lo = (i == 0)  ? thr[0]  - 1.0 : thr[i-1];
        double hi = (i == 16) ? thr[15] + 1.0 : thr[i];
        double rep = 0.5*(lo + hi);
        double aj = 0.0, bj = c1j;
        for (int o = 0; o < 16; ++o) {
            if (a[o]*rep + c[o] > 0.0) {
                double w1f = (double)w1[j*16 + o] * aij;
                aj += w1f*a[o]; bj += w1f*c[o];
            }
        }
        g_abf[i*16 + j]     = (float)aj;
        g_abf[i*16 + 8 + j] = (float)bj;
    }

    // ---- flags: wait for all minmax blocks, then decide ----
    __syncthreads();                      // matrices visible block-wide
    __shared__ int s_fast;
    if (t == 0) {
        while (atomicAdd(&g_cnt, 0) < 128) { }
        atomicSub(&g_cnt, 128);           // reset for next graph replay
        float dmin = ord_dec(atomicAdd(&g_dminu, 0u));
        float dmax = ord_dec(atomicAdd(&g_dmaxu, 0u));
        int fast = (dmin > 1e-3f) ? 1 : 0;
        for (int v = 0; v < 4 && fast; ++v)
            for (int b = 0; b < BB && fast; ++b) {
                const float* R = g_rot[v][b];
                const float* T = g_trans[v][b];
                float dev = 0.f;
                for (int i = 0; i < 9; ++i) {
                    float ident = (i == 0 || i == 4 || i == 8) ? 1.f : 0.f;
                    dev = fmaxf(dev, fabsf(R[i] - ident));
                }
                if (dev > 1e-5f || fabsf(T[1]) > 1e-3f || fabsf(T[2]) > 1e-3f) { fast = 0; break; }
                double tx = (double)T[0];
                double d0 = tx / (double)dmax, d1 = tx / (double)dmin;
                double dlo = fmin(d0, d1), dhi = fmax(d0, d1);
                int jl = (int)floor(dlo) - 1;
                int jh = (int)floor(dhi) + 1;
                int kt = jh - jl + 1;
                if (kt > 16) { fast = 0; break; }
                g_jlo[v][b]  = jl;
                g_ktap[v][b] = kt;
            }
        g_fast = fast;
        s_fast = fast;
    }
    __syncthreads();
    if (s_fast && g_uni) {
        int v = t >> 6;                   // 256 = 4*2*32 exactly
        int b = (t >> 5) & 1;
        int d = t & 31;
        float dep = __ldg(depthv + (size_t)(b*DD + d)*HWSZ);   // slice head
        float tx  = g_trans[v][b][0];
        float delta = __fdividef(tx, dep);
        float jf = floorf(delta);
        float fx = delta - jf;
        int jj = (int)jf - g_jlo[v][b];
        jj = min(max(jj, 0), g_ktap[v][b] - 2);
        g_dj[v][b][d] = jj;
        g_df[v][b][d] = fx;
    }
}

// ---------------------------------------------------------------------------
// templated Q accumulation: Q(p,k) = sum_c ref_c(p) * src_c(p+k)
// ---------------------------------------------------------------------------
template<int KT>
__device__ __forceinline__ void qaccum(const float* __restrict__ refb,
                                       const float* __restrict__ srcb,
                                       int hw, int base, int klo, int khi,
                                       float* __restrict__ Qs, int tid)
{
    float Qr[KT];
    #pragma unroll
    for (int k = 0; k < KT; ++k) Qr[k] = 0.f;
    #pragma unroll 4
    for (int c = 0; c < CC; ++c) {
        float rc = __ldg(refb + (size_t)c*HWSZ + hw);
        const float* sc = srcb + (size_t)c*HWSZ + base;
        #pragma unroll
        for (int k = 0; k < KT; ++k) {
            float sv = (k >= klo && k <= khi) ? __ldg(sc + k) : 0.f;
            Qr[k] = fmaf(rc, sv, Qr[k]);
        }
    }
    #pragma unroll
    for (int k = 0; k < KT; ++k) Qs[k*128 + tid] = Qr[k];
}

// ---------------------------------------------------------------------------
// k2: merged sim kernel. Fast path = shift-factorized similarity (view-
// parallel, blockIdx.y = view). Fallback = full bilinear gather (vi==0
// blocks only; register spills confined to this never-hot branch by the
// launch_bounds cap, protecting fast-path occupancy).
// ---------------------------------------------------------------------------
__global__ void __launch_bounds__(128, 8) sim_kernel(const float* __restrict__ feat,
                                                     const float* __restrict__ depthv,
                                                     float* __restrict__ out)
{
    __shared__ float  sbuf[DD*128];    // 16KB: fast uses first 8KB as Qs; gen uses all as ssim
    __shared__ float  s_thr[16];
    __shared__ float4 s_ab[17*4];
    __shared__ float  s_w2[8];
    __shared__ float  s_B2;
    __shared__ int    s_dj[DD];
    __shared__ float  s_df[DD];

    int tid = threadIdx.x;
    int vi  = blockIdx.y;
    int g   = blockIdx.x * 128 + tid;
    int b   = g / HWSZ;               // same for whole block (HWSZ % 128 == 0)
    int hw  = g - b*HWSZ;
    int fast = g_fast;
    int uni  = g_uni;

    if (tid < 16) s_thr[tid] = g_thr[tid];
    if (tid < 68) s_ab[tid] = ((const float4*)g_abf)[tid];
    if (tid < 8)  s_w2[tid] = g_w2s[tid];
    if (tid == 8) s_B2 = g_B2s;
    if (fast && uni && tid < DD) { s_dj[tid] = g_dj[vi][b][tid]; s_df[tid] = g_df[vi][b][tid]; }
    __syncthreads();

    if (fast) {
        float* Qs = sbuf;
        int w = hw % WW;
        int jlo  = g_jlo[vi][b];
        int ktap = g_ktap[vi][b];
        float tx = g_trans[vi][b][0];

        const float* refb = feat + (size_t)(b*CC)*HWSZ;
        const float* srcb = feat + (size_t)(((vi+1)*BB + b)*CC)*HWSZ;

        int klo = -(w + jlo);
        int khi = (WW-1) - (w + jlo);
        int base = hw + jlo;

        if (ktap <= 8)       qaccum<8>(refb, srcb, hw, base, klo, khi, Qs, tid);
        else if (ktap <= 12) qaccum<12>(refb, srcb, hw, base, klo, khi, Qs, tid);
        else                 qaccum<16>(refb, srcb, hw, base, klo, khi, Qs, tid);

        float* svout = g_simv + ((size_t)(vi*BB + b)*DD)*HWSZ + hw;
        float vmaxo = -1e30f;

        if (uni) {
            #pragma unroll 8
            for (int d = 0; d < DD; ++d) {
                int jj = s_dj[d];
                float fx = s_df[d];
                float q0 = Qs[jj*128 + tid];
                float q1 = Qs[(jj+1)*128 + tid];
                float sim = fmaf(fx, q1 - q0, q0) * (1.f/32.f);
                svout[(size_t)d*HWSZ] = sim;
                vmaxo = fmaxf(vmaxo, mlp_o2(sim, s_thr, s_ab, s_w2, s_B2));
            }
        } else {
            const float* depcol = depthv + (size_t)(b*DD)*HWSZ + hw;
            int jcap = ktap - 2;
            for (int d = 0; d < DD; ++d) {
                float dep = __ldg(depcol + (size_t)d*HWSZ);
                float delta = __fdividef(tx, dep);
                float jf = floorf(delta);
                float fx = delta - jf;
                int jj = (int)jf - jlo;
                jj = min(max(jj, 0), jcap);
                float q0 = Qs[jj*128 + tid];
                float q1 = Qs[(jj+1)*128 + tid];
                float sim = fmaf(fx, q1 - q0, q0) * (1.f/32.f);
                svout[(size_t)d*HWSZ] = sim;
                vmaxo = fmaxf(vmaxo, mlp_o2(sim, s_thr, s_ab, s_w2, s_B2));
            }
        }

        out[OFF_VW + (b*4 + vi)*HWSZ + hw] = 1.f / (1.f + __expf(-vmaxo));
        return;
    }

    // ---- general fallback: vi==0 blocks cover all NPIX pixels ----
    if (vi != 0) return;
    {
        float* ssim = sbuf;
        int h = hw / WW, w = hw - h*WW;
        float xf = (float)w, yf = (float)h;

        const float* ref = feat + (size_t)(b*CC)*HWSZ + hw;
        float refv[CC];
        #pragma unroll
        for (int c = 0; c < CC; ++c) refv[c] = __ldg(ref + (size_t)c*HWSZ);

        float acc[DD];
        #pragma unroll
        for (int d = 0; d < DD; ++d) acc[d] = 0.f;
        float wsum = 1e-5f;
        const float* depcol = depthv + (size_t)(b*DD)*HWSZ + hw;

        for (int v = 1; v < VV; ++v) {
            const float* R = g_rot[v-1][b];
            const float* T = g_trans[v-1][b];
            float rx = R[0]*xf + R[1]*yf + R[2];
            float ry = R[3]*xf + R[4]*yf + R[5];
            float rz = R[6]*xf + R[7]*yf + R[8];
            float tx = T[0], ty = T[1], tz = T[2];
            const float* src = feat + (size_t)((v*BB + b)*CC)*HWSZ;
            float vmaxo = -1e30f;

            for (int d = 0; d < DD; ++d) {
                float dep = __ldg(depcol + (size_t)d*HWSZ);
                float px = fmaf(rx, dep, tx);
                float py = fmaf(ry, dep, ty);
                float pz = fmaf(rz, dep, tz);
                float iz = 1.0f / pz;
                float xs = px * iz, ys = py * iz;
                float x0f = floorf(xs), y0f = floorf(ys);
                float wx = xs - x0f, wy = ys - y0f;
                int ix = (int)x0f, iy = (int)y0f;
                float w00 = (1.f-wx)*(1.f-wy), w01 = wx*(1.f-wy);
                float w10 = (1.f-wx)*wy,       w11 = wx*wy;
                bool vx0 = (ix   >= 0) && (ix   < WW);
                bool vx1 = (ix+1 >= 0) && (ix+1 < WW);
                bool vy0 = (iy   >= 0) && (iy   < HH);
                bool vy1 = (iy+1 >= 0) && (iy+1 < HH);
                if (!(vx0 && vy0)) w00 = 0.f;
                if (!(vx1 && vy0)) w01 = 0.f;
                if (!(vx0 && vy1)) w10 = 0.f;
                if (!(vx1 && vy1)) w11 = 0.f;
                int x0c = min(max(ix,   0), WW-1), x1c = min(max(ix+1, 0), WW-1);
                int y0c = min(max(iy,   0), HH-1), y1c = min(max(iy+1, 0), HH-1);
                int o00 = y0c*WW + x0c, o01 = y0c*WW + x1c;
                int o10 = y1c*WW + x0c, o11 = y1c*WW + x1c;

                float s = 0.f;
                #pragma unroll
                for (int c = 0; c < CC; ++c) {
                    const float* p = src + (size_t)c*HWSZ;
                    float tap = fmaf(w00, __ldg(p+o00),
                                fmaf(w01, __ldg(p+o01),
                                fmaf(w10, __ldg(p+o10), w11 * __ldg(p+o11))));
                    s = fmaf(tap, refv[c], s);
                }
                float sim = s * (1.f/32.f);
                ssim[d*128 + tid] = sim;
                vmaxo = fmaxf(vmaxo, mlp_o2(sim, s_thr, s_ab, s_w2, s_B2));
            }

            float vmax = 1.f / (1.f + __expf(-vmaxo));
            out[OFF_VW + (b*4 + (v-1))*HWSZ + hw] = vmax;
            wsum += vmax;
            #pragma unroll
            for (int d = 0; d < DD; ++d)
                acc[d] = fmaf(ssim[d*128 + tid], vmax, acc[d]);
        }

        float invw = 1.f / wsum;
        float* so = g_sim + (size_t)(b*DD)*HWSZ + hw;
        #pragma unroll
        for (int d = 0; d < DD; ++d) so[(size_t)d*HWSZ] = acc[d] * invw;
    }
}

// ---------------------------------------------------------------------------
// k3 (fast path only): combine views, float4 over pixels.
// ---------------------------------------------------------------------------
__global__ void __launch_bounds__(128) combine_kernel(float* __restrict__ out)
{
    if (!g_fast) return;
    int t  = blockIdx.x * 128 + threadIdx.x;
    int g4 = t * 4;
    int b  = g4 / HWSZ;
    int hw = g4 - b*HWSZ;

    float4 vw0 = *(const float4*)(out + OFF_VW + (size_t)(b*4 + 0)*HWSZ + hw);
    float4 vw1 = *(const float4*)(out + OFF_VW + (size_t)(b*4 + 1)*HWSZ + hw);
    float4 vw2 = *(const float4*)(out + OFF_VW + (size_t)(b*4 + 2)*HWSZ + hw);
    float4 vw3 = *(const float4*)(out + OFF_VW + (size_t)(b*4 + 3)*HWSZ + hw);
    float4 inv;
    inv.x = 1.f / (1e-5f + vw0.x + vw1.x + vw2.x + vw3.x);
    inv.y = 1.f / (1e-5f + vw0.y + vw1.y + vw2.y + vw3.y);
    inv.z = 1.f / (1e-5f + vw0.z + vw1.z + vw2.z + vw3.z);
    inv.w = 1.f / (1e-5f + vw0.w + vw1.w + vw2.w + vw3.w);

    const float* s0 = g_simv + ((size_t)(0*BB + b)*DD)*HWSZ + hw;
    const float* s1 = g_simv + ((size_t)(1*BB + b)*DD)*HWSZ + hw;
    const float* s2 = g_simv + ((size_t)(2*BB + b)*DD)*HWSZ + hw;
    const float* s3 = g_simv + ((size_t)(3*BB + b)*DD)*HWSZ + hw;
    float* so = g_sim + (size_t)(b*DD)*HWSZ + hw;

    #pragma unroll 4
    for (int d = 0; d < DD; ++d) {
        float4 a = *(const float4*)(s0 + (size_t)d*HWSZ);
        float4 bq= *(const float4*)(s1 + (size_t)d*HWSZ);
        float4 c = *(const float4*)(s2 + (size_t)d*HWSZ);
        float4 e = *(const float4*)(s3 + (size_t)d*HWSZ);
        float4 r;
        r.x = (a.x*vw0.x + bq.x*vw1.x + c.x*vw2.x + e.x*vw3.x) * inv.x;
        r.y = (a.y*vw0.y + bq.y*vw1.y + c.y*vw2.y + e.y*vw3.y) * inv.y;
        r.z = (a.z*vw0.z + bq.z*vw1.z + c.z*vw2.z + e.z*vw3.z) * inv.z;
        r.w = (a.w*vw0.w + bq.w*vw1.w + c.w*vw2.w + e.w*vw3.w) * inv.w;
        *(float4*)(so + (size_t)d*HWSZ) = r;
    }
}

// ---------------------------------------------------------------------------
// k4: 3x3x3 conv + softmax + argmax, D split across 8 threads per pixel.
// Correlation orientation: cost[d] += rw[kd]*sim[d+kd-1]  =>  kd = dd - d + 1.
// ---------------------------------------------------------------------------
__global__ void __launch_bounds__(256) post_kernel(const float* __restrict__ depthv,
                                                   const float* __restrict__ regw,
                                                   const float* __restrict__ regb,
                                                   float* __restrict__ out)
{
    __shared__ float rw[27];
    __shared__ float rb;
    __shared__ float red[8][33];
    __shared__ int   redi[8][33];
    int tx = threadIdx.x;   // pixel lane 0..31
    int ty = threadIdx.y;   // d-group 0..7
    int lin = ty*32 + tx;
    if (lin < 27) rw[lin] = regw[lin];
    if (lin == 27) rb = regb[0];
    __syncthreads();

    int g  = blockIdx.x * 32 + tx;
    int b  = g / HWSZ;
    int hw = g - b*HWSZ;
    int h  = hw / WW, w = hw - h*WW;
    int dbase = ty * 4;
    const float* simb = g_sim + (size_t)(b*DD)*HWSZ;

    float cost[4] = {rb, rb, rb, rb};

    #pragma unroll
    for (int o = 0; o < 6; ++o) {
        int dd = dbase - 1 + o;
        if (dd < 0 || dd >= DD) continue;
        float s[9];
        #pragma unroll
        for (int kh = 0; kh < 3; ++kh)
            #pragma unroll
            for (int kw = 0; kw < 3; ++kw) {
                int h2 = h + kh - 1, w2 = w + kw - 1;
                s[kh*3+kw] = (h2 >= 0 && h2 < HH && w2 >= 0 && w2 < WW)
                             ? __ldg(simb + (size_t)dd*HWSZ + h2*WW + w2) : 0.f;
            }
        #pragma unroll
        for (int q = 0; q < 4; ++q) {
            int kd = dd - (dbase + q) + 1;   // correlation: dd = d + kd - 1
            if (kd >= 0 && kd <= 2) {
                float p = 0.f;
                #pragma unroll
                for (int i = 0; i < 9; ++i) p = fmaf(rw[kd*9+i], s[i], p);
                cost[q] += p;
            }
        }
    }

    float lm = fmaxf(fmaxf(cost[0], cost[1]), fmaxf(cost[2], cost[3]));
    red[ty][tx] = lm;
    __syncthreads();
    float m;
    {
        float t0 = fmaxf(red[0][tx], red[1][tx]);
        float t1 = fmaxf(red[2][tx], red[3][tx]);
        float t2 = fmaxf(red[4][tx], red[5][tx]);
        float t3 = fmaxf(red[6][tx], red[7][tx]);
        m = fmaxf(fmaxf(t0, t1), fmaxf(t2, t3));
    }
    __syncthreads();

    float e[4];
    float ls = 0.f;
    #pragma unroll
    for (int q = 0; q < 4; ++q) { e[q] = __expf(cost[q] - m); ls += e[q]; }
    red[ty][tx] = ls;
    __syncthreads();
    float sum = red[0][tx] + red[1][tx] + red[2][tx] + red[3][tx]
              + red[4][tx] + red[5][tx] + red[6][tx] + red[7][tx];
    float isum = 1.f / sum;
    __syncthreads();

    int li = 0; float lb = cost[0];
    #pragma unroll
    for (int q = 1; q < 4; ++q) if (cost[q] > lb) { lb = cost[q]; li = q; }
    red[ty][tx]  = lb;
    redi[ty][tx] = dbase + li;
    __syncthreads();

    if (ty == 0) {
        float best = red[0][tx]; int bi = redi[0][tx];
        #pragma unroll
        for (int yy = 1; yy < 8; ++yy)
            if (red[yy][tx] > best) { best = red[yy][tx]; bi = redi[yy][tx]; }
        out[OFF_DEPTH + g] = __ldg(depthv + (size_t)(b*DD + bi)*HWSZ + hw);
        out[OFF_CONF  + g] = isum;
    }

    #pragma unroll
    for (int q = 0; q < 4; ++q) {
        int d = dbase + q;
        out[OFF_PROB + (size_t)(b*DD + d)*HWSZ + hw] = e[q] * isum;
        out[OFF_COST + (size_t)(b*DD + d)*HWSZ + hw] = cost[q];
    }
}

extern "C" void kernel_launch(void* const* d_in, const int* in_sizes, int n_in,
                              void* d_out, int out_size)
{
    const float* feat   = (const float*)d_in[0];
    const float* pm     = (const float*)d_in[1];
    const float* depthv = (const float*)d_in[2];
    int base = (n_in >= 18) ? 4 : 3;
    const float* w0 = (const float*)d_in[base + 0];
    const float* g0 = (const float*)d_in[base + 1];
    const float* b0 = (const float*)d_in[base + 2];
    const float* m0 = (const float*)d_in[base + 3];
    const float* v0 = (const float*)d_in[base + 4];
    const float* w1 = (const float*)d_in[base + 5];
    const float* g1 = (const float*)d_in[base + 6];
    const float* b1 = (const float*)d_in[base + 7];
    const float* m1 = (const float*)d_in[base + 8];
    const float* v1 = (const float*)d_in[base + 9];
    const float* w2 = (const float*)d_in[base + 10];
    const float* b2 = (const float*)d_in[base + 11];
    const float* regw = (const float*)d_in[base + 12];
    const float* regb = (const float*)d_in[base + 13];
    float* out = (float*)d_out;

    prep_kernel<<<129, 256>>>(depthv, pm, w0, g0, b0, m0, v0,
                              w1, g1, b1, m1, v1, w2, b2);
    sim_kernel<<<dim3(NPIX/128, 4), 128>>>(feat, depthv, out);
    combine_kernel<<<NPIX/4/128, 128>>>(out);
    post_kernel<<<NPIX/32, dim3(32, 8)>>>(depthv, regw, regb, out);
}

// round 14
// speedup vs baseline: 1.3963x; 1.0902x over previous
#include <cuda_runtime.h>
#include <math.h>

#define HH 128
#define WW 160
#define CC 32
#define DD 32
#define BB 2
#define VV 5
#define HWSZ (HH*WW)       // 20480
#define NPIX (BB*HWSZ)     // 40960
#define NDEP (BB*DD*HWSZ)  // 1310720

// out layout (flattened tuple in reference-return order):
#define OFF_DEPTH 0
#define OFF_CONF  40960
#define OFF_PROB  81920
#define OFF_COST  1392640
#define OFF_VW    2703360

__device__ float g_rot[4][BB][9];
__device__ float g_trans[4][BB][3];
// piecewise-affine MLP table: g_abf[i*16 + j] = alpha_j, [i*16+8+j] = beta_j
__device__ float g_thr[16];
__device__ float g_abf[17*16];
__device__ float g_w2s[8];
__device__ float g_B2s;
__device__ float g_sim[BB*DD*HWSZ];
__device__ float g_simv[4*BB*DD*HWSZ];   // per-view sim volumes (fast path)
__device__ unsigned g_dminu = 0xFFFFFFFFu;  // ordered-encoded min (idempotent across replays)
__device__ unsigned g_dmaxu = 0u;
__device__ int g_uni = 1;                // depth spatially uniform? (only ever cleared)
__device__ int g_cnt = 0;                // intra-grid barrier counter (reset each replay)
__device__ int g_fast;
__device__ int g_jlo[4][BB];
__device__ int g_ktap[4][BB];
__device__ int   g_dj[4][BB][DD];        // per-(v,b,d) tap index (uniform-depth path)
__device__ float g_df[4][BB][DD];        // per-(v,b,d) lerp fraction

__device__ __forceinline__ unsigned ord_enc(float x) {
    unsigned u = __float_as_uint(x);
    return (u & 0x80000000u) ? ~u : (u | 0x80000000u);
}
__device__ __forceinline__ float ord_dec(unsigned u) {
    u = (u & 0x80000000u) ? (u & 0x7FFFFFFFu) : ~u;
    return __uint_as_float(u);
}

// folded pixelwise MLP via exact piecewise-affine table
__device__ __forceinline__ float mlp_o2(float sim,
    const float* __restrict__ s_thr, const float4* __restrict__ s_ab,
    const float* __restrict__ s_w2, float s_B2)
{
    int idx = 0;
    #pragma unroll
    for (int k = 0; k < 16; ++k) idx += (sim > s_thr[k]) ? 1 : 0;
    const float4* tab = s_ab + idx*4;
    float4 A0 = tab[0], A1 = tab[1], B0 = tab[2], B1 = tab[3];
    float o2 = s_B2;
    o2 = fmaf(s_w2[0], fmaxf(fmaf(A0.x, sim, B0.x), 0.f), o2);
    o2 = fmaf(s_w2[1], fmaxf(fmaf(A0.y, sim, B0.y), 0.f), o2);
    o2 = fmaf(s_w2[2], fmaxf(fmaf(A0.z, sim, B0.z), 0.f), o2);
    o2 = fmaf(s_w2[3], fmaxf(fmaf(A0.w, sim, B0.w), 0.f), o2);
    o2 = fmaf(s_w2[4], fmaxf(fmaf(A1.x, sim, B1.x), 0.f), o2);
    o2 = fmaf(s_w2[5], fmaxf(fmaf(A1.y, sim, B1.y), 0.f), o2);
    o2 = fmaf(s_w2[6], fmaxf(fmaf(A1.z, sim, B1.z), 0.f), o2);
    o2 = fmaf(s_w2[7], fmaxf(fmaf(A1.w, sim, B1.w), 0.f), o2);
    return o2;
}

// ---------------------------------------------------------------------------
// k1: prep + minmax + flags, one launch (intra-grid spin barrier; 129 blocks
// co-resident on 148 SMs -> deadlock-free).
// ---------------------------------------------------------------------------
__global__ void __launch_bounds__(256) prep_kernel(const float* __restrict__ depthv,
    const float* __restrict__ pm,
    const float* __restrict__ w0, const float* __restrict__ g0,
    const float* __restrict__ b0, const float* __restrict__ m0, const float* __restrict__ v0,
    const float* __restrict__ w1, const float* __restrict__ g1,
    const float* __restrict__ b1, const float* __restrict__ m1, const float* __restrict__ v1,
    const float* __restrict__ w2, const float* __restrict__ b2)
{
    if (blockIdx.x < 128) {
        __shared__ unsigned smin[256], smax[256];
        __shared__ int smism;
        if (threadIdx.x == 0) smism = 0;
        __syncthreads();
        unsigned mn = 0xFFFFFFFFu, mx = 0u;
        int mism = 0;
        for (int i = blockIdx.x*256 + threadIdx.x; i < NDEP; i += 128*256) {
            float dv = depthv[i];
            unsigned e = ord_enc(dv);
            mn = min(mn, e); mx = max(mx, e);
            int head = (i / HWSZ) * HWSZ;
            if (__float_as_uint(dv) != __float_as_uint(__ldg(depthv + head))) mism = 1;
        }
        smin[threadIdx.x] = mn; smax[threadIdx.x] = mx;
        if (mism) smism = 1;
        __syncthreads();
        for (int s = 128; s > 0; s >>= 1) {
            if (threadIdx.x < s) {
                smin[threadIdx.x] = min(smin[threadIdx.x], smin[threadIdx.x+s]);
                smax[threadIdx.x] = max(smax[threadIdx.x], smax[threadIdx.x+s]);
            }
            __syncthreads();
        }
        if (threadIdx.x == 0) {
            atomicMin(&g_dminu, smin[0]);
            atomicMax(&g_dmaxu, smax[0]);
            if (smism) g_uni = 0;         // only cleared -> idempotent
            __threadfence();
            atomicAdd(&g_cnt, 1);
        }
        return;
    }

    // ---- block 128 ----
    int t = threadIdx.x;
    if (t < 8) {
        int b = t >> 2;
        int v = (t & 3) + 1;
        double Ar[9], tr[3], As[9], ts[3];
        for (int which = 0; which < 2; ++which) {
            int view = which ? v : 0;
            const float* E = pm + ((b*VV + view)*2 + 0)*16;
            const float* K = pm + ((b*VV + view)*2 + 1)*16;
            double* A = which ? As : Ar;
            double* tv = which ? ts : tr;
            for (int r = 0; r < 3; ++r) {
                for (int c = 0; c < 3; ++c) {
                    double s = 0.0;
                    for (int k = 0; k < 3; ++k) s += (double)K[r*4+k]*(double)E[k*4+c];
                    A[r*3+c] = s;
                }
                double s = 0.0;
                for (int k = 0; k < 3; ++k) s += (double)K[r*4+k]*(double)E[k*4+3];
                tv[r] = s;
            }
        }
        double c00 = Ar[4]*Ar[8]-Ar[5]*Ar[7];
        double c01 = Ar[5]*Ar[6]-Ar[3]*Ar[8];
        double c02 = Ar[3]*Ar[7]-Ar[4]*Ar[6];
        double det = Ar[0]*c00 + Ar[1]*c01 + Ar[2]*c02;
        double id  = 1.0/det;
        double Ai[9];
        Ai[0] = c00*id;
        Ai[1] = (Ar[2]*Ar[7]-Ar[1]*Ar[8])*id;
        Ai[2] = (Ar[1]*Ar[5]-Ar[2]*Ar[4])*id;
        Ai[3] = c01*id;
        Ai[4] = (Ar[0]*Ar[8]-Ar[2]*Ar[6])*id;
        Ai[5] = (Ar[2]*Ar[3]-Ar[0]*Ar[5])*id;
        Ai[6] = c02*id;
        Ai[7] = (Ar[1]*Ar[6]-Ar[0]*Ar[7])*id;
        Ai[8] = (Ar[0]*Ar[4]-Ar[1]*Ar[3])*id;
        double rot[9];
        for (int r = 0; r < 3; ++r)
            for (int c = 0; c < 3; ++c) {
                double s = 0.0;
                for (int k = 0; k < 3; ++k) s += As[r*3+k]*Ai[k*3+c];
                rot[r*3+c] = s;
                g_rot[v-1][b][r*3+c] = (float)s;
            }
        for (int r = 0; r < 3; ++r) {
            double s = ts[r];
            for (int k = 0; k < 3; ++k) s -= rot[r*3+k]*tr[k];
            g_trans[v-1][b][r] = (float)s;
        }
    } else if (t >= 16 && t < 16 + 17*8) {
        // one thread per (interval i, hidden unit j): exact piecewise-affine MLP
        int i = (t - 16) >> 3;
        int j = (t - 16) & 7;
        double a[16], c[16];
        for (int o = 0; o < 16; ++o) {
            double ai = (double)g0[o] / sqrt((double)v0[o] + 1e-5);
            a[o] = (double)w0[o] * ai;
            c[o] = (double)b0[o] - (double)m0[o] * ai;
        }
        double thr[16];
        for (int o = 0; o < 16; ++o) {
            if (a[o] != 0.0) thr[o] = -c[o] / a[o];
            else             thr[o] = (c[o] > 0.0) ? -1e30 : 1e30;
        }
        for (int ii = 1; ii < 16; ++ii) {
            double key = thr[ii]; int jj = ii - 1;
            while (jj >= 0 && thr[jj] > key) { thr[jj+1] = thr[jj]; --jj; }
            thr[jj+1] = key;
        }
        if (i == 0 && j < 8) {
            if (j == 0) {
                for (int k = 0; k < 16; ++k) g_thr[k] = (float)thr[k];
                g_B2s = b2[0];
            }
            g_w2s[j] = w2[j];
        }
        double aij = (double)g1[j] / sqrt((double)v1[j] + 1e-5);
        double c1j = (double)b1[j] - (double)m1[j] * aij;
        double lo = (i == 0)  ? thr[0]  - 1.0 : thr[i-1];
        double hi = (i == 16) ? thr[15] + 1.0 : thr[i];
        double rep = 0.5*(lo + hi);
        double aj = 0.0, bj = c1j;
        for (int o = 0; o < 16; ++o) {
            if (a[o]*rep + c[o] > 0.0) {
                double w1f = (double)w1[j*16 + o] * aij;
                aj += w1f*a[o]; bj += w1f*c[o];
            }
        }
        g_abf[i*16 + j]     = (float)aj;
        g_abf[i*16 + 8 + j] = (float)bj;
    }

    // ---- flags: wait for all minmax blocks, then decide ----
    __syncthreads();
    __shared__ int s_fast;
    if (t == 0) {
        while (atomicAdd(&g_cnt, 0) < 128) { }
        atomicSub(&g_cnt, 128);           // reset for next graph replay
        float dmin = ord_dec(atomicAdd(&g_dminu, 0u));
        float dmax = ord_dec(atomicAdd(&g_dmaxu, 0u));
        int fast = (dmin > 1e-3f) ? 1 : 0;
        for (int v = 0; v < 4 && fast; ++v)
            for (int b = 0; b < BB && fast; ++b) {
                const float* R = g_rot[v][b];
                const float* T = g_trans[v][b];
                float dev = 0.f;
                for (int i = 0; i < 9; ++i) {
                    float ident = (i == 0 || i == 4 || i == 8) ? 1.f : 0.f;
                    dev = fmaxf(dev, fabsf(R[i] - ident));
                }
                if (dev > 1e-5f || fabsf(T[1]) > 1e-3f || fabsf(T[2]) > 1e-3f) { fast = 0; break; }
                double tx = (double)T[0];
                double d0 = tx / (double)dmax, d1 = tx / (double)dmin;
                double dlo = fmin(d0, d1), dhi = fmax(d0, d1);
                int jl = (int)floor(dlo) - 1;
                int jh = (int)floor(dhi) + 1;
                int kt = jh - jl + 1;
                if (kt > 16) { fast = 0; break; }
                g_jlo[v][b]  = jl;
                g_ktap[v][b] = kt;
            }
        g_fast = fast;
        s_fast = fast;
    }
    __syncthreads();
    if (s_fast && g_uni) {
        int v = t >> 6;                   // 256 = 4*2*32 exactly
        int b = (t >> 5) & 1;
        int d = t & 31;
        float dep = __ldg(depthv + (size_t)(b*DD + d)*HWSZ);   // slice head
        float tx  = g_trans[v][b][0];
        float delta = __fdividef(tx, dep);
        float jf = floorf(delta);
        float fx = delta - jf;
        int jj = (int)jf - g_jlo[v][b];
        jj = min(max(jj, 0), g_ktap[v][b] - 2);
        g_dj[v][b][d] = jj;
        g_df[v][b][d] = fx;
    }
}

// ---------------------------------------------------------------------------
// templated Q accumulation: Q(p,k) = sum_c ref_c(p) * src_c(p+k)
// ---------------------------------------------------------------------------
template<int KT>
__device__ __forceinline__ void qaccum(const float* __restrict__ refb,
                                       const float* __restrict__ srcb,
                                       int hw, int base, int klo, int khi,
                                       float* __restrict__ Qs, int tid)
{
    float Qr[KT];
    #pragma unroll
    for (int k = 0; k < KT; ++k) Qr[k] = 0.f;
    #pragma unroll 4
    for (int c = 0; c < CC; ++c) {
        float rc = __ldg(refb + (size_t)c*HWSZ + hw);
        const float* sc = srcb + (size_t)c*HWSZ + base;
        #pragma unroll
        for (int k = 0; k < KT; ++k) {
            float sv = (k >= klo && k <= khi) ? __ldg(sc + k) : 0.f;
            Qr[k] = fmaf(rc, sv, Qr[k]);
        }
    }
    #pragma unroll
    for (int k = 0; k < KT; ++k) Qs[k*128 + tid] = Qr[k];
}

// ---------------------------------------------------------------------------
// k2: merged sim kernel (fast shift-factorized path + bilinear fallback).
// ---------------------------------------------------------------------------
__global__ void __launch_bounds__(128, 8) sim_kernel(const float* __restrict__ feat,
                                                     const float* __restrict__ depthv,
                                                     float* __restrict__ out)
{
    __shared__ float  sbuf[DD*128];    // fast: first 8KB = Qs; gen: all = ssim
    __shared__ float  s_thr[16];
    __shared__ float4 s_ab[17*4];
    __shared__ float  s_w2[8];
    __shared__ float  s_B2;
    __shared__ int    s_dj[DD];
    __shared__ float  s_df[DD];

    int tid = threadIdx.x;
    int vi  = blockIdx.y;
    int g   = blockIdx.x * 128 + tid;
    int b   = g / HWSZ;               // same for whole block (HWSZ % 128 == 0)
    int hw  = g - b*HWSZ;
    int fast = g_fast;
    int uni  = g_uni;

    if (tid < 16) s_thr[tid] = g_thr[tid];
    if (tid < 68) s_ab[tid] = ((const float4*)g_abf)[tid];
    if (tid < 8)  s_w2[tid] = g_w2s[tid];
    if (tid == 8) s_B2 = g_B2s;
    if (fast && uni && tid < DD) { s_dj[tid] = g_dj[vi][b][tid]; s_df[tid] = g_df[vi][b][tid]; }
    __syncthreads();

    if (fast) {
        float* Qs = sbuf;
        int w = hw % WW;
        int jlo  = g_jlo[vi][b];
        int ktap = g_ktap[vi][b];
        float tx = g_trans[vi][b][0];

        const float* refb = feat + (size_t)(b*CC)*HWSZ;
        const float* srcb = feat + (size_t)(((vi+1)*BB + b)*CC)*HWSZ;

        int klo = -(w + jlo);
        int khi = (WW-1) - (w + jlo);
        int base = hw + jlo;

        if (ktap <= 8)       qaccum<8>(refb, srcb, hw, base, klo, khi, Qs, tid);
        else if (ktap <= 12) qaccum<12>(refb, srcb, hw, base, klo, khi, Qs, tid);
        else                 qaccum<16>(refb, srcb, hw, base, klo, khi, Qs, tid);

        float* svout = g_simv + ((size_t)(vi*BB + b)*DD)*HWSZ + hw;
        float vmaxo = -1e30f;

        if (uni) {
            #pragma unroll 8
            for (int d = 0; d < DD; ++d) {
                int jj = s_dj[d];
                float fx = s_df[d];
                float q0 = Qs[jj*128 + tid];
                float q1 = Qs[(jj+1)*128 + tid];
                float sim = fmaf(fx, q1 - q0, q0) * (1.f/32.f);
                svout[(size_t)d*HWSZ] = sim;
                vmaxo = fmaxf(vmaxo, mlp_o2(sim, s_thr, s_ab, s_w2, s_B2));
            }
        } else {
            const float* depcol = depthv + (size_t)(b*DD)*HWSZ + hw;
            int jcap = ktap - 2;
            for (int d = 0; d < DD; ++d) {
                float dep = __ldg(depcol + (size_t)d*HWSZ);
                float delta = __fdividef(tx, dep);
                float jf = floorf(delta);
                float fx = delta - jf;
                int jj = (int)jf - jlo;
                jj = min(max(jj, 0), jcap);
                float q0 = Qs[jj*128 + tid];
                float q1 = Qs[(jj+1)*128 + tid];
                float sim = fmaf(fx, q1 - q0, q0) * (1.f/32.f);
                svout[(size_t)d*HWSZ] = sim;
                vmaxo = fmaxf(vmaxo, mlp_o2(sim, s_thr, s_ab, s_w2, s_B2));
            }
        }

        out[OFF_VW + (b*4 + vi)*HWSZ + hw] = 1.f / (1.f + __expf(-vmaxo));
        return;
    }

    // ---- general fallback: vi==0 blocks cover all NPIX pixels ----
    if (vi != 0) return;
    {
        float* ssim = sbuf;
        int h = hw / WW, w = hw - h*WW;
        float xf = (float)w, yf = (float)h;

        const float* ref = feat + (size_t)(b*CC)*HWSZ + hw;
        float refv[CC];
        #pragma unroll
        for (int c = 0; c < CC; ++c) refv[c] = __ldg(ref + (size_t)c*HWSZ);

        float acc[DD];
        #pragma unroll
        for (int d = 0; d < DD; ++d) acc[d] = 0.f;
        float wsum = 1e-5f;
        const float* depcol = depthv + (size_t)(b*DD)*HWSZ + hw;

        for (int v = 1; v < VV; ++v) {
            const float* R = g_rot[v-1][b];
            const float* T = g_trans[v-1][b];
            float rx = R[0]*xf + R[1]*yf + R[2];
            float ry = R[3]*xf + R[4]*yf + R[5];
            float rz = R[6]*xf + R[7]*yf + R[8];
            float tx = T[0], ty = T[1], tz = T[2];
            const float* src = feat + (size_t)((v*BB + b)*CC)*HWSZ;
            float vmaxo = -1e30f;

            for (int d = 0; d < DD; ++d) {
                float dep = __ldg(depcol + (size_t)d*HWSZ);
                float px = fmaf(rx, dep, tx);
                float py = fmaf(ry, dep, ty);
                float pz = fmaf(rz, dep, tz);
                float iz = 1.0f / pz;
                float xs = px * iz, ys = py * iz;
                float x0f = floorf(xs), y0f = floorf(ys);
                float wx = xs - x0f, wy = ys - y0f;
                int ix = (int)x0f, iy = (int)y0f;
                float w00 = (1.f-wx)*(1.f-wy), w01 = wx*(1.f-wy);
                float w10 = (1.f-wx)*wy,       w11 = wx*wy;
                bool vx0 = (ix   >= 0) && (ix   < WW);
                bool vx1 = (ix+1 >= 0) && (ix+1 < WW);
                bool vy0 = (iy   >= 0) && (iy   < HH);
                bool vy1 = (iy+1 >= 0) && (iy+1 < HH);
                if (!(vx0 && vy0)) w00 = 0.f;
                if (!(vx1 && vy0)) w01 = 0.f;
                if (!(vx0 && vy1)) w10 = 0.f;
                if (!(vx1 && vy1)) w11 = 0.f;
                int x0c = min(max(ix,   0), WW-1), x1c = min(max(ix+1, 0), WW-1);
                int y0c = min(max(iy,   0), HH-1), y1c = min(max(iy+1, 0), HH-1);
                int o00 = y0c*WW + x0c, o01 = y0c*WW + x1c;
                int o10 = y1c*WW + x0c, o11 = y1c*WW + x1c;

                float s = 0.f;
                #pragma unroll
                for (int c = 0; c < CC; ++c) {
                    const float* p = src + (size_t)c*HWSZ;
                    float tap = fmaf(w00, __ldg(p+o00),
                                fmaf(w01, __ldg(p+o01),
                                fmaf(w10, __ldg(p+o10), w11 * __ldg(p+o11))));
                    s = fmaf(tap, refv[c], s);
                }
                float sim = s * (1.f/32.f);
                ssim[d*128 + tid] = sim;
                vmaxo = fmaxf(vmaxo, mlp_o2(sim, s_thr, s_ab, s_w2, s_B2));
            }

            float vmax = 1.f / (1.f + __expf(-vmaxo));
            out[OFF_VW + (b*4 + (v-1))*HWSZ + hw] = vmax;
            wsum += vmax;
            #pragma unroll
            for (int d = 0; d < DD; ++d)
                acc[d] = fmaf(ssim[d*128 + tid], vmax, acc[d]);
        }

        float invw = 1.f / wsum;
        float* so = g_sim + (size_t)(b*DD)*HWSZ + hw;
        #pragma unroll
        for (int d = 0; d < DD; ++d) so[(size_t)d*HWSZ] = acc[d] * invw;
    }
}

// ---------------------------------------------------------------------------
// k3 (fast path only): combine views, float4 over pixels, D split over
// blockIdx.y for 4x more parallelism.
// ---------------------------------------------------------------------------
__global__ void __launch_bounds__(128) combine_kernel(float* __restrict__ out)
{
    if (!g_fast) return;
    int t  = blockIdx.x * 128 + threadIdx.x;
    int g4 = t * 4;
    int b  = g4 / HWSZ;
    int hw = g4 - b*HWSZ;
    int d0 = blockIdx.y * 8;

    float4 vw0 = *(const float4*)(out + OFF_VW + (size_t)(b*4 + 0)*HWSZ + hw);
    float4 vw1 = *(const float4*)(out + OFF_VW + (size_t)(b*4 + 1)*HWSZ + hw);
    float4 vw2 = *(const float4*)(out + OFF_VW + (size_t)(b*4 + 2)*HWSZ + hw);
    float4 vw3 = *(const float4*)(out + OFF_VW + (size_t)(b*4 + 3)*HWSZ + hw);
    float4 inv;
    inv.x = 1.f / (1e-5f + vw0.x + vw1.x + vw2.x + vw3.x);
    inv.y = 1.f / (1e-5f + vw0.y + vw1.y + vw2.y + vw3.y);
    inv.z = 1.f / (1e-5f + vw0.z + vw1.z + vw2.z + vw3.z);
    inv.w = 1.f / (1e-5f + vw0.w + vw1.w + vw2.w + vw3.w);

    const float* s0 = g_simv + ((size_t)(0*BB + b)*DD + d0)*HWSZ + hw;
    const float* s1 = g_simv + ((size_t)(1*BB + b)*DD + d0)*HWSZ + hw;
    const float* s2 = g_simv + ((size_t)(2*BB + b)*DD + d0)*HWSZ + hw;
    const float* s3 = g_simv + ((size_t)(3*BB + b)*DD + d0)*HWSZ + hw;
    float* so = g_sim + ((size_t)(b*DD) + d0)*HWSZ + hw;

    #pragma unroll
    for (int d = 0; d < 8; ++d) {
        float4 a = *(const float4*)(s0 + (size_t)d*HWSZ);
        float4 bq= *(const float4*)(s1 + (size_t)d*HWSZ);
        float4 c = *(const float4*)(s2 + (size_t)d*HWSZ);
        float4 e = *(const float4*)(s3 + (size_t)d*HWSZ);
        float4 r;
        r.x = (a.x*vw0.x + bq.x*vw1.x + c.x*vw2.x + e.x*vw3.x) * inv.x;
        r.y = (a.y*vw0.y + bq.y*vw1.y + c.y*vw2.y + e.y*vw3.y) * inv.y;
        r.z = (a.z*vw0.z + bq.z*vw1.z + c.z*vw2.z + e.z*vw3.z) * inv.z;
        r.w = (a.w*vw0.w + bq.w*vw1.w + c.w*vw2.w + e.w*vw3.w) * inv.w;
        *(float4*)(so + (size_t)d*HWSZ) = r;
    }
}

// ---------------------------------------------------------------------------
// k4: 3x3x3 conv + softmax + argmax. Block = 32 row-aligned pixels x 8
// d-groups. The (34 slices x 3 rows x 34 cols) neighborhood is staged in
// shared once (zero-padded), so the conv inner loop is pure LDS+FMA.
// Correlation orientation: cost[d] += rw[kd]*sim[d+kd-1].
// ---------------------------------------------------------------------------
__global__ void __launch_bounds__(256) post_kernel(const float* __restrict__ depthv,
                                                   const float* __restrict__ regw,
                                                   const float* __restrict__ regb,
                                                   float* __restrict__ out)
{
    __shared__ float rw[27];
    __shared__ float rb;
    __shared__ float tile[34*3*34];   // [dd+1][row][col], 13.9 KB
    __shared__ float red[8][33];
    __shared__ int   redi[8][33];
    int tx = threadIdx.x;   // pixel lane 0..31
    int ty = threadIdx.y;   // d-group 0..7
    int lin = ty*32 + tx;
    if (lin < 27) rw[lin] = regw[lin];
    if (lin == 27) rb = regb[0];

    int gp = blockIdx.x * 32;         // 32 | 160 -> block lies in one image row
    int b  = gp / HWSZ;
    int hwb = gp - b*HWSZ;
    int h  = hwb / WW;
    int c0 = hwb - h*WW;
    const float* simb = g_sim + (size_t)(b*DD)*HWSZ;

    // stage the full neighborhood: dd in [-1,32], rows h-1..h+1, cols c0-1..c0+32
    for (int i = lin; i < 34*3*34; i += 256) {
        int dd = i / (3*34) - 1;
        int rem = i - (dd+1)*(3*34);
        int r  = rem / 34;
        int cc = rem - r*34;
        int h2 = h - 1 + r;
        int w2 = c0 - 1 + cc;
        float v = 0.f;
        if (dd >= 0 && dd < DD && h2 >= 0 && h2 < HH && w2 >= 0 && w2 < WW)
            v = __ldg(simb + (size_t)dd*HWSZ + h2*WW + w2);
        tile[i] = v;
    }
    __syncthreads();

    int g  = gp + tx;
    int hw = hwb + tx;
    int dbase = ty * 4;

    float cost[4] = {rb, rb, rb, rb};
    #pragma unroll
    for (int q = 0; q < 4; ++q) {
        #pragma unroll
        for (int kd = 0; kd < 3; ++kd) {
            int di = dbase + q + kd;          // tile slice = dd+1 = (dbase+q+kd-1)+1
            const float* tl = tile + di*(3*34);
            float p = 0.f;
            #pragma unroll
            for (int kh = 0; kh < 3; ++kh)
                #pragma unroll
                for (int kw = 0; kw < 3; ++kw)
                    p = fmaf(rw[kd*9 + kh*3 + kw], tl[kh*34 + tx + kw], p);
            cost[q] += p;
        }
    }

    float lm = fmaxf(fmaxf(cost[0], cost[1]), fmaxf(cost[2], cost[3]));
    red[ty][tx] = lm;
    __syncthreads();
    float m;
    {
        float t0 = fmaxf(red[0][tx], red[1][tx]);
        float t1 = fmaxf(red[2][tx], red[3][tx]);
        float t2 = fmaxf(red[4][tx], red[5][tx]);
        float t3 = fmaxf(red[6][tx], red[7][tx]);
        m = fmaxf(fmaxf(t0, t1), fmaxf(t2, t3));
    }
    __syncthreads();

    float e[4];
    float ls = 0.f;
    #pragma unroll
    for (int q = 0; q < 4; ++q) { e[q] = __expf(cost[q] - m); ls += e[q]; }
    red[ty][tx] = ls;
    __syncthreads();
    float sum = red[0][tx] + red[1][tx] + red[2][tx] + red[3][tx]
              + red[4][tx] + red[5][tx] + red[6][tx] + red[7][tx];
    float isum = 1.f / sum;
    __syncthreads();

    int li = 0; float lb = cost[0];
    #pragma unroll
    for (int q = 1; q < 4; ++q) if (cost[q] > lb) { lb = cost[q]; li = q; }
    red[ty][tx]  = lb;
    redi[ty][tx] = dbase + li;
    __syncthreads();

    if (ty == 0) {
        float best = red[0][tx]; int bi = redi[0][tx];
        #pragma unroll
        for (int yy = 1; yy < 8; ++yy)
            if (red[yy][tx] > best) { best = red[yy][tx]; bi = redi[yy][tx]; }
        out[OFF_DEPTH + g] = __ldg(depthv + (size_t)(b*DD + bi)*HWSZ + hw);
        out[OFF_CONF  + g] = isum;
    }

    #pragma unroll
    for (int q = 0; q < 4; ++q) {
        int d = dbase + q;
        out[OFF_PROB + (size_t)(b*DD + d)*HWSZ + hw] = e[q] * isum;
        out[OFF_COST + (size_t)(b*DD + d)*HWSZ + hw] = cost[q];
    }
}

extern "C" void kernel_launch(void* const* d_in, const int* in_sizes, int n_in,
                              void* d_out, int out_size)
{
    const float* feat   = (const float*)d_in[0];
    const float* pm     = (const float*)d_in[1];
    const float* depthv = (const float*)d_in[2];
    int base = (n_in >= 18) ? 4 : 3;
    const float* w0 = (const float*)d_in[base + 0];
    const float* g0 = (const float*)d_in[base + 1];
    const float* b0 = (const float*)d_in[base + 2];
    const float* m0 = (const float*)d_in[base + 3];
    const float* v0 = (const float*)d_in[base + 4];
    const float* w1 = (const float*)d_in[base + 5];
    const float* g1 = (const float*)d_in[base + 6];
    const float* b1 = (const float*)d_in[base + 7];
    const float* m1 = (const float*)d_in[base + 8];
    const float* v1 = (const float*)d_in[base + 9];
    const float* w2 = (const float*)d_in[base + 10];
    const float* b2 = (const float*)d_in[base + 11];
    const float* regw = (const float*)d_in[base + 12];
    const float* regb = (const float*)d_in[base + 13];
    float* out = (float*)d_out;

    prep_kernel<<<129, 256>>>(depthv, pm, w0, g0, b0, m0, v0,
                              w1, g1, b1, m1, v1, w2, b2);
    sim_kernel<<<dim3(NPIX/128, 4), 128>>>(feat, depthv, out);
    combine_kernel<<<dim3(NPIX/4/128, 4), 128>>>(out);
    post_kernel<<<NPIX/32, dim3(32, 8)>>>(depthv, regw, regb, out);
}

// round 15
// speedup vs baseline: 1.4451x; 1.0349x over previous
#include <cuda_runtime.h>
#include <math.h>

#define HH 128
#define WW 160
#define CC 32
#define DD 32
#define BB 2
#define VV 5
#define HWSZ (HH*WW)       // 20480
#define NPIX (BB*HWSZ)     // 40960
#define NDEP (BB*DD*HWSZ)  // 1310720

// out layout (flattened tuple in reference-return order):
#define OFF_DEPTH 0
#define OFF_CONF  40960
#define OFF_PROB  81920
#define OFF_COST  1392640
#define OFF_VW    2703360

__device__ float g_rot[4][BB][9];
__device__ float g_trans[4][BB][3];
// piecewise-affine MLP table: g_abf[i*16 + j] = alpha_j, [i*16+8+j] = beta_j
__device__ float g_thr[16];
__device__ float g_abf[17*16];
__device__ float g_w2s[8];
__device__ float g_B2s;
__device__ float g_sim[BB*DD*HWSZ];
__device__ float g_simv[4*BB*DD*HWSZ];   // per-view sim volumes (fast path)
__device__ unsigned g_dminu = 0xFFFFFFFFu;  // ordered-encoded min (idempotent across replays)
__device__ unsigned g_dmaxu = 0u;
__device__ int g_uni = 1;                // depth spatially uniform? (only ever cleared)
__device__ int g_cnt = 0;                // intra-grid barrier counter (reset each replay)
__device__ int g_fast;
__device__ int g_jlo[4][BB];
__device__ int g_ktap[4][BB];
__device__ int   g_dj[4][BB][DD];        // per-(v,b,d) tap index (uniform-depth path)
__device__ float g_df[4][BB][DD];        // per-(v,b,d) lerp fraction

__device__ __forceinline__ unsigned ord_enc(float x) {
    unsigned u = __float_as_uint(x);
    return (u & 0x80000000u) ? ~u : (u | 0x80000000u);
}
__device__ __forceinline__ float ord_dec(unsigned u) {
    u = (u & 0x80000000u) ? (u & 0x7FFFFFFFu) : ~u;
    return __uint_as_float(u);
}

// folded pixelwise MLP via exact piecewise-affine table
__device__ __forceinline__ float mlp_o2(float sim,
    const float* __restrict__ s_thr, const float4* __restrict__ s_ab,
    const float* __restrict__ s_w2, float s_B2)
{
    int idx = 0;
    #pragma unroll
    for (int k = 0; k < 16; ++k) idx += (sim > s_thr[k]) ? 1 : 0;
    const float4* tab = s_ab + idx*4;
    float4 A0 = tab[0], A1 = tab[1], B0 = tab[2], B1 = tab[3];
    float o2 = s_B2;
    o2 = fmaf(s_w2[0], fmaxf(fmaf(A0.x, sim, B0.x), 0.f), o2);
    o2 = fmaf(s_w2[1], fmaxf(fmaf(A0.y, sim, B0.y), 0.f), o2);
    o2 = fmaf(s_w2[2], fmaxf(fmaf(A0.z, sim, B0.z), 0.f), o2);
    o2 = fmaf(s_w2[3], fmaxf(fmaf(A0.w, sim, B0.w), 0.f), o2);
    o2 = fmaf(s_w2[4], fmaxf(fmaf(A1.x, sim, B1.x), 0.f), o2);
    o2 = fmaf(s_w2[5], fmaxf(fmaf(A1.y, sim, B1.y), 0.f), o2);
    o2 = fmaf(s_w2[6], fmaxf(fmaf(A1.z, sim, B1.z), 0.f), o2);
    o2 = fmaf(s_w2[7], fmaxf(fmaf(A1.w, sim, B1.w), 0.f), o2);
    return o2;
}

// ---------------------------------------------------------------------------
// k1: prep + minmax + flags, one launch (intra-grid spin barrier; 129 blocks
// co-resident on 148 SMs -> deadlock-free).
// ---------------------------------------------------------------------------
__global__ void __launch_bounds__(256) prep_kernel(const float* __restrict__ depthv,
    const float* __restrict__ pm,
    const float* __restrict__ w0, const float* __restrict__ g0,
    const float* __restrict__ b0, const float* __restrict__ m0, const float* __restrict__ v0,
    const float* __restrict__ w1, const float* __restrict__ g1,
    const float* __restrict__ b1, const float* __restrict__ m1, const float* __restrict__ v1,
    const float* __restrict__ w2, const float* __restrict__ b2)
{
    if (blockIdx.x < 128) {
        __shared__ unsigned smin[256], smax[256];
        __shared__ int smism;
        if (threadIdx.x == 0) smism = 0;
        __syncthreads();
        unsigned mn = 0xFFFFFFFFu, mx = 0u;
        int mism = 0;
        for (int i = blockIdx.x*256 + threadIdx.x; i < NDEP; i += 128*256) {
            float dv = depthv[i];
            unsigned e = ord_enc(dv);
            mn = min(mn, e); mx = max(mx, e);
            int head = (i / HWSZ) * HWSZ;
            if (__float_as_uint(dv) != __float_as_uint(__ldg(depthv + head))) mism = 1;
        }
        smin[threadIdx.x] = mn; smax[threadIdx.x] = mx;
        if (mism) smism = 1;
        __syncthreads();
        for (int s = 128; s > 0; s >>= 1) {
            if (threadIdx.x < s) {
                smin[threadIdx.x] = min(smin[threadIdx.x], smin[threadIdx.x+s]);
                smax[threadIdx.x] = max(smax[threadIdx.x], smax[threadIdx.x+s]);
            }
            __syncthreads();
        }
        if (threadIdx.x == 0) {
            atomicMin(&g_dminu, smin[0]);
            atomicMax(&g_dmaxu, smax[0]);
            if (smism) g_uni = 0;         // only cleared -> idempotent
            __threadfence();
            atomicAdd(&g_cnt, 1);
        }
        return;
    }

    // ---- block 128 ----
    int t = threadIdx.x;
    if (t < 8) {
        int b = t >> 2;
        int v = (t & 3) + 1;
        double Ar[9], tr[3], As[9], ts[3];
        for (int which = 0; which < 2; ++which) {
            int view = which ? v : 0;
            const float* E = pm + ((b*VV + view)*2 + 0)*16;
            const float* K = pm + ((b*VV + view)*2 + 1)*16;
            double* A = which ? As : Ar;
            double* tv = which ? ts : tr;
            for (int r = 0; r < 3; ++r) {
                for (int c = 0; c < 3; ++c) {
                    double s = 0.0;
                    for (int k = 0; k < 3; ++k) s += (double)K[r*4+k]*(double)E[k*4+c];
                    A[r*3+c] = s;
                }
                double s = 0.0;
                for (int k = 0; k < 3; ++k) s += (double)K[r*4+k]*(double)E[k*4+3];
                tv[r] = s;
            }
        }
        double c00 = Ar[4]*Ar[8]-Ar[5]*Ar[7];
        double c01 = Ar[5]*Ar[6]-Ar[3]*Ar[8];
        double c02 = Ar[3]*Ar[7]-Ar[4]*Ar[6];
        double det = Ar[0]*c00 + Ar[1]*c01 + Ar[2]*c02;
        double id  = 1.0/det;
        double Ai[9];
        Ai[0] = c00*id;
        Ai[1] = (Ar[2]*Ar[7]-Ar[1]*Ar[8])*id;
        Ai[2] = (Ar[1]*Ar[5]-Ar[2]*Ar[4])*id;
        Ai[3] = c01*id;
        Ai[4] = (Ar[0]*Ar[8]-Ar[2]*Ar[6])*id;
        Ai[5] = (Ar[2]*Ar[3]-Ar[0]*Ar[5])*id;
        Ai[6] = c02*id;
        Ai[7] = (Ar[1]*Ar[6]-Ar[0]*Ar[7])*id;
        Ai[8] = (Ar[0]*Ar[4]-Ar[1]*Ar[3])*id;
        double rot[9];
        for (int r = 0; r < 3; ++r)
            for (int c = 0; c < 3; ++c) {
                double s = 0.0;
                for (int k = 0; k < 3; ++k) s += As[r*3+k]*Ai[k*3+c];
                rot[r*3+c] = s;
                g_rot[v-1][b][r*3+c] = (float)s;
            }
        for (int r = 0; r < 3; ++r) {
            double s = ts[r];
            for (int k = 0; k < 3; ++k) s -= rot[r*3+k]*tr[k];
            g_trans[v-1][b][r] = (float)s;
        }
    } else if (t >= 16 && t < 16 + 17*8) {
        // one thread per (interval i, hidden unit j): exact piecewise-affine MLP
        int i = (t - 16) >> 3;
        int j = (t - 16) & 7;
        double a[16], c[16];
        for (int o = 0; o < 16; ++o) {
            double ai = (double)g0[o] / sqrt((double)v0[o] + 1e-5);
            a[o] = (double)w0[o] * ai;
            c[o] = (double)b0[o] - (double)m0[o] * ai;
        }
        double thr[16];
        for (int o = 0; o < 16; ++o) {
            if (a[o] != 0.0) thr[o] = -c[o] / a[o];
            else             thr[o] = (c[o] > 0.0) ? -1e30 : 1e30;
        }
        for (int ii = 1; ii < 16; ++ii) {
            double key = thr[ii]; int jj = ii - 1;
            while (jj >= 0 && thr[jj] > key) { thr[jj+1] = thr[jj]; --jj; }
            thr[jj+1] = key;
        }
        if (i == 0 && j < 8) {
            if (j == 0) {
                for (int k = 0; k < 16; ++k) g_thr[k] = (float)thr[k];
                g_B2s = b2[0];
            }
            g_w2s[j] = w2[j];
        }
        double aij = (double)g1[j] / sqrt((double)v1[j] + 1e-5);
        double c1j = (double)b1[j] - (double)m1[j] * aij;
        double lo = (i == 0)  ? thr[0]  - 1.0 : thr[i-1];
        double hi = (i == 16) ? thr[15] + 1.0 : thr[i];
        double rep = 0.5*(lo + hi);
        double aj = 0.0, bj = c1j;
        for (int o = 0; o < 16; ++o) {
            if (a[o]*rep + c[o] > 0.0) {
                double w1f = (double)w1[j*16 + o] * aij;
                aj += w1f*a[o]; bj += w1f*c[o];
            }
        }
        g_abf[i*16 + j]     = (float)aj;
        g_abf[i*16 + 8 + j] = (float)bj;
    }

    // ---- flags: wait for all minmax blocks, then decide ----
    __syncthreads();
    __shared__ int s_fast;
    if (t == 0) {
        while (atomicAdd(&g_cnt, 0) < 128) { }
        atomicSub(&g_cnt, 128);           // reset for next graph replay
        float dmin = ord_dec(atomicAdd(&g_dminu, 0u));
        float dmax = ord_dec(atomicAdd(&g_dmaxu, 0u));
        int fast = (dmin > 1e-3f) ? 1 : 0;
        for (int v = 0; v < 4 && fast; ++v)
            for (int b = 0; b < BB && fast; ++b) {
                const float* R = g_rot[v][b];
                const float* T = g_trans[v][b];
                float dev = 0.f;
                for (int i = 0; i < 9; ++i) {
                    float ident = (i == 0 || i == 4 || i == 8) ? 1.f : 0.f;
                    dev = fmaxf(dev, fabsf(R[i] - ident));
                }
                if (dev > 1e-5f || fabsf(T[1]) > 1e-3f || fabsf(T[2]) > 1e-3f) { fast = 0; break; }
                double tx = (double)T[0];
                double d0 = tx / (double)dmax, d1 = tx / (double)dmin;
                double dlo = fmin(d0, d1), dhi = fmax(d0, d1);
                int jl = (int)floor(dlo) - 1;
                int jh = (int)floor(dhi) + 1;
                int kt = jh - jl + 1;
                if (kt > 16) { fast = 0; break; }
                g_jlo[v][b]  = jl;
                g_ktap[v][b] = kt;
            }
        g_fast = fast;
        s_fast = fast;
    }
    __syncthreads();
    if (s_fast && g_uni) {
        int v = t >> 6;                   // 256 = 4*2*32 exactly
        int b = (t >> 5) & 1;
        int d = t & 31;
        float dep = __ldg(depthv + (size_t)(b*DD + d)*HWSZ);   // slice head
        float tx  = g_trans[v][b][0];
        float delta = __fdividef(tx, dep);
        float jf = floorf(delta);
        float fx = delta - jf;
        int jj = (int)jf - g_jlo[v][b];
        jj = min(max(jj, 0), g_ktap[v][b] - 2);
        g_dj[v][b][d] = jj;
        g_df[v][b][d] = fx;
    }
}

// ---------------------------------------------------------------------------
// templated Q accumulation: Q(p,k) = sum_c ref_c(p) * src_c(p+k)
// ---------------------------------------------------------------------------
template<int KT>
__device__ __forceinline__ void qaccum(const float* __restrict__ refb,
                                       const float* __restrict__ srcb,
                                       int hw, int base, int klo, int khi,
                                       float* __restrict__ Qs, int tid)
{
    float Qr[KT];
    #pragma unroll
    for (int k = 0; k < KT; ++k) Qr[k] = 0.f;
    #pragma unroll 4
    for (int c = 0; c < CC; ++c) {
        float rc = __ldg(refb + (size_t)c*HWSZ + hw);
        const float* sc = srcb + (size_t)c*HWSZ + base;
        #pragma unroll
        for (int k = 0; k < KT; ++k) {
            float sv = (k >= klo && k <= khi) ? __ldg(sc + k) : 0.f;
            Qr[k] = fmaf(rc, sv, Qr[k]);
        }
    }
    #pragma unroll
    for (int k = 0; k < KT; ++k) Qs[k*128 + tid] = Qr[k];
}

// ---------------------------------------------------------------------------
// k2: merged sim kernel (fast shift-factorized path + bilinear fallback).
// ---------------------------------------------------------------------------
__global__ void __launch_bounds__(128, 8) sim_kernel(const float* __restrict__ feat,
                                                     const float* __restrict__ depthv,
                                                     float* __restrict__ out)
{
    __shared__ float  sbuf[DD*128];    // fast: first 8KB = Qs; gen: all = ssim
    __shared__ float  s_thr[16];
    __shared__ float4 s_ab[17*4];
    __shared__ float  s_w2[8];
    __shared__ float  s_B2;
    __shared__ int    s_dj[DD];
    __shared__ float  s_df[DD];

    int tid = threadIdx.x;
    int vi  = blockIdx.y;
    int g   = blockIdx.x * 128 + tid;
    int b   = g / HWSZ;               // same for whole block (HWSZ % 128 == 0)
    int hw  = g - b*HWSZ;
    int fast = g_fast;
    int uni  = g_uni;

    if (tid < 16) s_thr[tid] = g_thr[tid];
    if (tid < 68) s_ab[tid] = ((const float4*)g_abf)[tid];
    if (tid < 8)  s_w2[tid] = g_w2s[tid];
    if (tid == 8) s_B2 = g_B2s;
    if (fast && uni && tid < DD) { s_dj[tid] = g_dj[vi][b][tid]; s_df[tid] = g_df[vi][b][tid]; }
    __syncthreads();

    if (fast) {
        float* Qs = sbuf;
        int w = hw % WW;
        int jlo  = g_jlo[vi][b];
        int ktap = g_ktap[vi][b];
        float tx = g_trans[vi][b][0];

        const float* refb = feat + (size_t)(b*CC)*HWSZ;
        const float* srcb = feat + (size_t)(((vi+1)*BB + b)*CC)*HWSZ;

        int klo = -(w + jlo);
        int khi = (WW-1) - (w + jlo);
        int base = hw + jlo;

        if (ktap <= 8)       qaccum<8>(refb, srcb, hw, base, klo, khi, Qs, tid);
        else if (ktap <= 12) qaccum<12>(refb, srcb, hw, base, klo, khi, Qs, tid);
        else                 qaccum<16>(refb, srcb, hw, base, klo, khi, Qs, tid);

        float* svout = g_simv + ((size_t)(vi*BB + b)*DD)*HWSZ + hw;
        float vmaxo = -1e30f;

        if (uni) {
            #pragma unroll 8
            for (int d = 0; d < DD; ++d) {
                int jj = s_dj[d];
                float fx = s_df[d];
                float q0 = Qs[jj*128 + tid];
                float q1 = Qs[(jj+1)*128 + tid];
                float sim = fmaf(fx, q1 - q0, q0) * (1.f/32.f);
                svout[(size_t)d*HWSZ] = sim;
                vmaxo = fmaxf(vmaxo, mlp_o2(sim, s_thr, s_ab, s_w2, s_B2));
            }
        } else {
            const float* depcol = depthv + (size_t)(b*DD)*HWSZ + hw;
            int jcap = ktap - 2;
            for (int d = 0; d < DD; ++d) {
                float dep = __ldg(depcol + (size_t)d*HWSZ);
                float delta = __fdividef(tx, dep);
                float jf = floorf(delta);
                float fx = delta - jf;
                int jj = (int)jf - jlo;
                jj = min(max(jj, 0), jcap);
                float q0 = Qs[jj*128 + tid];
                float q1 = Qs[(jj+1)*128 + tid];
                float sim = fmaf(fx, q1 - q0, q0) * (1.f/32.f);
                svout[(size_t)d*HWSZ] = sim;
                vmaxo = fmaxf(vmaxo, mlp_o2(sim, s_thr, s_ab, s_w2, s_B2));
            }
        }

        out[OFF_VW + (b*4 + vi)*HWSZ + hw] = 1.f / (1.f + __expf(-vmaxo));
        return;
    }

    // ---- general fallback: vi==0 blocks cover all NPIX pixels ----
    if (vi != 0) return;
    {
        float* ssim = sbuf;
        int h = hw / WW, w = hw - h*WW;
        float xf = (float)w, yf = (float)h;

        const float* ref = feat + (size_t)(b*CC)*HWSZ + hw;
        float refv[CC];
        #pragma unroll
        for (int c = 0; c < CC; ++c) refv[c] = __ldg(ref + (size_t)c*HWSZ);

        float acc[DD];
        #pragma unroll
        for (int d = 0; d < DD; ++d) acc[d] = 0.f;
        float wsum = 1e-5f;
        const float* depcol = depthv + (size_t)(b*DD)*HWSZ + hw;

        for (int v = 1; v < VV; ++v) {
            const float* R = g_rot[v-1][b];
            const float* T = g_trans[v-1][b];
            float rx = R[0]*xf + R[1]*yf + R[2];
            float ry = R[3]*xf + R[4]*yf + R[5];
            float rz = R[6]*xf + R[7]*yf + R[8];
            float tx = T[0], ty = T[1], tz = T[2];
            const float* src = feat + (size_t)((v*BB + b)*CC)*HWSZ;
            float vmaxo = -1e30f;

            for (int d = 0; d < DD; ++d) {
                float dep = __ldg(depcol + (size_t)d*HWSZ);
                float px = fmaf(rx, dep, tx);
                float py = fmaf(ry, dep, ty);
                float pz = fmaf(rz, dep, tz);
                float iz = 1.0f / pz;
                float xs = px * iz, ys = py * iz;
                float x0f = floorf(xs), y0f = floorf(ys);
                float wx = xs - x0f, wy = ys - y0f;
                int ix = (int)x0f, iy = (int)y0f;
                float w00 = (1.f-wx)*(1.f-wy), w01 = wx*(1.f-wy);
                float w10 = (1.f-wx)*wy,       w11 = wx*wy;
                bool vx0 = (ix   >= 0) && (ix   < WW);
                bool vx1 = (ix+1 >= 0) && (ix+1 < WW);
                bool vy0 = (iy   >= 0) && (iy   < HH);
                bool vy1 = (iy+1 >= 0) && (iy+1 < HH);
                if (!(vx0 && vy0)) w00 = 0.f;
                if (!(vx1 && vy0)) w01 = 0.f;
                if (!(vx0 && vy1)) w10 = 0.f;
                if (!(vx1 && vy1)) w11 = 0.f;
                int x0c = min(max(ix,   0), WW-1), x1c = min(max(ix+1, 0), WW-1);
                int y0c = min(max(iy,   0), HH-1), y1c = min(max(iy+1, 0), HH-1);
                int o00 = y0c*WW + x0c, o01 = y0c*WW + x1c;
                int o10 = y1c*WW + x0c, o11 = y1c*WW + x1c;

                float s = 0.f;
                #pragma unroll
                for (int c = 0; c < CC; ++c) {
                    const float* p = src + (size_t)c*HWSZ;
                    float tap = fmaf(w00, __ldg(p+o00),
                                fmaf(w01, __ldg(p+o01),
                                fmaf(w10, __ldg(p+o10), w11 * __ldg(p+o11))));
                    s = fmaf(tap, refv[c], s);
                }
                float sim = s * (1.f/32.f);
                ssim[d*128 + tid] = sim;
                vmaxo = fmaxf(vmaxo, mlp_o2(sim, s_thr, s_ab, s_w2, s_B2));
            }

            float vmax = 1.f / (1.f + __expf(-vmaxo));
            out[OFF_VW + (b*4 + (v-1))*HWSZ + hw] = vmax;
            wsum += vmax;
            #pragma unroll
            for (int d = 0; d < DD; ++d)
                acc[d] = fmaf(ssim[d*128 + tid], vmax, acc[d]);
        }

        float invw = 1.f / wsum;
        float* so = g_sim + (size_t)(b*DD)*HWSZ + hw;
        #pragma unroll
        for (int d = 0; d < DD; ++d) so[(size_t)d*HWSZ] = acc[d] * invw;
    }
}

// ---------------------------------------------------------------------------
// k3 (fast path only): combine views, float4 over pixels, D split over
// blockIdx.y for 4x more parallelism.
// ---------------------------------------------------------------------------
__global__ void __launch_bounds__(128) combine_kernel(float* __restrict__ out)
{
    if (!g_fast) return;
    int t  = blockIdx.x * 128 + threadIdx.x;
    int g4 = t * 4;
    int b  = g4 / HWSZ;
    int hw = g4 - b*HWSZ;
    int d0 = blockIdx.y * 8;

    float4 vw0 = *(const float4*)(out + OFF_VW + (size_t)(b*4 + 0)*HWSZ + hw);
    float4 vw1 = *(const float4*)(out + OFF_VW + (size_t)(b*4 + 1)*HWSZ + hw);
    float4 vw2 = *(const float4*)(out + OFF_VW + (size_t)(b*4 + 2)*HWSZ + hw);
    float4 vw3 = *(const float4*)(out + OFF_VW + (size_t)(b*4 + 3)*HWSZ + hw);
    float4 inv;
    inv.x = 1.f / (1e-5f + vw0.x + vw1.x + vw2.x + vw3.x);
    inv.y = 1.f / (1e-5f + vw0.y + vw1.y + vw2.y + vw3.y);
    inv.z = 1.f / (1e-5f + vw0.z + vw1.z + vw2.z + vw3.z);
    inv.w = 1.f / (1e-5f + vw0.w + vw1.w + vw2.w + vw3.w);

    const float* s0 = g_simv + ((size_t)(0*BB + b)*DD + d0)*HWSZ + hw;
    const float* s1 = g_simv + ((size_t)(1*BB + b)*DD + d0)*HWSZ + hw;
    const float* s2 = g_simv + ((size_t)(2*BB + b)*DD + d0)*HWSZ + hw;
    const float* s3 = g_simv + ((size_t)(3*BB + b)*DD + d0)*HWSZ + hw;
    float* so = g_sim + ((size_t)(b*DD) + d0)*HWSZ + hw;

    #pragma unroll
    for (int d = 0; d < 8; ++d) {
        float4 a = *(const float4*)(s0 + (size_t)d*HWSZ);
        float4 bq= *(const float4*)(s1 + (size_t)d*HWSZ);
        float4 c = *(const float4*)(s2 + (size_t)d*HWSZ);
        float4 e = *(const float4*)(s3 + (size_t)d*HWSZ);
        float4 r;
        r.x = (a.x*vw0.x + bq.x*vw1.x + c.x*vw2.x + e.x*vw3.x) * inv.x;
        r.y = (a.y*vw0.y + bq.y*vw1.y + c.y*vw2.y + e.y*vw3.y) * inv.y;
        r.z = (a.z*vw0.z + bq.z*vw1.z + c.z*vw2.z + e.z*vw3.z) * inv.z;
        r.w = (a.w*vw0.w + bq.w*vw1.w + c.w*vw2.w + e.w*vw3.w) * inv.w;
        *(float4*)(so + (size_t)d*HWSZ) = r;
    }
}

// ---------------------------------------------------------------------------
// k4: 3x3x3 conv + softmax + argmax, D split across 8 threads per pixel
// (R13 unstaged form — measured faster than shared staging).
// Correlation orientation: cost[d] += rw[kd]*sim[d+kd-1]  =>  kd = dd - d + 1.
// ---------------------------------------------------------------------------
__global__ void __launch_bounds__(256) post_kernel(const float* __restrict__ depthv,
                                                   const float* __restrict__ regw,
                                                   const float* __restrict__ regb,
                                                   float* __restrict__ out)
{
    __shared__ float rw[27];
    __shared__ float rb;
    __shared__ float red[8][33];
    __shared__ int   redi[8][33];
    int tx = threadIdx.x;   // pixel lane 0..31
    int ty = threadIdx.y;   // d-group 0..7
    int lin = ty*32 + tx;
    if (lin < 27) rw[lin] = regw[lin];
    if (lin == 27) rb = regb[0];
    __syncthreads();

    int g  = blockIdx.x * 32 + tx;
    int b  = g / HWSZ;
    int hw = g - b*HWSZ;
    int h  = hw / WW, w = hw - h*WW;
    int dbase = ty * 4;
    const float* simb = g_sim + (size_t)(b*DD)*HWSZ;

    float cost[4] = {rb, rb, rb, rb};

    #pragma unroll
    for (int o = 0; o < 6; ++o) {
        int dd = dbase - 1 + o;
        if (dd < 0 || dd >= DD) continue;
        float s[9];
        #pragma unroll
        for (int kh = 0; kh < 3; ++kh)
            #pragma unroll
            for (int kw = 0; kw < 3; ++kw) {
                int h2 = h + kh - 1, w2 = w + kw - 1;
                s[kh*3+kw] = (h2 >= 0 && h2 < HH && w2 >= 0 && w2 < WW)
                             ? __ldg(simb + (size_t)dd*HWSZ + h2*WW + w2) : 0.f;
            }
        #pragma unroll
        for (int q = 0; q < 4; ++q) {
            int kd = dd - (dbase + q) + 1;   // correlation: dd = d + kd - 1
            if (kd >= 0 && kd <= 2) {
                float p = 0.f;
                #pragma unroll
                for (int i = 0; i < 9; ++i) p = fmaf(rw[kd*9+i], s[i], p);
                cost[q] += p;
            }
        }
    }

    float lm = fmaxf(fmaxf(cost[0], cost[1]), fmaxf(cost[2], cost[3]));
    red[ty][tx] = lm;
    __syncthreads();
    float m;
    {
        float t0 = fmaxf(red[0][tx], red[1][tx]);
        float t1 = fmaxf(red[2][tx], red[3][tx]);
        float t2 = fmaxf(red[4][tx], red[5][tx]);
        float t3 = fmaxf(red[6][tx], red[7][tx]);
        m = fmaxf(fmaxf(t0, t1), fmaxf(t2, t3));
    }
    __syncthreads();

    float e[4];
    float ls = 0.f;
    #pragma unroll
    for (int q = 0; q < 4; ++q) { e[q] = __expf(cost[q] - m); ls += e[q]; }
    red[ty][tx] = ls;
    __syncthreads();
    float sum = red[0][tx] + red[1][tx] + red[2][tx] + red[3][tx]
              + red[4][tx] + red[5][tx] + red[6][tx] + red[7][tx];
    float isum = 1.f / sum;
    __syncthreads();

    int li = 0; float lb = cost[0];
    #pragma unroll
    for (int q = 1; q < 4; ++q) if (cost[q] > lb) { lb = cost[q]; li = q; }
    red[ty][tx]  = lb;
    redi[ty][tx] = dbase + li;
    __syncthreads();

    if (ty == 0) {
        float best = red[0][tx]; int bi = redi[0][tx];
        #pragma unroll
        for (int yy = 1; yy < 8; ++yy)
            if (red[yy][tx] > best) { best = red[yy][tx]; bi = redi[yy][tx]; }
        out[OFF_DEPTH + g] = __ldg(depthv + (size_t)(b*DD + bi)*HWSZ + hw);
        out[OFF_CONF  + g] = isum;
    }

    #pragma unroll
    for (int q = 0; q < 4; ++q) {
        int d = dbase + q;
        out[OFF_PROB + (size_t)(b*DD + d)*HWSZ + hw] = e[q] * isum;
        out[OFF_COST + (size_t)(b*DD + d)*HWSZ + hw] = cost[q];
    }
}

extern "C" void kernel_launch(void* const* d_in, const int* in_sizes, int n_in,
                              void* d_out, int out_size)
{
    const float* feat   = (const float*)d_in[0];
    const float* pm     = (const float*)d_in[1];
    const float* depthv = (const float*)d_in[2];
    int base = (n_in >= 18) ? 4 : 3;
    const float* w0 = (const float*)d_in[base + 0];
    const float* g0 = (const float*)d_in[base + 1];
    const float* b0 = (const float*)d_in[base + 2];
    const float* m0 = (const float*)d_in[base + 3];
    const float* v0 = (const float*)d_in[base + 4];
    const float* w1 = (const float*)d_in[base + 5];
    const float* g1 = (const float*)d_in[base + 6];
    const float* b1 = (const float*)d_in[base + 7];
    const float* m1 = (const float*)d_in[base + 8];
    const float* v1 = (const float*)d_in[base + 9];
    const float* w2 = (const float*)d_in[base + 10];
    const float* b2 = (const float*)d_in[base + 11];
    const float* regw = (const float*)d_in[base + 12];
    const float* regb = (const float*)d_in[base + 13];
    float* out = (float*)d_out;

    prep_kernel<<<129, 256>>>(depthv, pm, w0, g0, b0, m0, v0,
                              w1, g1, b1, m1, v1, w2, b2);
    sim_kernel<<<dim3(NPIX/128, 4), 128>>>(feat, depthv, out);
    combine_kernel<<<dim3(NPIX/4/128, 4), 128>>>(out);
    post_kernel<<<NPIX/32, dim3(32, 8)>>>(depthv, regw, regb, out);
}

// round 16
// speedup vs baseline: 1.4638x; 1.0129x over previous
#include <cuda_runtime.h>
#include <math.h>

#define HH 128
#define WW 160
#define CC 32
#define DD 32
#define BB 2
#define VV 5
#define HWSZ (HH*WW)       // 20480
#define NPIX (BB*HWSZ)     // 40960
#define NDEP (BB*DD*HWSZ)  // 1310720

// out layout (flattened tuple in reference-return order):
#define OFF_DEPTH 0
#define OFF_CONF  40960
#define OFF_PROB  81920
#define OFF_COST  1392640
#define OFF_VW    2703360

__device__ float g_rot[4][BB][9];
__device__ float g_trans[4][BB][3];
// piecewise-affine MLP table: g_abf[i*16 + j] = alpha_j, [i*16+8+j] = beta_j
__device__ float g_thr[16];
__device__ float g_abf[17*16];
__device__ float g_w2s[8];
__device__ float g_B2s;
__device__ float g_sim[BB*DD*HWSZ];
__device__ float g_simv[4*BB*DD*HWSZ];   // per-view sim volumes (fast path)
__device__ unsigned g_dminu = 0xFFFFFFFFu;  // ordered-encoded min (idempotent across replays)
__device__ unsigned g_dmaxu = 0u;
__device__ int g_uni = 1;                // depth spatially uniform? (only ever cleared)
__device__ int g_cnt = 0;                // intra-grid barrier counter (reset each replay)
__device__ int g_fast;
__device__ int g_jlo[4][BB];
__device__ int g_ktap[4][BB];
__device__ int   g_dj[4][BB][DD];        // per-(v,b,d) tap index (uniform-depth path)
__device__ float g_df[4][BB][DD];        // per-(v,b,d) lerp fraction

__device__ __forceinline__ unsigned ord_enc(float x) {
    unsigned u = __float_as_uint(x);
    return (u & 0x80000000u) ? ~u : (u | 0x80000000u);
}
__device__ __forceinline__ float ord_dec(unsigned u) {
    u = (u & 0x80000000u) ? (u & 0x7FFFFFFFu) : ~u;
    return __uint_as_float(u);
}

// folded pixelwise MLP via exact piecewise-affine table
__device__ __forceinline__ float mlp_o2(float sim,
    const float* __restrict__ s_thr, const float4* __restrict__ s_ab,
    const float* __restrict__ s_w2, float s_B2)
{
    int idx = 0;
    #pragma unroll
    for (int k = 0; k < 16; ++k) idx += (sim > s_thr[k]) ? 1 : 0;
    const float4* tab = s_ab + idx*4;
    float4 A0 = tab[0], A1 = tab[1], B0 = tab[2], B1 = tab[3];
    float o2 = s_B2;
    o2 = fmaf(s_w2[0], fmaxf(fmaf(A0.x, sim, B0.x), 0.f), o2);
    o2 = fmaf(s_w2[1], fmaxf(fmaf(A0.y, sim, B0.y), 0.f), o2);
    o2 = fmaf(s_w2[2], fmaxf(fmaf(A0.z, sim, B0.z), 0.f), o2);
    o2 = fmaf(s_w2[3], fmaxf(fmaf(A0.w, sim, B0.w), 0.f), o2);
    o2 = fmaf(s_w2[4], fmaxf(fmaf(A1.x, sim, B1.x), 0.f), o2);
    o2 = fmaf(s_w2[5], fmaxf(fmaf(A1.y, sim, B1.y), 0.f), o2);
    o2 = fmaf(s_w2[6], fmaxf(fmaf(A1.z, sim, B1.z), 0.f), o2);
    o2 = fmaf(s_w2[7], fmaxf(fmaf(A1.w, sim, B1.w), 0.f), o2);
    return o2;
}

// ---------------------------------------------------------------------------
// k1: prep + minmax + flags, one launch (intra-grid spin barrier; 129 blocks
// co-resident on 148 SMs -> deadlock-free).
// ---------------------------------------------------------------------------
__global__ void __launch_bounds__(256) prep_kernel(const float* __restrict__ depthv,
    const float* __restrict__ pm,
    const float* __restrict__ w0, const float* __restrict__ g0,
    const float* __restrict__ b0, const float* __restrict__ m0, const float* __restrict__ v0,
    const float* __restrict__ w1, const float* __restrict__ g1,
    const float* __restrict__ b1, const float* __restrict__ m1, const float* __restrict__ v1,
    const float* __restrict__ w2, const float* __restrict__ b2)
{
    if (blockIdx.x < 128) {
        __shared__ unsigned smin[256], smax[256];
        __shared__ int smism;
        if (threadIdx.x == 0) smism = 0;
        __syncthreads();
        unsigned mn = 0xFFFFFFFFu, mx = 0u;
        int mism = 0;
        for (int i = blockIdx.x*256 + threadIdx.x; i < NDEP; i += 128*256) {
            float dv = depthv[i];
            unsigned e = ord_enc(dv);
            mn = min(mn, e); mx = max(mx, e);
            int head = (i / HWSZ) * HWSZ;
            if (__float_as_uint(dv) != __float_as_uint(__ldg(depthv + head))) mism = 1;
        }
        smin[threadIdx.x] = mn; smax[threadIdx.x] = mx;
        if (mism) smism = 1;
        __syncthreads();
        for (int s = 128; s > 0; s >>= 1) {
            if (threadIdx.x < s) {
                smin[threadIdx.x] = min(smin[threadIdx.x], smin[threadIdx.x+s]);
                smax[threadIdx.x] = max(smax[threadIdx.x], smax[threadIdx.x+s]);
            }
            __syncthreads();
        }
        if (threadIdx.x == 0) {
            atomicMin(&g_dminu, smin[0]);
            atomicMax(&g_dmaxu, smax[0]);
            if (smism) g_uni = 0;         // only cleared -> idempotent
            __threadfence();
            atomicAdd(&g_cnt, 1);
        }
        return;
    }

    // ---- block 128 ----
    int t = threadIdx.x;
    if (t < 8) {
        int b = t >> 2;
        int v = (t & 3) + 1;
        double Ar[9], tr[3], As[9], ts[3];
        for (int which = 0; which < 2; ++which) {
            int view = which ? v : 0;
            const float* E = pm + ((b*VV + view)*2 + 0)*16;
            const float* K = pm + ((b*VV + view)*2 + 1)*16;
            double* A = which ? As : Ar;
            double* tv = which ? ts : tr;
            for (int r = 0; r < 3; ++r) {
                for (int c = 0; c < 3; ++c) {
                    double s = 0.0;
                    for (int k = 0; k < 3; ++k) s += (double)K[r*4+k]*(double)E[k*4+c];
                    A[r*3+c] = s;
                }
                double s = 0.0;
                for (int k = 0; k < 3; ++k) s += (double)K[r*4+k]*(double)E[k*4+3];
                tv[r] = s;
            }
        }
        double c00 = Ar[4]*Ar[8]-Ar[5]*Ar[7];
        double c01 = Ar[5]*Ar[6]-Ar[3]*Ar[8];
        double c02 = Ar[3]*Ar[7]-Ar[4]*Ar[6];
        double det = Ar[0]*c00 + Ar[1]*c01 + Ar[2]*c02;
        double id  = 1.0/det;
        double Ai[9];
        Ai[0] = c00*id;
        Ai[1] = (Ar[2]*Ar[7]-Ar[1]*Ar[8])*id;
        Ai[2] = (Ar[1]*Ar[5]-Ar[2]*Ar[4])*id;
        Ai[3] = c01*id;
        Ai[4] = (Ar[0]*Ar[8]-Ar[2]*Ar[6])*id;
        Ai[5] = (Ar[2]*Ar[3]-Ar[0]*Ar[5])*id;
        Ai[6] = c02*id;
        Ai[7] = (Ar[1]*Ar[6]-Ar[0]*Ar[7])*id;
        Ai[8] = (Ar[0]*Ar[4]-Ar[1]*Ar[3])*id;
        double rot[9];
        for (int r = 0; r < 3; ++r)
            for (int c = 0; c < 3; ++c) {
                double s = 0.0;
                for (int k = 0; k < 3; ++k) s += As[r*3+k]*Ai[k*3+c];
                rot[r*3+c] = s;
                g_rot[v-1][b][r*3+c] = (float)s;
            }
        for (int r = 0; r < 3; ++r) {
            double s = ts[r];
            for (int k = 0; k < 3; ++k) s -= rot[r*3+k]*tr[k];
            g_trans[v-1][b][r] = (float)s;
        }
    } else if (t >= 16 && t < 16 + 17*8) {
        // one thread per (interval i, hidden unit j): exact piecewise-affine MLP
        int i = (t - 16) >> 3;
        int j = (t - 16) & 7;
        double a[16], c[16];
        for (int o = 0; o < 16; ++o) {
            double ai = (double)g0[o] / sqrt((double)v0[o] + 1e-5);
            a[o] = (double)w0[o] * ai;
            c[o] = (double)b0[o] - (double)m0[o] * ai;
        }
        double thr[16];
        for (int o = 0; o < 16; ++o) {
            if (a[o] != 0.0) thr[o] = -c[o] / a[o];
            else             thr[o] = (c[o] > 0.0) ? -1e30 : 1e30;
        }
        for (int ii = 1; ii < 16; ++ii) {
            double key = thr[ii]; int jj = ii - 1;
            while (jj >= 0 && thr[jj] > key) { thr[jj+1] = thr[jj]; --jj; }
            thr[jj+1] = key;
        }
        if (i == 0 && j < 8) {
            if (j == 0) {
                for (int k = 0; k < 16; ++k) g_thr[k] = (float)thr[k];
                g_B2s = b2[0];
            }
            g_w2s[j] = w2[j];
        }
        double aij = (double)g1[j] / sqrt((double)v1[j] + 1e-5);
        double c1j = (double)b1[j] - (double)m1[j] * aij;
        double lo = (i == 0)  ? thr[0]  - 1.0 : thr[i-1];
        double hi = (i == 16) ? thr[15] + 1.0 : thr[i];
        double rep = 0.5*(lo + hi);
        double aj = 0.0, bj = c1j;
        for (int o = 0; o < 16; ++o) {
            if (a[o]*rep + c[o] > 0.0) {
                double w1f = (double)w1[j*16 + o] * aij;
                aj += w1f*a[o]; bj += w1f*c[o];
            }
        }
        g_abf[i*16 + j]     = (float)aj;
        g_abf[i*16 + 8 + j] = (float)bj;
    }

    // ---- flags: wait for all minmax blocks, then decide ----
    __syncthreads();
    __shared__ int s_fast;
    if (t == 0) {
        while (atomicAdd(&g_cnt, 0) < 128) { }
        atomicSub(&g_cnt, 128);           // reset for next graph replay
        float dmin = ord_dec(atomicAdd(&g_dminu, 0u));
        float dmax = ord_dec(atomicAdd(&g_dmaxu, 0u));
        int fast = (dmin > 1e-3f) ? 1 : 0;
        for (int v = 0; v < 4 && fast; ++v)
            for (int b = 0; b < BB && fast; ++b) {
                const float* R = g_rot[v][b];
                const float* T = g_trans[v][b];
                float dev = 0.f;
                for (int i = 0; i < 9; ++i) {
                    float ident = (i == 0 || i == 4 || i == 8) ? 1.f : 0.f;
                    dev = fmaxf(dev, fabsf(R[i] - ident));
                }
                if (dev > 1e-5f || fabsf(T[1]) > 1e-3f || fabsf(T[2]) > 1e-3f) { fast = 0; break; }
                double tx = (double)T[0];
                double d0 = tx / (double)dmax, d1 = tx / (double)dmin;
                double dlo = fmin(d0, d1), dhi = fmax(d0, d1);
                int jl = (int)floor(dlo) - 1;
                int jh = (int)floor(dhi) + 1;
                int kt = jh - jl + 1;
                if (kt > 16) { fast = 0; break; }
                g_jlo[v][b]  = jl;
                g_ktap[v][b] = kt;
            }
        g_fast = fast;
        s_fast = fast;
    }
    __syncthreads();
    if (s_fast && g_uni) {
        int v = t >> 6;                   // 256 = 4*2*32 exactly
        int b = (t >> 5) & 1;
        int d = t & 31;
        float dep = __ldg(depthv + (size_t)(b*DD + d)*HWSZ);   // slice head
        float tx  = g_trans[v][b][0];
        float delta = __fdividef(tx, dep);
        float jf = floorf(delta);
        float fx = delta - jf;
        int jj = (int)jf - g_jlo[v][b];
        jj = min(max(jj, 0), g_ktap[v][b] - 2);
        g_dj[v][b][d] = jj;
        g_df[v][b][d] = fx;
    }
}

// ---------------------------------------------------------------------------
// templated Q accumulation: Q(p,k) = sum_c ref_c(p) * src_c(p+k)
// ---------------------------------------------------------------------------
template<int KT>
__device__ __forceinline__ void qaccum(const float* __restrict__ refb,
                                       const float* __restrict__ srcb,
                                       int hw, int base, int klo, int khi,
                                       float* __restrict__ Qs, int tid)
{
    float Qr[KT];
    #pragma unroll
    for (int k = 0; k < KT; ++k) Qr[k] = 0.f;
    #pragma unroll 4
    for (int c = 0; c < CC; ++c) {
        float rc = __ldg(refb + (size_t)c*HWSZ + hw);
        const float* sc = srcb + (size_t)c*HWSZ + base;
        #pragma unroll
        for (int k = 0; k < KT; ++k) {
            float sv = (k >= klo && k <= khi) ? __ldg(sc + k) : 0.f;
            Qr[k] = fmaf(rc, sv, Qr[k]);
        }
    }
    #pragma unroll
    for (int k = 0; k < KT; ++k) Qs[k*128 + tid] = Qr[k];
}

// ---------------------------------------------------------------------------
// k2: merged sim kernel (fast shift-factorized path + bilinear fallback).
// ---------------------------------------------------------------------------
__global__ void __launch_bounds__(128, 8) sim_kernel(const float* __restrict__ feat,
                                                     const float* __restrict__ depthv,
                                                     float* __restrict__ out)
{
    __shared__ float  sbuf[DD*128];    // fast: first 8KB = Qs; gen: all = ssim
    __shared__ float  s_thr[16];
    __shared__ float4 s_ab[17*4];
    __shared__ float  s_w2[8];
    __shared__ float  s_B2;
    __shared__ int    s_dj[DD];
    __shared__ float  s_df[DD];

    int tid = threadIdx.x;
    int vi  = blockIdx.y;
    int g   = blockIdx.x * 128 + tid;
    int b   = g / HWSZ;               // same for whole block (HWSZ % 128 == 0)
    int hw  = g - b*HWSZ;
    int fast = g_fast;
    int uni  = g_uni;

    if (tid < 16) s_thr[tid] = g_thr[tid];
    if (tid < 68) s_ab[tid] = ((const float4*)g_abf)[tid];
    if (tid < 8)  s_w2[tid] = g_w2s[tid];
    if (tid == 8) s_B2 = g_B2s;
    if (fast && uni && tid < DD) { s_dj[tid] = g_dj[vi][b][tid]; s_df[tid] = g_df[vi][b][tid]; }
    __syncthreads();

    if (fast) {
        float* Qs = sbuf;
        int w = hw % WW;
        int jlo  = g_jlo[vi][b];
        int ktap = g_ktap[vi][b];
        float tx = g_trans[vi][b][0];

        const float* refb = feat + (size_t)(b*CC)*HWSZ;
        const float* srcb = feat + (size_t)(((vi+1)*BB + b)*CC)*HWSZ;

        int klo = -(w + jlo);
        int khi = (WW-1) - (w + jlo);
        int base = hw + jlo;

        if (ktap <= 8)       qaccum<8>(refb, srcb, hw, base, klo, khi, Qs, tid);
        else if (ktap <= 12) qaccum<12>(refb, srcb, hw, base, klo, khi, Qs, tid);
        else                 qaccum<16>(refb, srcb, hw, base, klo, khi, Qs, tid);

        float* svout = g_simv + ((size_t)(vi*BB + b)*DD)*HWSZ + hw;
        float vmaxo = -1e30f;

        if (uni) {
            #pragma unroll 8
            for (int d = 0; d < DD; ++d) {
                int jj = s_dj[d];
                float fx = s_df[d];
                float q0 = Qs[jj*128 + tid];
                float q1 = Qs[(jj+1)*128 + tid];
                float sim = fmaf(fx, q1 - q0, q0) * (1.f/32.f);
                svout[(size_t)d*HWSZ] = sim;
                vmaxo = fmaxf(vmaxo, mlp_o2(sim, s_thr, s_ab, s_w2, s_B2));
            }
        } else {
            const float* depcol = depthv + (size_t)(b*DD)*HWSZ + hw;
            int jcap = ktap - 2;
            for (int d = 0; d < DD; ++d) {
                float dep = __ldg(depcol + (size_t)d*HWSZ);
                float delta = __fdividef(tx, dep);
                float jf = floorf(delta);
                float fx = delta - jf;
                int jj = (int)jf - jlo;
                jj = min(max(jj, 0), jcap);
                float q0 = Qs[jj*128 + tid];
                float q1 = Qs[(jj+1)*128 + tid];
                float sim = fmaf(fx, q1 - q0, q0) * (1.f/32.f);
                svout[(size_t)d*HWSZ] = sim;
                vmaxo = fmaxf(vmaxo, mlp_o2(sim, s_thr, s_ab, s_w2, s_B2));
            }
        }

        out[OFF_VW + (b*4 + vi)*HWSZ + hw] = 1.f / (1.f + __expf(-vmaxo));
        return;
    }

    // ---- general fallback: vi==0 blocks cover all NPIX pixels ----
    if (vi != 0) return;
    {
        float* ssim = sbuf;
        int h = hw / WW, w = hw - h*WW;
        float xf = (float)w, yf = (float)h;

        const float* ref = feat + (size_t)(b*CC)*HWSZ + hw;
        float refv[CC];
        #pragma unroll
        for (int c = 0; c < CC; ++c) refv[c] = __ldg(ref + (size_t)c*HWSZ);

        float acc[DD];
        #pragma unroll
        for (int d = 0; d < DD; ++d) acc[d] = 0.f;
        float wsum = 1e-5f;
        const float* depcol = depthv + (size_t)(b*DD)*HWSZ + hw;

        for (int v = 1; v < VV; ++v) {
            const float* R = g_rot[v-1][b];
            const float* T = g_trans[v-1][b];
            float rx = R[0]*xf + R[1]*yf + R[2];
            float ry = R[3]*xf + R[4]*yf + R[5];
            float rz = R[6]*xf + R[7]*yf + R[8];
            float tx = T[0], ty = T[1], tz = T[2];
            const float* src = feat + (size_t)((v*BB + b)*CC)*HWSZ;
            float vmaxo = -1e30f;

            for (int d = 0; d < DD; ++d) {
                float dep = __ldg(depcol + (size_t)d*HWSZ);
                float px = fmaf(rx, dep, tx);
                float py = fmaf(ry, dep, ty);
                float pz = fmaf(rz, dep, tz);
                float iz = 1.0f / pz;
                float xs = px * iz, ys = py * iz;
                float x0f = floorf(xs), y0f = floorf(ys);
                float wx = xs - x0f, wy = ys - y0f;
                int ix = (int)x0f, iy = (int)y0f;
                float w00 = (1.f-wx)*(1.f-wy), w01 = wx*(1.f-wy);
                float w10 = (1.f-wx)*wy,       w11 = wx*wy;
                bool vx0 = (ix   >= 0) && (ix   < WW);
                bool vx1 = (ix+1 >= 0) && (ix+1 < WW);
                bool vy0 = (iy   >= 0) && (iy   < HH);
                bool vy1 = (iy+1 >= 0) && (iy+1 < HH);
                if (!(vx0 && vy0)) w00 = 0.f;
                if (!(vx1 && vy0)) w01 = 0.f;
                if (!(vx0 && vy1)) w10 = 0.f;
                if (!(vx1 && vy1)) w11 = 0.f;
                int x0c = min(max(ix,   0), WW-1), x1c = min(max(ix+1, 0), WW-1);
                int y0c = min(max(iy,   0), HH-1), y1c = min(max(iy+1, 0), HH-1);
                int o00 = y0c*WW + x0c, o01 = y0c*WW + x1c;
                int o10 = y1c*WW + x0c, o11 = y1c*WW + x1c;

                float s = 0.f;
                #pragma unroll
                for (int c = 0; c < CC; ++c) {
                    const float* p = src + (size_t)c*HWSZ;
                    float tap = fmaf(w00, __ldg(p+o00),
                                fmaf(w01, __ldg(p+o01),
                                fmaf(w10, __ldg(p+o10), w11 * __ldg(p+o11))));
                    s = fmaf(tap, refv[c], s);
                }
                float sim = s * (1.f/32.f);
                ssim[d*128 + tid] = sim;
                vmaxo = fmaxf(vmaxo, mlp_o2(sim, s_thr, s_ab, s_w2, s_B2));
            }

            float vmax = 1.f / (1.f + __expf(-vmaxo));
            out[OFF_VW + (b*4 + (v-1))*HWSZ + hw] = vmax;
            wsum += vmax;
            #pragma unroll
            for (int d = 0; d < DD; ++d)
                acc[d] = fmaf(ssim[d*128 + tid], vmax, acc[d]);
        }

        float invw = 1.f / wsum;
        float* so = g_sim + (size_t)(b*DD)*HWSZ + hw;
        #pragma unroll
        for (int d = 0; d < DD; ++d) so[(size_t)d*HWSZ] = acc[d] * invw;
    }
}

// ---------------------------------------------------------------------------
// k3 (fast path only): combine views, float4 over pixels, D split over
// blockIdx.y for 4x more parallelism.
// ---------------------------------------------------------------------------
__global__ void __launch_bounds__(128) combine_kernel(float* __restrict__ out)
{
    if (!g_fast) return;
    int t  = blockIdx.x * 128 + threadIdx.x;
    int g4 = t * 4;
    int b  = g4 / HWSZ;
    int hw = g4 - b*HWSZ;
    int d0 = blockIdx.y * 8;

    float4 vw0 = *(const float4*)(out + OFF_VW + (size_t)(b*4 + 0)*HWSZ + hw);
    float4 vw1 = *(const float4*)(out + OFF_VW + (size_t)(b*4 + 1)*HWSZ + hw);
    float4 vw2 = *(const float4*)(out + OFF_VW + (size_t)(b*4 + 2)*HWSZ + hw);
    float4 vw3 = *(const float4*)(out + OFF_VW + (size_t)(b*4 + 3)*HWSZ + hw);
    float4 inv;
    inv.x = 1.f / (1e-5f + vw0.x + vw1.x + vw2.x + vw3.x);
    inv.y = 1.f / (1e-5f + vw0.y + vw1.y + vw2.y + vw3.y);
    inv.z = 1.f / (1e-5f + vw0.z + vw1.z + vw2.z + vw3.z);
    inv.w = 1.f / (1e-5f + vw0.w + vw1.w + vw2.w + vw3.w);

    const float* s0 = g_simv + ((size_t)(0*BB + b)*DD + d0)*HWSZ + hw;
    const float* s1 = g_simv + ((size_t)(1*BB + b)*DD + d0)*HWSZ + hw;
    const float* s2 = g_simv + ((size_t)(2*BB + b)*DD + d0)*HWSZ + hw;
    const float* s3 = g_simv + ((size_t)(3*BB + b)*DD + d0)*HWSZ + hw;
    float* so = g_sim + ((size_t)(b*DD) + d0)*HWSZ + hw;

    #pragma unroll
    for (int d = 0; d < 8; ++d) {
        float4 a = *(const float4*)(s0 + (size_t)d*HWSZ);
        float4 bq= *(const float4*)(s1 + (size_t)d*HWSZ);
        float4 c = *(const float4*)(s2 + (size_t)d*HWSZ);
        float4 e = *(const float4*)(s3 + (size_t)d*HWSZ);
        float4 r;
        r.x = (a.x*vw0.x + bq.x*vw1.x + c.x*vw2.x + e.x*vw3.x) * inv.x;
        r.y = (a.y*vw0.y + bq.y*vw1.y + c.y*vw2.y + e.y*vw3.y) * inv.y;
        r.z = (a.z*vw0.z + bq.z*vw1.z + c.z*vw2.z + e.z*vw3.z) * inv.z;
        r.w = (a.w*vw0.w + bq.w*vw1.w + c.w*vw2.w + e.w*vw3.w) * inv.w;
        *(float4*)(so + (size_t)d*HWSZ) = r;
    }
}

// ---------------------------------------------------------------------------
// k4: 3x3x3 conv + softmax + argmax. Block = (32 pixels, 4 d-groups of 8):
// 10 slices per group for 8 outputs (11.25 loads/output vs 13.5 at 8x4).
// Correlation orientation: cost[d] += rw[kd]*sim[d+kd-1]  =>  kd = dd - d + 1.
// ---------------------------------------------------------------------------
__global__ void __launch_bounds__(128) post_kernel(const float* __restrict__ depthv,
                                                   const float* __restrict__ regw,
                                                   const float* __restrict__ regb,
                                                   float* __restrict__ out)
{
    __shared__ float rw[27];
    __shared__ float rb;
    __shared__ float red[4][33];
    __shared__ int   redi[4][33];
    int tx = threadIdx.x;   // pixel lane 0..31
    int ty = threadIdx.y;   // d-group 0..3
    int lin = ty*32 + tx;
    if (lin < 27) rw[lin] = regw[lin];
    if (lin == 27) rb = regb[0];
    __syncthreads();

    int g  = blockIdx.x * 32 + tx;
    int b  = g / HWSZ;
    int hw = g - b*HWSZ;
    int h  = hw / WW, w = hw - h*WW;
    int dbase = ty * 8;
    const float* simb = g_sim + (size_t)(b*DD)*HWSZ;

    float cost[8];
    #pragma unroll
    for (int q = 0; q < 8; ++q) cost[q] = rb;

    #pragma unroll
    for (int o = 0; o < 10; ++o) {
        int dd = dbase - 1 + o;
        if (dd < 0 || dd >= DD) continue;
        float s[9];
        #pragma unroll
        for (int kh = 0; kh < 3; ++kh)
            #pragma unroll
            for (int kw = 0; kw < 3; ++kw) {
                int h2 = h + kh - 1, w2 = w + kw - 1;
                s[kh*3+kw] = (h2 >= 0 && h2 < HH && w2 >= 0 && w2 < WW)
                             ? __ldg(simb + (size_t)dd*HWSZ + h2*WW + w2) : 0.f;
            }
        #pragma unroll
        for (int q = 0; q < 8; ++q) {
            int kd = dd - (dbase + q) + 1;   // correlation: dd = d + kd - 1
            if (kd >= 0 && kd <= 2) {
                float p = 0.f;
                #pragma unroll
                for (int i = 0; i < 9; ++i) p = fmaf(rw[kd*9+i], s[i], p);
                cost[q] += p;
            }
        }
    }

    float lm = cost[0];
    #pragma unroll
    for (int q = 1; q < 8; ++q) lm = fmaxf(lm, cost[q]);
    red[ty][tx] = lm;
    __syncthreads();
    float m = fmaxf(fmaxf(red[0][tx], red[1][tx]), fmaxf(red[2][tx], red[3][tx]));
    __syncthreads();

    float e[8];
    float ls = 0.f;
    #pragma unroll
    for (int q = 0; q < 8; ++q) { e[q] = __expf(cost[q] - m); ls += e[q]; }
    red[ty][tx] = ls;
    __syncthreads();
    float sum = red[0][tx] + red[1][tx] + red[2][tx] + red[3][tx];
    float isum = 1.f / sum;
    __syncthreads();

    int li = 0; float lb = cost[0];
    #pragma unroll
    for (int q = 1; q < 8; ++q) if (cost[q] > lb) { lb = cost[q]; li = q; }
    red[ty][tx]  = lb;
    redi[ty][tx] = dbase + li;
    __syncthreads();

    if (ty == 0) {
        float best = red[0][tx]; int bi = redi[0][tx];
        #pragma unroll
        for (int yy = 1; yy < 4; ++yy)
            if (red[yy][tx] > best) { best = red[yy][tx]; bi = redi[yy][tx]; }
        out[OFF_DEPTH + g] = __ldg(depthv + (size_t)(b*DD + bi)*HWSZ + hw);
        out[OFF_CONF  + g] = isum;
    }

    #pragma unroll
    for (int q = 0; q < 8; ++q) {
        int d = dbase + q;
        out[OFF_PROB + (size_t)(b*DD + d)*HWSZ + hw] = e[q] * isum;
        out[OFF_COST + (size_t)(b*DD + d)*HWSZ + hw] = cost[q];
    }
}

extern "C" void kernel_launch(void* const* d_in, const int* in_sizes, int n_in,
                              void* d_out, int out_size)
{
    const float* feat   = (const float*)d_in[0];
    const float* pm     = (const float*)d_in[1];
    const float* depthv = (const float*)d_in[2];
    int base = (n_in >= 18) ? 4 : 3;
    const float* w0 = (const float*)d_in[base + 0];
    const float* g0 = (const float*)d_in[base + 1];
    const float* b0 = (const float*)d_in[base + 2];
    const float* m0 = (const float*)d_in[base + 3];
    const float* v0 = (const float*)d_in[base + 4];
    const float* w1 = (const float*)d_in[base + 5];
    const float* g1 = (const float*)d_in[base + 6];
    const float* b1 = (const float*)d_in[base + 7];
    const float* m1 = (const float*)d_in[base + 8];
    const float* v1 = (const float*)d_in[base + 9];
    const float* w2 = (const float*)d_in[base + 10];
    const float* b2 = (const float*)d_in[base + 11];
    const float* regw = (const float*)d_in[base + 12];
    const float* regb = (const float*)d_in[base + 13];
    float* out = (float*)d_out;

    prep_kernel<<<129, 256>>>(depthv, pm, w0, g0, b0, m0, v0,
                              w1, g1, b1, m1, v1, w2, b2);
    sim_kernel<<<dim3(NPIX/128, 4), 128>>>(feat, depthv, out);
    combine_kernel<<<dim3(NPIX/4/128, 4), 128>>>(out);
    post_kernel<<<NPIX/32, dim3(32, 4)>>>(depthv, regw, regb, out);
}